// round 1
// baseline (speedup 1.0000x reference)
#include <cuda_runtime.h>
#include <math.h>

// ---------------------------------------------------------------------------
// Problem constants (MLA prefill)
// ---------------------------------------------------------------------------
namespace {
constexpr int B_   = 2;
constexpr int S_   = 2048;
constexpr int H_   = 2048;
constexpr int NH_  = 16;
constexpr int QL   = 1536;           // q lora rank
constexpr int KVL  = 512;            // kv lora rank
constexpr int DN   = 128;            // nope dim
constexpr int DR   = 64;             // rope dim
constexpr int DV   = 128;            // v dim
constexpr int DQK  = 192;            // DN + DR
constexpr int BS   = B_ * S_;        // 4096 rows
constexpr float SCALE = 0.07216878364870322f; // 1/sqrt(192)

constexpr int QK_LD = 193;           // padded smem stride (odd -> <=2-way conflicts)
constexpr int FLASH_SMEM = (64 * QK_LD * 2 + 64 * 128 + 64 * 64) * 4; // 147,968 B
} // namespace

// ---------------------------------------------------------------------------
// Scratch (static device globals; no runtime allocation allowed)
// ---------------------------------------------------------------------------
__device__ float g_qlora[(size_t)BS * QL];            // 25 MB
__device__ float g_q[(size_t)BS * NH_ * DQK];         // 50 MB (nope|pe per head)
__device__ float g_kv[(size_t)BS * (KVL + DR)];       //  9 MB (kv_c | k_pe)
__device__ float g_kvx[(size_t)BS * NH_ * (DN + DV)]; // 67 MB (k_nope|v per head)
__device__ float g_attn[(size_t)BS * NH_ * DV];       // 33 MB

// ---------------------------------------------------------------------------
// Tiled SGEMM:  C[M,N] = A[M,K] * B[N,K]^T   (both K-contiguous)
// 128x128 tile, BK=16, 256 threads, 8x8 micro-tile per thread.
// M must be a multiple of 128 (always true here); N is guarded.
// ---------------------------------------------------------------------------
__global__ __launch_bounds__(256, 2)
void sgemm_nt(const float* __restrict__ A, const float* __restrict__ Bw,
              float* __restrict__ C, int N, int K, int lda, int ldb, int ldc)
{
    __shared__ float As[16][128];
    __shared__ float Bs[16][128];
    const int tid = threadIdx.x;
    const int tr = tid >> 4, tc = tid & 15;
    const int m0 = blockIdx.y * 128, n0 = blockIdx.x * 128;
    const int lr = tid >> 2;          // 0..63
    const int lk = (tid & 3) << 2;    // 0,4,8,12

    float acc[8][8];
    #pragma unroll
    for (int i = 0; i < 8; i++)
        #pragma unroll
        for (int j = 0; j < 8; j++) acc[i][j] = 0.f;

    for (int k0 = 0; k0 < K; k0 += 16) {
        #pragma unroll
        for (int hh = 0; hh < 2; hh++) {
            const int row = lr + hh * 64;
            float4 a = *(const float4*)(A + (size_t)(m0 + row) * lda + k0 + lk);
            As[lk + 0][row] = a.x; As[lk + 1][row] = a.y;
            As[lk + 2][row] = a.z; As[lk + 3][row] = a.w;
            const int n = n0 + row;
            float4 b = make_float4(0.f, 0.f, 0.f, 0.f);
            if (n < N) b = *(const float4*)(Bw + (size_t)n * ldb + k0 + lk);
            Bs[lk + 0][row] = b.x; Bs[lk + 1][row] = b.y;
            Bs[lk + 2][row] = b.z; Bs[lk + 3][row] = b.w;
        }
        __syncthreads();
        #pragma unroll
        for (int k = 0; k < 16; k++) {
            float4 a0 = *(const float4*)&As[k][tr * 4];
            float4 a1 = *(const float4*)&As[k][tr * 4 + 64];
            float4 b0 = *(const float4*)&Bs[k][tc * 4];
            float4 b1 = *(const float4*)&Bs[k][tc * 4 + 64];
            float av[8] = {a0.x, a0.y, a0.z, a0.w, a1.x, a1.y, a1.z, a1.w};
            float bv[8] = {b0.x, b0.y, b0.z, b0.w, b1.x, b1.y, b1.z, b1.w};
            #pragma unroll
            for (int i = 0; i < 8; i++)
                #pragma unroll
                for (int j = 0; j < 8; j++)
                    acc[i][j] = fmaf(av[i], bv[j], acc[i][j]);
        }
        __syncthreads();
    }
    #pragma unroll
    for (int ih = 0; ih < 2; ih++)
        #pragma unroll
        for (int i = 0; i < 4; i++) {
            const int m = m0 + ih * 64 + tr * 4 + i;
            #pragma unroll
            for (int jh = 0; jh < 2; jh++) {
                const int n = n0 + jh * 64 + tc * 4;
                if (n < N) {
                    float4 v = make_float4(acc[ih * 4 + i][jh * 4 + 0],
                                           acc[ih * 4 + i][jh * 4 + 1],
                                           acc[ih * 4 + i][jh * 4 + 2],
                                           acc[ih * 4 + i][jh * 4 + 3]);
                    *(float4*)(C + (size_t)m * ldc + n) = v;
                }
            }
        }
}

// ---------------------------------------------------------------------------
// Row-wise RMSNorm (in place): x = w * x / sqrt(mean(x^2) + eps)
// One block (256 thr) per row; only first n columns of a row of stride ld.
// ---------------------------------------------------------------------------
__global__ __launch_bounds__(256)
void rmsnorm_kernel(float* __restrict__ x, const float* __restrict__ w, int n, int ld)
{
    const int row = blockIdx.x;
    float* p = x + (size_t)row * ld;
    float ss = 0.f;
    for (int i = threadIdx.x; i < n; i += 256) { float v = p[i]; ss = fmaf(v, v, ss); }
    __shared__ float red[8];
    #pragma unroll
    for (int o = 16; o > 0; o >>= 1) ss += __shfl_xor_sync(0xffffffffu, ss, o);
    if ((threadIdx.x & 31) == 0) red[threadIdx.x >> 5] = ss;
    __syncthreads();
    __shared__ float s_inv;
    if (threadIdx.x == 0) {
        float t = 0.f;
        #pragma unroll
        for (int i = 0; i < 8; i++) t += red[i];
        s_inv = rsqrtf(t / (float)n + 1e-6f);
    }
    __syncthreads();
    const float inv = s_inv;
    for (int i = threadIdx.x; i < n; i += 256) p[i] = w[i] * p[i] * inv;
}

// ---------------------------------------------------------------------------
// Interleaved RoPE on one (even,odd) pair.
// inv[i] = 10000^(-2i/64); f = pos * inv[i]  (matches reference fp32 layout)
// ---------------------------------------------------------------------------
__device__ __forceinline__ void rope_pair(float* p, int pos, int i)
{
    const float invf = (float)pow(10000.0, -(double)(2 * i) / 64.0);
    const float f = (float)pos * invf;
    float sn, c;
    sincosf(f, &sn, &c);
    const float e = p[0], o = p[1];
    p[0] = e * c - o * sn;
    p[1] = e * sn + o * c;
}

__global__ void rope_q_kernel(float* __restrict__ q)
{
    const int idx = blockIdx.x * blockDim.x + threadIdx.x; // BS*NH*32 total
    const int i   = idx & 31;
    const int h   = (idx >> 5) & (NH_ - 1);
    const int row = idx >> 9;
    const int s   = row & (S_ - 1);
    rope_pair(q + (size_t)row * (NH_ * DQK) + h * DQK + DN + 2 * i, s, i);
}

__global__ void rope_k_kernel(float* __restrict__ kv)
{
    const int idx = blockIdx.x * blockDim.x + threadIdx.x; // BS*32 total
    const int i   = idx & 31;
    const int row = idx >> 5;
    const int s   = row & (S_ - 1);
    rope_pair(kv + (size_t)row * (KVL + DR) + KVL + 2 * i, s, i);
}

// ---------------------------------------------------------------------------
// Flash attention, fp32, no mask.
// Block = (q-tile 64) x (head) x (batch), 256 threads (16x16),
// each thread: 4 q-rows x (4 score cols | 8 out cols).
// K tile assembled in smem from k_nope (g_kvx) + shared k_pe (g_kv).
// ---------------------------------------------------------------------------
__global__ __launch_bounds__(256)
void flash_kernel(const float* __restrict__ q, const float* __restrict__ kvx,
                  const float* __restrict__ kv, float* __restrict__ out)
{
    extern __shared__ float sm[];
    float* Qs = sm;                  // [64][QK_LD] (192 used)
    float* Ks = Qs + 64 * QK_LD;     // [64][QK_LD]
    float* Vs = Ks + 64 * QK_LD;     // [64][128]
    float* Ps = Vs + 64 * 128;       // [64][64]

    const int h  = blockIdx.y, b = blockIdx.z;
    const int q0 = blockIdx.x * 64;
    const int tid = threadIdx.x;
    const int ty = tid >> 4, tx = tid & 15;

    // Q tile: 192 contiguous floats per (row, head) in g_q (pe already roped)
    for (int u = tid; u < 64 * 48; u += 256) {
        const int r = u / 48, c = (u % 48) << 2;
        float4 a = *(const float4*)(q + (size_t)(b * S_ + q0 + r) * (NH_ * DQK) + h * DQK + c);
        Qs[r * QK_LD + c + 0] = a.x; Qs[r * QK_LD + c + 1] = a.y;
        Qs[r * QK_LD + c + 2] = a.z; Qs[r * QK_LD + c + 3] = a.w;
    }

    float m[4], l[4], acc[4][8];
    #pragma unroll
    for (int i = 0; i < 4; i++) {
        m[i] = -1e30f; l[i] = 0.f;
        #pragma unroll
        for (int c = 0; c < 8; c++) acc[i][c] = 0.f;
    }

    for (int kt = 0; kt < S_; kt += 64) {
        __syncthreads(); // previous PV / Q-load done before overwriting tiles
        // K nope (from kvx, per head)
        for (int u = tid; u < 64 * 32; u += 256) {
            const int r = u >> 5, c = (u & 31) << 2;
            float4 a = *(const float4*)(kvx + (size_t)(b * S_ + kt + r) * (NH_ * (DN + DV))
                                        + h * (DN + DV) + c);
            Ks[r * QK_LD + c + 0] = a.x; Ks[r * QK_LD + c + 1] = a.y;
            Ks[r * QK_LD + c + 2] = a.z; Ks[r * QK_LD + c + 3] = a.w;
        }
        // K pe (shared across heads, from g_kv cols 512..575)
        for (int u = tid; u < 64 * 16; u += 256) {
            const int r = u >> 4, c = (u & 15) << 2;
            float4 a = *(const float4*)(kv + (size_t)(b * S_ + kt + r) * (KVL + DR) + KVL + c);
            Ks[r * QK_LD + DN + c + 0] = a.x; Ks[r * QK_LD + DN + c + 1] = a.y;
            Ks[r * QK_LD + DN + c + 2] = a.z; Ks[r * QK_LD + DN + c + 3] = a.w;
        }
        // V (from kvx, per head, cols 128..255)
        for (int u = tid; u < 64 * 32; u += 256) {
            const int r = u >> 5, c = (u & 31) << 2;
            *(float4*)&Vs[r * 128 + c] =
                *(const float4*)(kvx + (size_t)(b * S_ + kt + r) * (NH_ * (DN + DV))
                                 + h * (DN + DV) + DN + c);
        }
        __syncthreads();

        // S = Q K^T * scale  (4x4 per thread)
        float sc[4][4];
        #pragma unroll
        for (int i = 0; i < 4; i++)
            #pragma unroll
            for (int j = 0; j < 4; j++) sc[i][j] = 0.f;
        for (int k = 0; k < DQK; k++) {
            float av[4], bv[4];
            #pragma unroll
            for (int i = 0; i < 4; i++) av[i] = Qs[(ty * 4 + i) * QK_LD + k];
            #pragma unroll
            for (int j = 0; j < 4; j++) bv[j] = Ks[(tx * 4 + j) * QK_LD + k];
            #pragma unroll
            for (int i = 0; i < 4; i++)
                #pragma unroll
                for (int j = 0; j < 4; j++)
                    sc[i][j] = fmaf(av[i], bv[j], sc[i][j]);
        }

        // online softmax update (reduce over tx = key dimension, 16 lanes)
        #pragma unroll
        for (int i = 0; i < 4; i++) {
            float mx = -1e30f;
            #pragma unroll
            for (int j = 0; j < 4; j++) { sc[i][j] *= SCALE; mx = fmaxf(mx, sc[i][j]); }
            #pragma unroll
            for (int o = 1; o < 16; o <<= 1) mx = fmaxf(mx, __shfl_xor_sync(0xffffffffu, mx, o));
            const float mnew  = fmaxf(m[i], mx);
            const float alpha = __expf(m[i] - mnew);
            float rs = 0.f;
            #pragma unroll
            for (int j = 0; j < 4; j++) {
                const float pij = __expf(sc[i][j] - mnew);
                sc[i][j] = pij; rs += pij;
            }
            #pragma unroll
            for (int o = 1; o < 16; o <<= 1) rs += __shfl_xor_sync(0xffffffffu, rs, o);
            l[i] = l[i] * alpha + rs;
            m[i] = mnew;
            #pragma unroll
            for (int c = 0; c < 8; c++) acc[i][c] *= alpha;
            #pragma unroll
            for (int j = 0; j < 4; j++)
                Ps[(ty * 4 + i) * 64 + tx * 4 + j] = sc[i][j];
        }
        __syncthreads();

        // O += P V   (each thread: 4 q-rows x 8 v-cols)
        for (int kk = 0; kk < 64; kk++) {
            float pv[4];
            #pragma unroll
            for (int i = 0; i < 4; i++) pv[i] = Ps[(ty * 4 + i) * 64 + kk];
            const float4 v0 = *(const float4*)&Vs[kk * 128 + tx * 8];
            const float4 v1 = *(const float4*)&Vs[kk * 128 + tx * 8 + 4];
            const float vv[8] = {v0.x, v0.y, v0.z, v0.w, v1.x, v1.y, v1.z, v1.w};
            #pragma unroll
            for (int i = 0; i < 4; i++)
                #pragma unroll
                for (int c = 0; c < 8; c++)
                    acc[i][c] = fmaf(pv[i], vv[c], acc[i][c]);
        }
    }

    #pragma unroll
    for (int i = 0; i < 4; i++) {
        const float inv = 1.f / l[i];
        const int row = b * S_ + q0 + ty * 4 + i;
        float4 o0 = make_float4(acc[i][0] * inv, acc[i][1] * inv, acc[i][2] * inv, acc[i][3] * inv);
        float4 o1 = make_float4(acc[i][4] * inv, acc[i][5] * inv, acc[i][6] * inv, acc[i][7] * inv);
        *(float4*)(out + (size_t)row * (NH_ * DV) + h * DV + tx * 8)     = o0;
        *(float4*)(out + (size_t)row * (NH_ * DV) + h * DV + tx * 8 + 4) = o1;
    }
}

// ---------------------------------------------------------------------------
// Launcher
// ---------------------------------------------------------------------------
extern "C" void kernel_launch(void* const* d_in, const int* in_sizes, int n_in,
                              void* d_out, int out_size)
{
    const float* hs    = (const float*)d_in[0]; // hidden_states [B,S,H]
    const float* wq_a  = (const float*)d_in[1]; // [QL, H]
    const float* qnw   = (const float*)d_in[2]; // [QL]
    const float* wq_b  = (const float*)d_in[3]; // [NH*DQK, QL]
    const float* wkv_a = (const float*)d_in[4]; // [KVL+DR, H]
    const float* kvnw  = (const float*)d_in[5]; // [KVL]
    const float* wkv_b = (const float*)d_in[6]; // [NH*(DN+DV), KVL]
    const float* wo    = (const float*)d_in[7]; // [H, NH*DV]
    float* out = (float*)d_out;

    void* p;
    cudaGetSymbolAddress(&p, g_qlora); float* qlora = (float*)p;
    cudaGetSymbolAddress(&p, g_q);     float* qbuf  = (float*)p;
    cudaGetSymbolAddress(&p, g_kv);    float* kvbuf = (float*)p;
    cudaGetSymbolAddress(&p, g_kvx);   float* kvx   = (float*)p;
    cudaGetSymbolAddress(&p, g_attn);  float* attn  = (float*)p;

    const dim3 blk(256);

    // 1) q_lora = hs @ wq_a^T            [4096, 1536]
    sgemm_nt<<<dim3(QL / 128, BS / 128), blk>>>(hs, wq_a, qlora, QL, H_, H_, H_, QL);
    // 2) rmsnorm(q_lora)
    rmsnorm_kernel<<<BS, blk>>>(qlora, qnw, QL, QL);
    // 3) q = q_lora @ wq_b^T             [4096, 3072]
    sgemm_nt<<<dim3((NH_ * DQK) / 128, BS / 128), blk>>>(qlora, wq_b, qbuf,
                                                         NH_ * DQK, QL, QL, QL, NH_ * DQK);
    // 4) rope(q_pe) in place
    rope_q_kernel<<<(BS * NH_ * 32) / 256, blk>>>(qbuf);
    // 5) kv = hs @ wkv_a^T               [4096, 576]
    sgemm_nt<<<dim3((KVL + DR + 127) / 128, BS / 128), blk>>>(hs, wkv_a, kvbuf,
                                                              KVL + DR, H_, H_, H_, KVL + DR);
    // 6) rmsnorm(kv_c), rope(k_pe)
    rmsnorm_kernel<<<BS, blk>>>(kvbuf, kvnw, KVL, KVL + DR);
    rope_k_kernel<<<(BS * 32) / 256, blk>>>(kvbuf);
    // 7) kv_x = kv_c @ wkv_b^T           [4096, 4096]
    sgemm_nt<<<dim3((NH_ * (DN + DV)) / 128, BS / 128), blk>>>(kvbuf, wkv_b, kvx,
                                                               NH_ * (DN + DV), KVL,
                                                               KVL + DR, KVL, NH_ * (DN + DV));
    // 8) flash attention                  -> attn [4096, 2048]
    cudaFuncSetAttribute(flash_kernel, cudaFuncAttributeMaxDynamicSharedMemorySize, FLASH_SMEM);
    flash_kernel<<<dim3(S_ / 64, NH_, B_), blk, FLASH_SMEM>>>(qbuf, kvx, kvbuf, attn);
    // 9) out = attn @ wo^T               [4096, 2048]
    sgemm_nt<<<dim3(H_ / 128, BS / 128), blk>>>(attn, wo, out, H_, NH_ * DV,
                                                NH_ * DV, NH_ * DV, H_);
}

// round 4
// speedup vs baseline: 1.3772x; 1.3772x over previous
#include <cuda_runtime.h>
#include <cuda_bf16.h>
#include <math.h>
#include <stdint.h>

// ---------------------------------------------------------------------------
// Problem constants (MLA prefill)
// ---------------------------------------------------------------------------
namespace {
constexpr int B_   = 2;
constexpr int S_   = 2048;
constexpr int H_   = 2048;
constexpr int NH_  = 16;
constexpr int QL   = 1536;
constexpr int KVL  = 512;
constexpr int DN   = 128;
constexpr int DR   = 64;
constexpr int DV   = 128;
constexpr int DQK  = 192;
constexpr int BS   = B_ * S_;
constexpr float SCALE = 0.07216878364870322f; // 1/sqrt(192)

constexpr int QK_LD = 193;
constexpr int FLASH_SMEM = (64 * QK_LD * 2 + 64 * 128 + 64 * 64) * 4; // 147,968 B
} // namespace

// ---------------------------------------------------------------------------
// Scratch (static device globals; no runtime allocation allowed)
// ---------------------------------------------------------------------------
__device__ float g_qlora[(size_t)BS * QL];
__device__ float g_q[(size_t)BS * NH_ * DQK];
__device__ float g_kv[(size_t)BS * (KVL + DR)];
__device__ float g_kvx[(size_t)BS * NH_ * (DN + DV)];
__device__ float g_attn[(size_t)BS * NH_ * DV];
__device__ __nv_bfloat16 g_a3[(size_t)4096 * 6144];  // activations: [hi | lo | hi]
__device__ __nv_bfloat16 g_b3[(size_t)3072 * 4608];  // weights:     [hi | hi | lo]
__device__ float g_freq[32];

// ---------------------------------------------------------------------------
// Helpers
// ---------------------------------------------------------------------------
__device__ __forceinline__ uint32_t smem_u32(const void* p) {
    uint32_t a;
    asm("{ .reg .u64 t; cvta.to.shared.u64 t, %1; cvt.u32.u64 %0, t; }" : "=r"(a) : "l"(p));
    return a;
}
__device__ __forceinline__ void cp_async16(uint32_t dst, const void* src) {
    asm volatile("cp.async.cg.shared.global [%0], [%1], 16;" :: "r"(dst), "l"(src) : "memory");
}
#define CP_COMMIT() asm volatile("cp.async.commit_group;" ::: "memory")
#define CP_WAIT1()  asm volatile("cp.async.wait_group 1;" ::: "memory")

__device__ __forceinline__ void ldsm_x4(uint32_t& r0, uint32_t& r1, uint32_t& r2, uint32_t& r3,
                                        uint32_t addr) {
    asm volatile("ldmatrix.sync.aligned.m8n8.x4.shared.b16 {%0,%1,%2,%3}, [%4];"
                 : "=r"(r0), "=r"(r1), "=r"(r2), "=r"(r3) : "r"(addr));
}
__device__ __forceinline__ void mma_bf16(float* c, const uint32_t* a, const uint32_t* b) {
    asm volatile("mma.sync.aligned.m16n8k16.row.col.f32.bf16.bf16.f32 "
                 "{%0,%1,%2,%3}, {%4,%5,%6,%7}, {%8,%9}, {%0,%1,%2,%3};"
                 : "+f"(c[0]), "+f"(c[1]), "+f"(c[2]), "+f"(c[3])
                 : "r"(a[0]), "r"(a[1]), "r"(a[2]), "r"(a[3]), "r"(b[0]), "r"(b[1]));
}
// swizzled byte offset inside a [128 rows x 64B] tile (16B chunk c in [0,4))
__device__ __forceinline__ uint32_t swoff(int r, int c) {
    return (uint32_t)(r * 64 + ((c ^ ((r >> 1) & 3)) << 4));
}

// ---------------------------------------------------------------------------
// Split-3 conversion along K.
//   mode 0 (activations): out = [hi | lo | hi]
//   mode 1 (weights):     out = [hi | hi | lo]
// A3 . B3^T per row-pair = hiA.hiB + loA.hiB + hiA.loB  (drops only loA.loB)
// Rows in [R, Rpad) are zero-filled (N padding for GEMM tiles).
// ---------------------------------------------------------------------------
__global__ void conv3_kernel(const float* __restrict__ in, __nv_bfloat16* __restrict__ out,
                             int R, int Rpad, int Kin, int ldin, int mode)
{
    const int kq = Kin >> 2;
    const int idx = blockIdx.x * blockDim.x + threadIdx.x;
    if (idx >= Rpad * kq) return;
    const int row = idx / kq, cg = idx - row * kq;
    float4 v = make_float4(0.f, 0.f, 0.f, 0.f);
    if (row < R) v = *(const float4*)(in + (size_t)row * ldin + cg * 4);
    const float vv[4] = {v.x, v.y, v.z, v.w};
    __nv_bfloat16 hi[4], lo[4];
    #pragma unroll
    for (int i = 0; i < 4; i++) {
        hi[i] = __float2bfloat16(vv[i]);
        lo[i] = __float2bfloat16(vv[i] - __bfloat162float(hi[i]));
    }
    const int seg_lo = mode ? 2 : 1;   // where lo goes
    const int seg_hi = mode ? 1 : 2;   // where the second hi copy goes
    __nv_bfloat16* p = out + (size_t)row * (3 * Kin) + cg * 4;
    *(__nv_bfloat162*)(p + 0) = __nv_bfloat162(hi[0], hi[1]);
    *(__nv_bfloat162*)(p + 2) = __nv_bfloat162(hi[2], hi[3]);
    *(__nv_bfloat162*)(p + seg_lo * Kin + 0) = __nv_bfloat162(lo[0], lo[1]);
    *(__nv_bfloat162*)(p + seg_lo * Kin + 2) = __nv_bfloat162(lo[2], lo[3]);
    *(__nv_bfloat162*)(p + seg_hi * Kin + 0) = __nv_bfloat162(hi[0], hi[1]);
    *(__nv_bfloat162*)(p + seg_hi * Kin + 2) = __nv_bfloat162(hi[2], hi[3]);
}

// ---------------------------------------------------------------------------
// HMMA bf16 GEMM:  C[M,N](f32) = A3[M,K3] * B3[Npad,K3]^T
// CTA 128x128x32, 8 warps (2x4), warp tile 64x32, mma.sync m16n8k16,
// 3-stage cp.async pipeline, swizzled smem + ldmatrix.
// ---------------------------------------------------------------------------
__global__ __launch_bounds__(256, 1)
void gemm_bf16_kernel(const __nv_bfloat16* __restrict__ A,
                      const __nv_bfloat16* __restrict__ Bw,
                      float* __restrict__ C, int N, int K3, int ldc)
{
    __shared__ __nv_bfloat16 smv[3][2][128 * 32]; // [stage][A|B][tile]
    const int tid = threadIdx.x;
    const int warp = tid >> 5, lane = tid & 31;
    const int m0 = blockIdx.y * 128, n0 = blockIdx.x * 128;
    const int NC = K3 / 32;

    const uint32_t sbase = smem_u32(&smv[0][0][0]);
    constexpr uint32_t STG  = 2u * 128 * 32 * 2; // bytes per stage (A+B)
    constexpr uint32_t BOFF = 128u * 32 * 2;     // B tile offset within stage

    // loader: per thread 2 A chunks + 2 B chunks of 16B (rows lr0 and lr0+64)
    const int lr0 = tid >> 2, lc0 = tid & 3;
    const uint32_t so0 = swoff(lr0, lc0);          // swizzle invariant under +64 rows
    const __nv_bfloat16* gA0 = A  + (size_t)(m0 + lr0) * K3 + lc0 * 8;
    const __nv_bfloat16* gB0 = Bw + (size_t)(n0 + lr0) * K3 + lc0 * 8;

    auto load_stage = [&](int kc, int s) {
        const uint32_t sb = sbase + s * STG;
        const size_t ko = (size_t)kc * 32;
        cp_async16(sb + so0,                  gA0 + ko);
        cp_async16(sb + so0 + 64 * 64,        gA0 + ko + (size_t)64 * K3);
        cp_async16(sb + BOFF + so0,           gB0 + ko);
        cp_async16(sb + BOFF + so0 + 64 * 64, gB0 + ko + (size_t)64 * K3);
    };

    // warp tile coordinates
    const int wm = (warp >> 2) * 64, wn = (warp & 3) * 32;
    // ldmatrix per-thread addressing
    const int rA = wm + (lane & 15), cA = lane >> 4;
    const int swzA = (rA >> 1) & 3;
    const int rB = wn + (lane & 7) + ((lane >> 4) << 3), cB = (lane >> 3) & 1;
    const int swzB = (rB >> 1) & 3;

    float acc[4][4][4];
    #pragma unroll
    for (int i = 0; i < 4; i++)
        #pragma unroll
        for (int j = 0; j < 4; j++)
            #pragma unroll
            for (int k = 0; k < 4; k++) acc[i][j][k] = 0.f;

    load_stage(0, 0); CP_COMMIT();
    load_stage(1, 1); CP_COMMIT();
    CP_WAIT1();
    __syncthreads();

    for (int kc = 0; kc < NC; kc++) {
        const int s = kc % 3;
        if (kc + 2 < NC) load_stage(kc + 2, (kc + 2) % 3);
        CP_COMMIT();

        const uint32_t sb = sbase + s * STG;
        #pragma unroll
        for (int h = 0; h < 2; h++) {
            uint32_t a[4][4], b[4][2];
            #pragma unroll
            for (int i = 0; i < 4; i++)
                ldsm_x4(a[i][0], a[i][1], a[i][2], a[i][3],
                        sb + (uint32_t)((rA + 16 * i) * 64 + (((h * 2 + cA) ^ swzA) << 4)));
            #pragma unroll
            for (int j = 0; j < 2; j++) {
                uint32_t r0, r1, r2, r3;
                ldsm_x4(r0, r1, r2, r3,
                        sb + BOFF + (uint32_t)((rB + 16 * j) * 64 + (((h * 2 + cB) ^ swzB) << 4)));
                b[2 * j][0] = r0; b[2 * j][1] = r1;
                b[2 * j + 1][0] = r2; b[2 * j + 1][1] = r3;
            }
            #pragma unroll
            for (int i = 0; i < 4; i++)
                #pragma unroll
                for (int t = 0; t < 4; t++)
                    mma_bf16(acc[i][t], a[i], b[t]);
        }
        CP_WAIT1();
        __syncthreads();
    }

    // epilogue: per thread, m16n8 fragment layout
    const int gr = lane >> 2, gc = (lane & 3) * 2;
    #pragma unroll
    for (int i = 0; i < 4; i++) {
        const int row0 = m0 + wm + i * 16 + gr;
        #pragma unroll
        for (int t = 0; t < 4; t++) {
            const int col = n0 + wn + t * 8 + gc;
            if (col < N) {
                *(float2*)(C + (size_t)row0 * ldc + col) =
                    make_float2(acc[i][t][0], acc[i][t][1]);
                *(float2*)(C + (size_t)(row0 + 8) * ldc + col) =
                    make_float2(acc[i][t][2], acc[i][t][3]);
            }
        }
    }
}

// ---------------------------------------------------------------------------
// RMSNorm (in place), one block per row
// ---------------------------------------------------------------------------
__global__ __launch_bounds__(256)
void rmsnorm_kernel(float* __restrict__ x, const float* __restrict__ w, int n, int ld)
{
    const int row = blockIdx.x;
    float* p = x + (size_t)row * ld;
    float ss = 0.f;
    for (int i = threadIdx.x; i < n; i += 256) { float v = p[i]; ss = fmaf(v, v, ss); }
    __shared__ float red[8];
    #pragma unroll
    for (int o = 16; o > 0; o >>= 1) ss += __shfl_xor_sync(0xffffffffu, ss, o);
    if ((threadIdx.x & 31) == 0) red[threadIdx.x >> 5] = ss;
    __syncthreads();
    __shared__ float s_inv;
    if (threadIdx.x == 0) {
        float t = 0.f;
        #pragma unroll
        for (int i = 0; i < 8; i++) t += red[i];
        s_inv = rsqrtf(t / (float)n + 1e-6f);
    }
    __syncthreads();
    const float inv = s_inv;
    for (int i = threadIdx.x; i < n; i += 256) p[i] = w[i] * p[i] * inv;
}

// ---------------------------------------------------------------------------
// RoPE (interleaved); frequencies precomputed once into g_freq
// ---------------------------------------------------------------------------
__global__ void freq_init_kernel()
{
    if (threadIdx.x < 32)
        g_freq[threadIdx.x] = (float)pow(10000.0, -(double)threadIdx.x / 32.0);
}

__device__ __forceinline__ void rope_pair(float* p, int pos, int i)
{
    const float f = (float)pos * g_freq[i];
    float sn, c;
    sincosf(f, &sn, &c);
    const float e = p[0], o = p[1];
    p[0] = e * c - o * sn;
    p[1] = e * sn + o * c;
}

__global__ void rope_q_kernel(float* __restrict__ q)
{
    const int idx = blockIdx.x * blockDim.x + threadIdx.x;
    const int i   = idx & 31;
    const int h   = (idx >> 5) & (NH_ - 1);
    const int row = idx >> 9;
    const int s   = row & (S_ - 1);
    rope_pair(q + (size_t)row * (NH_ * DQK) + h * DQK + DN + 2 * i, s, i);
}

__global__ void rope_k_kernel(float* __restrict__ kv)
{
    const int idx = blockIdx.x * blockDim.x + threadIdx.x;
    const int i   = idx & 31;
    const int row = idx >> 5;
    const int s   = row & (S_ - 1);
    rope_pair(kv + (size_t)row * (KVL + DR) + KVL + 2 * i, s, i);
}

// ---------------------------------------------------------------------------
// Flash attention, fp32 (proven correct in R1)
// ---------------------------------------------------------------------------
__global__ __launch_bounds__(256)
void flash_kernel(const float* __restrict__ q, const float* __restrict__ kvx,
                  const float* __restrict__ kv, float* __restrict__ out)
{
    extern __shared__ float fsm[];
    float* Qs = fsm;
    float* Ks = Qs + 64 * QK_LD;
    float* Vs = Ks + 64 * QK_LD;
    float* Ps = Vs + 64 * 128;

    const int h  = blockIdx.y, b = blockIdx.z;
    const int q0 = blockIdx.x * 64;
    const int tid = threadIdx.x;
    const int ty = tid >> 4, tx = tid & 15;

    for (int u = tid; u < 64 * 48; u += 256) {
        const int r = u / 48, c = (u % 48) << 2;
        float4 a = *(const float4*)(q + (size_t)(b * S_ + q0 + r) * (NH_ * DQK) + h * DQK + c);
        Qs[r * QK_LD + c + 0] = a.x; Qs[r * QK_LD + c + 1] = a.y;
        Qs[r * QK_LD + c + 2] = a.z; Qs[r * QK_LD + c + 3] = a.w;
    }

    float m[4], l[4], acc[4][8];
    #pragma unroll
    for (int i = 0; i < 4; i++) {
        m[i] = -1e30f; l[i] = 0.f;
        #pragma unroll
        for (int c = 0; c < 8; c++) acc[i][c] = 0.f;
    }

    for (int kt = 0; kt < S_; kt += 64) {
        __syncthreads();
        for (int u = tid; u < 64 * 32; u += 256) {
            const int r = u >> 5, c = (u & 31) << 2;
            float4 a = *(const float4*)(kvx + (size_t)(b * S_ + kt + r) * (NH_ * (DN + DV))
                                        + h * (DN + DV) + c);
            Ks[r * QK_LD + c + 0] = a.x; Ks[r * QK_LD + c + 1] = a.y;
            Ks[r * QK_LD + c + 2] = a.z; Ks[r * QK_LD + c + 3] = a.w;
        }
        for (int u = tid; u < 64 * 16; u += 256) {
            const int r = u >> 4, c = (u & 15) << 2;
            float4 a = *(const float4*)(kv + (size_t)(b * S_ + kt + r) * (KVL + DR) + KVL + c);
            Ks[r * QK_LD + DN + c + 0] = a.x; Ks[r * QK_LD + DN + c + 1] = a.y;
            Ks[r * QK_LD + DN + c + 2] = a.z; Ks[r * QK_LD + DN + c + 3] = a.w;
        }
        for (int u = tid; u < 64 * 32; u += 256) {
            const int r = u >> 5, c = (u & 31) << 2;
            *(float4*)&Vs[r * 128 + c] =
                *(const float4*)(kvx + (size_t)(b * S_ + kt + r) * (NH_ * (DN + DV))
                                 + h * (DN + DV) + DN + c);
        }
        __syncthreads();

        float sc[4][4];
        #pragma unroll
        for (int i = 0; i < 4; i++)
            #pragma unroll
            for (int j = 0; j < 4; j++) sc[i][j] = 0.f;
        for (int k = 0; k < DQK; k++) {
            float av[4], bv[4];
            #pragma unroll
            for (int i = 0; i < 4; i++) av[i] = Qs[(ty * 4 + i) * QK_LD + k];
            #pragma unroll
            for (int j = 0; j < 4; j++) bv[j] = Ks[(tx * 4 + j) * QK_LD + k];
            #pragma unroll
            for (int i = 0; i < 4; i++)
                #pragma unroll
                for (int j = 0; j < 4; j++)
                    sc[i][j] = fmaf(av[i], bv[j], sc[i][j]);
        }

        #pragma unroll
        for (int i = 0; i < 4; i++) {
            float mx = -1e30f;
            #pragma unroll
            for (int j = 0; j < 4; j++) { sc[i][j] *= SCALE; mx = fmaxf(mx, sc[i][j]); }
            #pragma unroll
            for (int o = 1; o < 16; o <<= 1) mx = fmaxf(mx, __shfl_xor_sync(0xffffffffu, mx, o));
            const float mnew  = fmaxf(m[i], mx);
            const float alpha = __expf(m[i] - mnew);
            float rs = 0.f;
            #pragma unroll
            for (int j = 0; j < 4; j++) {
                const float pij = __expf(sc[i][j] - mnew);
                sc[i][j] = pij; rs += pij;
            }
            #pragma unroll
            for (int o = 1; o < 16; o <<= 1) rs += __shfl_xor_sync(0xffffffffu, rs, o);
            l[i] = l[i] * alpha + rs;
            m[i] = mnew;
            #pragma unroll
            for (int c = 0; c < 8; c++) acc[i][c] *= alpha;
            #pragma unroll
            for (int j = 0; j < 4; j++)
                Ps[(ty * 4 + i) * 64 + tx * 4 + j] = sc[i][j];
        }
        __syncthreads();

        for (int kk = 0; kk < 64; kk++) {
            float pv[4];
            #pragma unroll
            for (int i = 0; i < 4; i++) pv[i] = Ps[(ty * 4 + i) * 64 + kk];
            const float4 v0 = *(const float4*)&Vs[kk * 128 + tx * 8];
            const float4 v1 = *(const float4*)&Vs[kk * 128 + tx * 8 + 4];
            const float vv[8] = {v0.x, v0.y, v0.z, v0.w, v1.x, v1.y, v1.z, v1.w};
            #pragma unroll
            for (int i = 0; i < 4; i++)
                #pragma unroll
                for (int c = 0; c < 8; c++)
                    acc[i][c] = fmaf(pv[i], vv[c], acc[i][c]);
        }
    }

    #pragma unroll
    for (int i = 0; i < 4; i++) {
        const float inv = 1.f / l[i];
        const int row = b * S_ + q0 + ty * 4 + i;
        float4 o0 = make_float4(acc[i][0] * inv, acc[i][1] * inv, acc[i][2] * inv, acc[i][3] * inv);
        float4 o1 = make_float4(acc[i][4] * inv, acc[i][5] * inv, acc[i][6] * inv, acc[i][7] * inv);
        *(float4*)(out + (size_t)row * (NH_ * DV) + h * DV + tx * 8)     = o0;
        *(float4*)(out + (size_t)row * (NH_ * DV) + h * DV + tx * 8 + 4) = o1;
    }
}

// ---------------------------------------------------------------------------
// Launcher
// ---------------------------------------------------------------------------
static inline void run_conv3(const float* in, __nv_bfloat16* out, int R, int Rpad,
                             int Kin, int ldin, int mode)
{
    const int total = Rpad * (Kin / 4);
    conv3_kernel<<<(total + 255) / 256, 256>>>(in, out, R, Rpad, Kin, ldin, mode);
}

static inline void run_gemm(const __nv_bfloat16* A, const __nv_bfloat16* Bw, float* C,
                            int Npad, int N, int K3, int ldc)
{
    gemm_bf16_kernel<<<dim3(Npad / 128, BS / 128), 256>>>(A, Bw, C, N, K3, ldc);
}

extern "C" void kernel_launch(void* const* d_in, const int* in_sizes, int n_in,
                              void* d_out, int out_size)
{
    const float* hs    = (const float*)d_in[0];
    const float* wq_a  = (const float*)d_in[1];
    const float* qnw   = (const float*)d_in[2];
    const float* wq_b  = (const float*)d_in[3];
    const float* wkv_a = (const float*)d_in[4];
    const float* kvnw  = (const float*)d_in[5];
    const float* wkv_b = (const float*)d_in[6];
    const float* wo    = (const float*)d_in[7];
    float* out = (float*)d_out;

    void* p;
    cudaGetSymbolAddress(&p, g_qlora); float* qlora = (float*)p;
    cudaGetSymbolAddress(&p, g_q);     float* qbuf  = (float*)p;
    cudaGetSymbolAddress(&p, g_kv);    float* kvbuf = (float*)p;
    cudaGetSymbolAddress(&p, g_kvx);   float* kvx   = (float*)p;
    cudaGetSymbolAddress(&p, g_attn);  float* attn  = (float*)p;
    cudaGetSymbolAddress(&p, g_a3);    __nv_bfloat16* a3 = (__nv_bfloat16*)p;
    cudaGetSymbolAddress(&p, g_b3);    __nv_bfloat16* b3 = (__nv_bfloat16*)p;

    cudaFuncSetAttribute(flash_kernel, cudaFuncAttributeMaxDynamicSharedMemorySize, FLASH_SMEM);

    freq_init_kernel<<<1, 32>>>();

    // 1) q_lora = hs @ wq_a^T        [4096, 1536], K=2048 -> K3=6144
    run_conv3(hs, a3, BS, BS, H_, H_, 0);
    run_conv3(wq_a, b3, QL, QL, H_, H_, 1);
    run_gemm(a3, b3, qlora, QL, QL, 3 * H_, QL);

    // 2) kv = hs @ wkv_a^T           [4096, 576] (Npad 640)
    run_conv3(wkv_a, b3, KVL + DR, 640, H_, H_, 1);
    run_gemm(a3, b3, kvbuf, 640, KVL + DR, 3 * H_, KVL + DR);

    // 3) norms + k rope
    rmsnorm_kernel<<<BS, 256>>>(qlora, qnw, QL, QL);
    rmsnorm_kernel<<<BS, 256>>>(kvbuf, kvnw, KVL, KVL + DR);
    rope_k_kernel<<<(BS * 32) / 256, 256>>>(kvbuf);

    // 4) q = q_lora @ wq_b^T         [4096, 3072], K=1536 -> K3=4608
    run_conv3(qlora, a3, BS, BS, QL, QL, 0);
    run_conv3(wq_b, b3, NH_ * DQK, NH_ * DQK, QL, QL, 1);
    run_gemm(a3, b3, qbuf, NH_ * DQK, NH_ * DQK, 3 * QL, NH_ * DQK);
    rope_q_kernel<<<(BS * NH_ * 32) / 256, 256>>>(qbuf);

    // 5) kv_x = kv_c @ wkv_b^T       [4096, 4096], K=512 -> K3=1536
    run_conv3(kvbuf, a3, BS, BS, KVL, KVL + DR, 0);
    run_conv3(wkv_b, b3, NH_ * (DN + DV), NH_ * (DN + DV), KVL, KVL, 1);
    run_gemm(a3, b3, kvx, NH_ * (DN + DV), NH_ * (DN + DV), 3 * KVL, NH_ * (DN + DV));

    // 6) flash attention -> attn [4096, 2048]
    flash_kernel<<<dim3(S_ / 64, NH_, B_), 256, FLASH_SMEM>>>(qbuf, kvx, kvbuf, attn);

    // 7) out = attn @ wo^T           [4096, 2048], K=2048 -> K3=6144
    run_conv3(attn, a3, BS, BS, NH_ * DV, NH_ * DV, 0);
    run_conv3(wo, b3, H_, H_, NH_ * DV, NH_ * DV, 1);
    run_gemm(a3, b3, out, H_, H_, 3 * NH_ * DV, H_);
}

// round 6
// speedup vs baseline: 3.0198x; 2.1927x over previous
#include <cuda_runtime.h>
#include <cuda_bf16.h>
#include <math.h>
#include <stdint.h>

// ---------------------------------------------------------------------------
// Problem constants (MLA prefill)
// ---------------------------------------------------------------------------
namespace {
constexpr int B_   = 2;
constexpr int S_   = 2048;
constexpr int H_   = 2048;
constexpr int NH_  = 16;
constexpr int QL   = 1536;
constexpr int KVL  = 512;
constexpr int DN   = 128;
constexpr int DR   = 64;
constexpr int DV   = 128;
constexpr int DQK  = 192;
constexpr int BS   = B_ * S_;
constexpr float SCALE = 0.07216878364870322f; // 1/sqrt(192)

// flash smem: Qh/Ql [128][pitch200], Kh/Kl [64][200], Vth/Vtl [128][72]
constexpr int SM_QH  = 0;
constexpr int SM_QL  = SM_QH + 128 * 400;
constexpr int SM_KH  = SM_QL + 128 * 400;
constexpr int SM_KL  = SM_KH + 64 * 400;
constexpr int SM_VH  = SM_KL + 64 * 400;
constexpr int SM_VL  = SM_VH + 128 * 144;
constexpr int FLASH_SMEM = SM_VL + 128 * 144; // 190,464 B
} // namespace

// ---------------------------------------------------------------------------
// Scratch (static device globals; no runtime allocation allowed)
// ---------------------------------------------------------------------------
__device__ float g_qlora[(size_t)BS * QL];
__device__ float g_q[(size_t)BS * NH_ * DQK];
__device__ float g_kv[(size_t)BS * (KVL + DR)];
__device__ float g_kvx[(size_t)BS * NH_ * (DN + DV)];
__device__ float g_attn[(size_t)BS * NH_ * DV];
__device__ __nv_bfloat16 g_a3[(size_t)4096 * 6144];  // activations: [hi | lo | hi]
__device__ __nv_bfloat16 g_b3[(size_t)3072 * 4608];  // weights:     [hi | hi | lo]
// flash operands (bf16 hi/lo)
__device__ __nv_bfloat16 g_qh[(size_t)BS * NH_ * DQK];
__device__ __nv_bfloat16 g_ql2[(size_t)BS * NH_ * DQK];
__device__ __nv_bfloat16 g_kh[(size_t)BS * NH_ * DQK];
__device__ __nv_bfloat16 g_kl[(size_t)BS * NH_ * DQK];
__device__ __nv_bfloat16 g_vth[(size_t)B_ * NH_ * DV * S_];  // [b][h][dv][s]
__device__ __nv_bfloat16 g_vtl[(size_t)B_ * NH_ * DV * S_];
__device__ float g_freq[32];

// ---------------------------------------------------------------------------
// Helpers
// ---------------------------------------------------------------------------
__device__ __forceinline__ uint32_t smem_u32(const void* p) {
    uint32_t a;
    asm("{ .reg .u64 t; cvta.to.shared.u64 t, %1; cvt.u32.u64 %0, t; }" : "=r"(a) : "l"(p));
    return a;
}
__device__ __forceinline__ void cp_async16(uint32_t dst, const void* src) {
    asm volatile("cp.async.cg.shared.global [%0], [%1], 16;" :: "r"(dst), "l"(src) : "memory");
}
#define CP_COMMIT() asm volatile("cp.async.commit_group;" ::: "memory")
#define CP_WAIT1()  asm volatile("cp.async.wait_group 1;" ::: "memory")
#define CP_WAIT0()  asm volatile("cp.async.wait_group 0;" ::: "memory")

__device__ __forceinline__ void ldsm_x4(uint32_t& r0, uint32_t& r1, uint32_t& r2, uint32_t& r3,
                                        uint32_t addr) {
    asm volatile("ldmatrix.sync.aligned.m8n8.x4.shared.b16 {%0,%1,%2,%3}, [%4];"
                 : "=r"(r0), "=r"(r1), "=r"(r2), "=r"(r3) : "r"(addr));
}
__device__ __forceinline__ void mma_bf16(float* c, const uint32_t* a, const uint32_t* b) {
    asm volatile("mma.sync.aligned.m16n8k16.row.col.f32.bf16.bf16.f32 "
                 "{%0,%1,%2,%3}, {%4,%5,%6,%7}, {%8,%9}, {%0,%1,%2,%3};"
                 : "+f"(c[0]), "+f"(c[1]), "+f"(c[2]), "+f"(c[3])
                 : "r"(a[0]), "r"(a[1]), "r"(a[2]), "r"(a[3]), "r"(b[0]), "r"(b[1]));
}
__device__ __forceinline__ uint32_t swoff(int r, int c) {
    return (uint32_t)(r * 64 + ((c ^ ((r >> 1) & 3)) << 4));
}
__device__ __forceinline__ uint32_t pack_bf2(float x, float y) {
    __nv_bfloat162 t(__float2bfloat16(x), __float2bfloat16(y));
    return *(uint32_t*)&t;
}

// ---------------------------------------------------------------------------
// Split-3 conversion for GEMMs (proven in R4)
// ---------------------------------------------------------------------------
__global__ void conv3_kernel(const float* __restrict__ in, __nv_bfloat16* __restrict__ out,
                             int R, int Rpad, int Kin, int ldin, int mode)
{
    const int kq = Kin >> 2;
    const int idx = blockIdx.x * blockDim.x + threadIdx.x;
    if (idx >= Rpad * kq) return;
    const int row = idx / kq, cg = idx - row * kq;
    float4 v = make_float4(0.f, 0.f, 0.f, 0.f);
    if (row < R) v = *(const float4*)(in + (size_t)row * ldin + cg * 4);
    const float vv[4] = {v.x, v.y, v.z, v.w};
    __nv_bfloat16 hi[4], lo[4];
    #pragma unroll
    for (int i = 0; i < 4; i++) {
        hi[i] = __float2bfloat16(vv[i]);
        lo[i] = __float2bfloat16(vv[i] - __bfloat162float(hi[i]));
    }
    const int seg_lo = mode ? 2 : 1;
    const int seg_hi = mode ? 1 : 2;
    __nv_bfloat16* p = out + (size_t)row * (3 * Kin) + cg * 4;
    *(__nv_bfloat162*)(p + 0) = __nv_bfloat162(hi[0], hi[1]);
    *(__nv_bfloat162*)(p + 2) = __nv_bfloat162(hi[2], hi[3]);
    *(__nv_bfloat162*)(p + seg_lo * Kin + 0) = __nv_bfloat162(lo[0], lo[1]);
    *(__nv_bfloat162*)(p + seg_lo * Kin + 2) = __nv_bfloat162(lo[2], lo[3]);
    *(__nv_bfloat162*)(p + seg_hi * Kin + 0) = __nv_bfloat162(hi[0], hi[1]);
    *(__nv_bfloat162*)(p + seg_hi * Kin + 2) = __nv_bfloat162(hi[2], hi[3]);
}

// ---------------------------------------------------------------------------
// HMMA bf16 GEMM (proven in R4)
// ---------------------------------------------------------------------------
__global__ __launch_bounds__(256, 1)
void gemm_bf16_kernel(const __nv_bfloat16* __restrict__ A,
                      const __nv_bfloat16* __restrict__ Bw,
                      float* __restrict__ C, int N, int K3, int ldc)
{
    __shared__ __nv_bfloat16 smv[3][2][128 * 32];
    const int tid = threadIdx.x;
    const int warp = tid >> 5, lane = tid & 31;
    const int m0 = blockIdx.y * 128, n0 = blockIdx.x * 128;
    const int NC = K3 / 32;

    const uint32_t sbase = smem_u32(&smv[0][0][0]);
    constexpr uint32_t STG  = 2u * 128 * 32 * 2;
    constexpr uint32_t BOFF = 128u * 32 * 2;

    const int lr0 = tid >> 2, lc0 = tid & 3;
    const uint32_t so0 = swoff(lr0, lc0);
    const __nv_bfloat16* gA0 = A  + (size_t)(m0 + lr0) * K3 + lc0 * 8;
    const __nv_bfloat16* gB0 = Bw + (size_t)(n0 + lr0) * K3 + lc0 * 8;

    auto load_stage = [&](int kc, int s) {
        const uint32_t sb = sbase + s * STG;
        const size_t ko = (size_t)kc * 32;
        cp_async16(sb + so0,                  gA0 + ko);
        cp_async16(sb + so0 + 64 * 64,        gA0 + ko + (size_t)64 * K3);
        cp_async16(sb + BOFF + so0,           gB0 + ko);
        cp_async16(sb + BOFF + so0 + 64 * 64, gB0 + ko + (size_t)64 * K3);
    };

    const int wm = (warp >> 2) * 64, wn = (warp & 3) * 32;
    const int rA = wm + (lane & 15), cA = lane >> 4;
    const int swzA = (rA >> 1) & 3;
    const int rB = wn + (lane & 7) + ((lane >> 4) << 3), cB = (lane >> 3) & 1;
    const int swzB = (rB >> 1) & 3;

    float acc[4][4][4];
    #pragma unroll
    for (int i = 0; i < 4; i++)
        #pragma unroll
        for (int j = 0; j < 4; j++)
            #pragma unroll
            for (int k = 0; k < 4; k++) acc[i][j][k] = 0.f;

    load_stage(0, 0); CP_COMMIT();
    load_stage(1, 1); CP_COMMIT();
    CP_WAIT1();
    __syncthreads();

    for (int kc = 0; kc < NC; kc++) {
        const int s = kc % 3;
        if (kc + 2 < NC) load_stage(kc + 2, (kc + 2) % 3);
        CP_COMMIT();

        const uint32_t sb = sbase + s * STG;
        #pragma unroll
        for (int h = 0; h < 2; h++) {
            uint32_t a[4][4], b[4][2];
            #pragma unroll
            for (int i = 0; i < 4; i++)
                ldsm_x4(a[i][0], a[i][1], a[i][2], a[i][3],
                        sb + (uint32_t)((rA + 16 * i) * 64 + (((h * 2 + cA) ^ swzA) << 4)));
            #pragma unroll
            for (int j = 0; j < 2; j++) {
                uint32_t r0, r1, r2, r3;
                ldsm_x4(r0, r1, r2, r3,
                        sb + BOFF + (uint32_t)((rB + 16 * j) * 64 + (((h * 2 + cB) ^ swzB) << 4)));
                b[2 * j][0] = r0; b[2 * j][1] = r1;
                b[2 * j + 1][0] = r2; b[2 * j + 1][1] = r3;
            }
            #pragma unroll
            for (int i = 0; i < 4; i++)
                #pragma unroll
                for (int t = 0; t < 4; t++)
                    mma_bf16(acc[i][t], a[i], b[t]);
        }
        CP_WAIT1();
        __syncthreads();
    }

    const int gr = lane >> 2, gc = (lane & 3) * 2;
    #pragma unroll
    for (int i = 0; i < 4; i++) {
        const int row0 = m0 + wm + i * 16 + gr;
        #pragma unroll
        for (int t = 0; t < 4; t++) {
            const int col = n0 + wn + t * 8 + gc;
            if (col < N) {
                *(float2*)(C + (size_t)row0 * ldc + col) =
                    make_float2(acc[i][t][0], acc[i][t][1]);
                *(float2*)(C + (size_t)(row0 + 8) * ldc + col) =
                    make_float2(acc[i][t][2], acc[i][t][3]);
            }
        }
    }
}

// ---------------------------------------------------------------------------
// RMSNorm / RoPE
// ---------------------------------------------------------------------------
__global__ __launch_bounds__(256)
void rmsnorm_kernel(float* __restrict__ x, const float* __restrict__ w, int n, int ld)
{
    const int row = blockIdx.x;
    float* p = x + (size_t)row * ld;
    float ss = 0.f;
    for (int i = threadIdx.x; i < n; i += 256) { float v = p[i]; ss = fmaf(v, v, ss); }
    __shared__ float red[8];
    #pragma unroll
    for (int o = 16; o > 0; o >>= 1) ss += __shfl_xor_sync(0xffffffffu, ss, o);
    if ((threadIdx.x & 31) == 0) red[threadIdx.x >> 5] = ss;
    __syncthreads();
    __shared__ float s_inv;
    if (threadIdx.x == 0) {
        float t = 0.f;
        #pragma unroll
        for (int i = 0; i < 8; i++) t += red[i];
        s_inv = rsqrtf(t / (float)n + 1e-6f);
    }
    __syncthreads();
    const float inv = s_inv;
    for (int i = threadIdx.x; i < n; i += 256) p[i] = w[i] * p[i] * inv;
}

__global__ void freq_init_kernel()
{
    if (threadIdx.x < 32)
        g_freq[threadIdx.x] = (float)pow(10000.0, -(double)threadIdx.x / 32.0);
}

__device__ __forceinline__ void rope_pair(float* p, int pos, int i)
{
    const float f = (float)pos * g_freq[i];
    float sn, c;
    sincosf(f, &sn, &c);
    const float e = p[0], o = p[1];
    p[0] = e * c - o * sn;
    p[1] = e * sn + o * c;
}

__global__ void rope_q_kernel(float* __restrict__ q)
{
    const int idx = blockIdx.x * blockDim.x + threadIdx.x;
    const int i   = idx & 31;
    const int h   = (idx >> 5) & (NH_ - 1);
    const int row = idx >> 9;
    const int s   = row & (S_ - 1);
    rope_pair(q + (size_t)row * (NH_ * DQK) + h * DQK + DN + 2 * i, s, i);
}

__global__ void rope_k_kernel(float* __restrict__ kv)
{
    const int idx = blockIdx.x * blockDim.x + threadIdx.x;
    const int i   = idx & 31;
    const int row = idx >> 5;
    const int s   = row & (S_ - 1);
    rope_pair(kv + (size_t)row * (KVL + DR) + KVL + 2 * i, s, i);
}

// ---------------------------------------------------------------------------
// Flash prep conversions
// ---------------------------------------------------------------------------
__global__ void conv_hl_kernel(const float* __restrict__ in,
                               __nv_bfloat16* __restrict__ hi_o,
                               __nv_bfloat16* __restrict__ lo_o, int n4)
{
    const int idx = blockIdx.x * blockDim.x + threadIdx.x;
    if (idx >= n4) return;
    float4 v = *(const float4*)(in + (size_t)idx * 4);
    const float vv[4] = {v.x, v.y, v.z, v.w};
    __nv_bfloat16 hi[4], lo[4];
    #pragma unroll
    for (int i = 0; i < 4; i++) {
        hi[i] = __float2bfloat16(vv[i]);
        lo[i] = __float2bfloat16(vv[i] - __bfloat162float(hi[i]));
    }
    *(__nv_bfloat162*)(hi_o + (size_t)idx * 4 + 0) = __nv_bfloat162(hi[0], hi[1]);
    *(__nv_bfloat162*)(hi_o + (size_t)idx * 4 + 2) = __nv_bfloat162(hi[2], hi[3]);
    *(__nv_bfloat162*)(lo_o + (size_t)idx * 4 + 0) = __nv_bfloat162(lo[0], lo[1]);
    *(__nv_bfloat162*)(lo_o + (size_t)idx * 4 + 2) = __nv_bfloat162(lo[2], lo[3]);
}

// K assembly: [row][h][192] = kvx nope (per-head) | g_kv pe (shared) -> hi/lo
__global__ void convk_kernel(const float* __restrict__ kvx, const float* __restrict__ kv,
                             __nv_bfloat16* __restrict__ kh, __nv_bfloat16* __restrict__ kl)
{
    const int idx = blockIdx.x * blockDim.x + threadIdx.x; // (row, h, dg) dg in [0,48)
    if (idx >= BS * NH_ * 48) return;
    const int dg  = idx % 48;
    const int h   = (idx / 48) & (NH_ - 1);
    const int row = idx / (48 * NH_);
    float4 v;
    if (dg < 32) v = *(const float4*)(kvx + (size_t)row * (NH_ * 256) + h * 256 + dg * 4);
    else         v = *(const float4*)(kv + (size_t)row * (KVL + DR) + KVL + (dg - 32) * 4);
    const float vv[4] = {v.x, v.y, v.z, v.w};
    __nv_bfloat16 hi[4], lo[4];
    #pragma unroll
    for (int i = 0; i < 4; i++) {
        hi[i] = __float2bfloat16(vv[i]);
        lo[i] = __float2bfloat16(vv[i] - __bfloat162float(hi[i]));
    }
    const size_t o = ((size_t)row * NH_ + h) * 192 + dg * 4;
    *(__nv_bfloat162*)(kh + o + 0) = __nv_bfloat162(hi[0], hi[1]);
    *(__nv_bfloat162*)(kh + o + 2) = __nv_bfloat162(hi[2], hi[3]);
    *(__nv_bfloat162*)(kl + o + 0) = __nv_bfloat162(lo[0], lo[1]);
    *(__nv_bfloat162*)(kl + o + 2) = __nv_bfloat162(lo[2], lo[3]);
}

// V transpose: kvx[.,h,128+dv] (row=b*S+s) -> vt[b][h][dv][s], hi/lo
__global__ void convvt_kernel(const float* __restrict__ kvx,
                              __nv_bfloat16* __restrict__ vth, __nv_bfloat16* __restrict__ vtl)
{
    __shared__ float tile[32][33];
    const int bh = blockIdx.z;               // b*NH + h
    const int b = bh >> 4, h = bh & 15;
    const int s0 = blockIdx.x * 32, dv0 = blockIdx.y * 32;
    const int tx = threadIdx.x, ty = threadIdx.y;
    #pragma unroll
    for (int j = 0; j < 4; j++) {
        const int s = s0 + ty + 8 * j;
        tile[ty + 8 * j][tx] =
            kvx[(size_t)(b * S_ + s) * (NH_ * 256) + h * 256 + DN + dv0 + tx];
    }
    __syncthreads();
    #pragma unroll
    for (int j = 0; j < 4; j++) {
        const int dv = dv0 + ty + 8 * j;
        const float v = tile[tx][ty + 8 * j];
        const __nv_bfloat16 hi = __float2bfloat16(v);
        const __nv_bfloat16 lo = __float2bfloat16(v - __bfloat162float(hi));
        const size_t o = ((size_t)bh * DV + dv) * S_ + s0 + tx;
        vth[o] = hi; vtl[o] = lo;
    }
}

// ---------------------------------------------------------------------------
// Flash attention on HMMA (bf16 split-3 both phases)
// CTA: 128 q rows x (head, batch); 8 warps x 16 rows; key tiles of 64.
// ---------------------------------------------------------------------------
__global__ __launch_bounds__(256, 1)
void flash_mma_kernel(const __nv_bfloat16* __restrict__ qh, const __nv_bfloat16* __restrict__ ql,
                      const __nv_bfloat16* __restrict__ kh, const __nv_bfloat16* __restrict__ kl,
                      const __nv_bfloat16* __restrict__ vth, const __nv_bfloat16* __restrict__ vtl,
                      float* __restrict__ out)
{
    extern __shared__ __align__(128) char sm[];
    const uint32_t sb = smem_u32(sm);
    const int tid = threadIdx.x, warp = tid >> 5, lane = tid & 31;
    const int h = blockIdx.y, b = blockIdx.z;
    const int q0 = blockIdx.x * 128;
    const int wr = warp * 16;

    // Q tiles -> smem (hi + lo), pitch 400 B
    for (int u = tid; u < 128 * 24; u += 256) {
        const int r = u / 24, c = u % 24;
        const size_t off = ((size_t)(b * S_ + q0 + r) * NH_ + h) * 192 + c * 8;
        cp_async16(sb + SM_QH + r * 400 + c * 16, qh + off);
        cp_async16(sb + SM_QL + r * 400 + c * 16, ql + off);
    }

    float oacc[16][4];
    #pragma unroll
    for (int i = 0; i < 16; i++)
        #pragma unroll
        for (int j = 0; j < 4; j++) oacc[i][j] = 0.f;
    float m0 = -1e30f, m1 = -1e30f, l0 = 0.f, l1 = 0.f;

    // ldmatrix lane addressing (same scheme as proven gemm)
    const uint32_t aQoff = (uint32_t)(wr + (lane & 15)) * 400 + ((lane >> 4) << 4);
    const int rB8  = (lane & 7) + ((lane >> 4) << 3);
    const uint32_t bKoff = (uint32_t)rB8 * 400 + (((lane >> 3) & 1) << 4);
    const uint32_t bVoff = (uint32_t)rB8 * 144 + (((lane >> 3) & 1) << 4);

    for (int kt = 0; kt < S_; kt += 64) {
        __syncthreads(); // previous tile fully consumed
        // K tile (hi+lo)
        for (int u = tid; u < 64 * 24; u += 256) {
            const int r = u / 24, c = u % 24;
            const size_t off = ((size_t)(b * S_ + kt + r) * NH_ + h) * 192 + c * 8;
            cp_async16(sb + SM_KH + r * 400 + c * 16, kh + off);
            cp_async16(sb + SM_KL + r * 400 + c * 16, kl + off);
        }
        // Vt tile (hi+lo), pitch 144 B  [FIXED: offset is kt + ck*8, not kt*64]
        for (int u = tid; u < 128 * 8; u += 256) {
            const int dv = u / 8, ck = u % 8;
            const size_t off = ((size_t)(b * NH_ + h) * DV + dv) * S_ + kt + ck * 8;
            cp_async16(sb + SM_VH + dv * 144 + ck * 16, vth + off);
            cp_async16(sb + SM_VL + dv * 144 + ck * 16, vtl + off);
        }
        CP_COMMIT();
        CP_WAIT0();
        __syncthreads();

        // ---- S = Q K^T (3 segments over d=192) ----
        float sacc[8][4];
        #pragma unroll
        for (int i = 0; i < 8; i++)
            #pragma unroll
            for (int j = 0; j < 4; j++) sacc[i][j] = 0.f;

        #pragma unroll
        for (int seg = 0; seg < 3; seg++) {
            const uint32_t qb = sb + (seg == 1 ? SM_QL : SM_QH);
            const uint32_t kb = sb + (seg == 2 ? SM_KL : SM_KH);
            #pragma unroll
            for (int ks = 0; ks < 12; ks++) {
                uint32_t a[4];
                ldsm_x4(a[0], a[1], a[2], a[3], qb + aQoff + ks * 32);
                #pragma unroll
                for (int g = 0; g < 4; g++) {
                    uint32_t r0, r1, r2, r3;
                    ldsm_x4(r0, r1, r2, r3, kb + bKoff + (uint32_t)g * 16 * 400 + ks * 32);
                    uint32_t b0[2] = {r0, r1}, b1[2] = {r2, r3};
                    mma_bf16(sacc[2 * g], a, b0);
                    mma_bf16(sacc[2 * g + 1], a, b1);
                }
            }
        }

        // ---- online softmax (rows gr and gr+8) ----
        float mx0 = -1e30f, mx1 = -1e30f;
        #pragma unroll
        for (int nt = 0; nt < 8; nt++) {
            #pragma unroll
            for (int j = 0; j < 4; j++) sacc[nt][j] *= SCALE;
            mx0 = fmaxf(mx0, fmaxf(sacc[nt][0], sacc[nt][1]));
            mx1 = fmaxf(mx1, fmaxf(sacc[nt][2], sacc[nt][3]));
        }
        mx0 = fmaxf(mx0, __shfl_xor_sync(0xffffffffu, mx0, 1));
        mx0 = fmaxf(mx0, __shfl_xor_sync(0xffffffffu, mx0, 2));
        mx1 = fmaxf(mx1, __shfl_xor_sync(0xffffffffu, mx1, 1));
        mx1 = fmaxf(mx1, __shfl_xor_sync(0xffffffffu, mx1, 2));
        const float mn0 = fmaxf(m0, mx0), mn1 = fmaxf(m1, mx1);
        const float al0 = __expf(m0 - mn0), al1 = __expf(m1 - mn1);
        float rs0 = 0.f, rs1 = 0.f;
        #pragma unroll
        for (int nt = 0; nt < 8; nt++) {
            sacc[nt][0] = __expf(sacc[nt][0] - mn0);
            sacc[nt][1] = __expf(sacc[nt][1] - mn0);
            sacc[nt][2] = __expf(sacc[nt][2] - mn1);
            sacc[nt][3] = __expf(sacc[nt][3] - mn1);
            rs0 += sacc[nt][0] + sacc[nt][1];
            rs1 += sacc[nt][2] + sacc[nt][3];
        }
        rs0 += __shfl_xor_sync(0xffffffffu, rs0, 1);
        rs0 += __shfl_xor_sync(0xffffffffu, rs0, 2);
        rs1 += __shfl_xor_sync(0xffffffffu, rs1, 1);
        rs1 += __shfl_xor_sync(0xffffffffu, rs1, 2);
        l0 = l0 * al0 + rs0; m0 = mn0;
        l1 = l1 * al1 + rs1; m1 = mn1;
        #pragma unroll
        for (int nt = 0; nt < 16; nt++) {
            oacc[nt][0] *= al0; oacc[nt][1] *= al0;
            oacc[nt][2] *= al1; oacc[nt][3] *= al1;
        }

        // ---- O += P V (P split hi/lo in regs, V hi/lo in smem) ----
        #pragma unroll
        for (int kk = 0; kk < 4; kk++) {
            uint32_t ah[4], alr[4];
            {
                const float* p0 = sacc[2 * kk];
                const float* p1 = sacc[2 * kk + 1];
                float h00 = __bfloat162float(__float2bfloat16(p0[0]));
                float h01 = __bfloat162float(__float2bfloat16(p0[1]));
                float h02 = __bfloat162float(__float2bfloat16(p0[2]));
                float h03 = __bfloat162float(__float2bfloat16(p0[3]));
                float h10 = __bfloat162float(__float2bfloat16(p1[0]));
                float h11 = __bfloat162float(__float2bfloat16(p1[1]));
                float h12 = __bfloat162float(__float2bfloat16(p1[2]));
                float h13 = __bfloat162float(__float2bfloat16(p1[3]));
                ah[0] = pack_bf2(p0[0], p0[1]);
                ah[1] = pack_bf2(p0[2], p0[3]);
                ah[2] = pack_bf2(p1[0], p1[1]);
                ah[3] = pack_bf2(p1[2], p1[3]);
                alr[0] = pack_bf2(p0[0] - h00, p0[1] - h01);
                alr[1] = pack_bf2(p0[2] - h02, p0[3] - h03);
                alr[2] = pack_bf2(p1[0] - h10, p1[1] - h11);
                alr[3] = pack_bf2(p1[2] - h12, p1[3] - h13);
            }
            #pragma unroll
            for (int half = 0; half < 2; half++) {
                uint32_t bv[8][2];
                #pragma unroll
                for (int g = 0; g < 4; g++) {
                    uint32_t r0, r1, r2, r3;
                    ldsm_x4(r0, r1, r2, r3,
                            sb + SM_VH + bVoff + (uint32_t)(half * 64 + g * 16) * 144 + kk * 32);
                    bv[2 * g][0] = r0; bv[2 * g][1] = r1;
                    bv[2 * g + 1][0] = r2; bv[2 * g + 1][1] = r3;
                }
                #pragma unroll
                for (int t = 0; t < 8; t++) {
                    mma_bf16(oacc[half * 8 + t], ah, bv[t]);
                    mma_bf16(oacc[half * 8 + t], alr, bv[t]);
                }
                #pragma unroll
                for (int g = 0; g < 4; g++) {
                    uint32_t r0, r1, r2, r3;
                    ldsm_x4(r0, r1, r2, r3,
                            sb + SM_VL + bVoff + (uint32_t)(half * 64 + g * 16) * 144 + kk * 32);
                    bv[2 * g][0] = r0; bv[2 * g][1] = r1;
                    bv[2 * g + 1][0] = r2; bv[2 * g + 1][1] = r3;
                }
                #pragma unroll
                for (int t = 0; t < 8; t++)
                    mma_bf16(oacc[half * 8 + t], ah, bv[t]);
            }
        }
    }

    // epilogue
    const float inv0 = 1.f / l0, inv1 = 1.f / l1;
    const int gr = lane >> 2, gc = (lane & 3) * 2;
    const int row0 = b * S_ + q0 + wr + gr;
    #pragma unroll
    for (int nt = 0; nt < 16; nt++) {
        const int col = h * DV + nt * 8 + gc;
        *(float2*)(out + (size_t)row0 * (NH_ * DV) + col) =
            make_float2(oacc[nt][0] * inv0, oacc[nt][1] * inv0);
        *(float2*)(out + (size_t)(row0 + 8) * (NH_ * DV) + col) =
            make_float2(oacc[nt][2] * inv1, oacc[nt][3] * inv1);
    }
}

// ---------------------------------------------------------------------------
// Launcher
// ---------------------------------------------------------------------------
static inline void run_conv3(const float* in, __nv_bfloat16* out, int R, int Rpad,
                             int Kin, int ldin, int mode)
{
    const int total = Rpad * (Kin / 4);
    conv3_kernel<<<(total + 255) / 256, 256>>>(in, out, R, Rpad, Kin, ldin, mode);
}

static inline void run_gemm(const __nv_bfloat16* A, const __nv_bfloat16* Bw, float* C,
                            int Npad, int N, int K3, int ldc)
{
    gemm_bf16_kernel<<<dim3(Npad / 128, BS / 128), 256>>>(A, Bw, C, N, K3, ldc);
}

extern "C" void kernel_launch(void* const* d_in, const int* in_sizes, int n_in,
                              void* d_out, int out_size)
{
    const float* hs    = (const float*)d_in[0];
    const float* wq_a  = (const float*)d_in[1];
    const float* qnw   = (const float*)d_in[2];
    const float* wq_b  = (const float*)d_in[3];
    const float* wkv_a = (const float*)d_in[4];
    const float* kvnw  = (const float*)d_in[5];
    const float* wkv_b = (const float*)d_in[6];
    const float* wo    = (const float*)d_in[7];
    float* out = (float*)d_out;

    void* p;
    cudaGetSymbolAddress(&p, g_qlora); float* qlora = (float*)p;
    cudaGetSymbolAddress(&p, g_q);     float* qbuf  = (float*)p;
    cudaGetSymbolAddress(&p, g_kv);    float* kvbuf = (float*)p;
    cudaGetSymbolAddress(&p, g_kvx);   float* kvx   = (float*)p;
    cudaGetSymbolAddress(&p, g_attn);  float* attn  = (float*)p;
    cudaGetSymbolAddress(&p, g_a3);    __nv_bfloat16* a3 = (__nv_bfloat16*)p;
    cudaGetSymbolAddress(&p, g_b3);    __nv_bfloat16* b3 = (__nv_bfloat16*)p;
    cudaGetSymbolAddress(&p, g_qh);    __nv_bfloat16* qh = (__nv_bfloat16*)p;
    cudaGetSymbolAddress(&p, g_ql2);   __nv_bfloat16* ql = (__nv_bfloat16*)p;
    cudaGetSymbolAddress(&p, g_kh);    __nv_bfloat16* kh = (__nv_bfloat16*)p;
    cudaGetSymbolAddress(&p, g_kl);    __nv_bfloat16* kl = (__nv_bfloat16*)p;
    cudaGetSymbolAddress(&p, g_vth);   __nv_bfloat16* vth = (__nv_bfloat16*)p;
    cudaGetSymbolAddress(&p, g_vtl);   __nv_bfloat16* vtl = (__nv_bfloat16*)p;

    cudaFuncSetAttribute(flash_mma_kernel, cudaFuncAttributeMaxDynamicSharedMemorySize,
                         FLASH_SMEM);

    freq_init_kernel<<<1, 32>>>();

    // 1) q_lora = hs @ wq_a^T        [4096, 1536]
    run_conv3(hs, a3, BS, BS, H_, H_, 0);
    run_conv3(wq_a, b3, QL, QL, H_, H_, 1);
    run_gemm(a3, b3, qlora, QL, QL, 3 * H_, QL);

    // 2) kv = hs @ wkv_a^T           [4096, 576] (Npad 640)
    run_conv3(wkv_a, b3, KVL + DR, 640, H_, H_, 1);
    run_gemm(a3, b3, kvbuf, 640, KVL + DR, 3 * H_, KVL + DR);

    // 3) norms + k rope
    rmsnorm_kernel<<<BS, 256>>>(qlora, qnw, QL, QL);
    rmsnorm_kernel<<<BS, 256>>>(kvbuf, kvnw, KVL, KVL + DR);
    rope_k_kernel<<<(BS * 32) / 256, 256>>>(kvbuf);

    // 4) q = q_lora @ wq_b^T         [4096, 3072]
    run_conv3(qlora, a3, BS, BS, QL, QL, 0);
    run_conv3(wq_b, b3, NH_ * DQK, NH_ * DQK, QL, QL, 1);
    run_gemm(a3, b3, qbuf, NH_ * DQK, NH_ * DQK, 3 * QL, NH_ * DQK);
    rope_q_kernel<<<(BS * NH_ * 32) / 256, 256>>>(qbuf);

    // 5) kv_x = kv_c @ wkv_b^T       [4096, 4096]
    run_conv3(kvbuf, a3, BS, BS, KVL, KVL + DR, 0);
    run_conv3(wkv_b, b3, NH_ * (DN + DV), NH_ * (DN + DV), KVL, KVL, 1);
    run_gemm(a3, b3, kvx, NH_ * (DN + DV), NH_ * (DN + DV), 3 * KVL, NH_ * (DN + DV));

    // 6) flash prep: Q/K hi-lo, V hi-lo transposed
    conv_hl_kernel<<<(BS * NH_ * DQK / 4 + 255) / 256, 256>>>(qbuf, qh, ql, BS * NH_ * DQK / 4);
    convk_kernel<<<(BS * NH_ * 48 + 255) / 256, 256>>>(kvx, kvbuf, kh, kl);
    convvt_kernel<<<dim3(S_ / 32, DV / 32, B_ * NH_), dim3(32, 8)>>>(kvx, vth, vtl);

    // 7) flash attention (HMMA) -> attn [4096, 2048]
    flash_mma_kernel<<<dim3(S_ / 128, NH_, B_), 256, FLASH_SMEM>>>(qh, ql, kh, kl, vth, vtl, attn);

    // 8) out = attn @ wo^T           [4096, 2048]
    run_conv3(attn, a3, BS, BS, NH_ * DV, NH_ * DV, 0);
    run_conv3(wo, b3, H_, H_, NH_ * DV, NH_ * DV, 1);
    run_gemm(a3, b3, out, H_, H_, 3 * NH_ * DV, H_);
}

// round 7
// speedup vs baseline: 3.3827x; 1.1202x over previous
#include <cuda_runtime.h>
#include <cuda_bf16.h>
#include <math.h>
#include <stdint.h>

// ---------------------------------------------------------------------------
// Problem constants (MLA prefill)
// ---------------------------------------------------------------------------
namespace {
constexpr int B_   = 2;
constexpr int S_   = 2048;
constexpr int H_   = 2048;
constexpr int NH_  = 16;
constexpr int QL   = 1536;
constexpr int KVL  = 512;
constexpr int DN   = 128;
constexpr int DR   = 64;
constexpr int DV   = 128;
constexpr int DQK  = 192;
constexpr int BS   = B_ * S_;
constexpr float SCALE = 0.07216878364870322f; // 1/sqrt(192)

// flash smem: Qh/Ql [128][pitch200], Kh/Kl [64][200], Vth/Vtl [128][72]
constexpr int SM_QH  = 0;
constexpr int SM_QL  = SM_QH + 128 * 400;
constexpr int SM_KH  = SM_QL + 128 * 400;
constexpr int SM_KL  = SM_KH + 64 * 400;
constexpr int SM_VH  = SM_KL + 64 * 400;
constexpr int SM_VL  = SM_VH + 128 * 144;
constexpr int FLASH_SMEM = SM_VL + 128 * 144; // 190,464 B
} // namespace

// ---------------------------------------------------------------------------
// Scratch (static device globals; no runtime allocation allowed)
// ---------------------------------------------------------------------------
__device__ float g_qlora[(size_t)BS * QL];
__device__ float g_q[(size_t)BS * NH_ * DQK];
__device__ float g_kv[(size_t)BS * (KVL + DR)];
__device__ float g_kvx[(size_t)BS * NH_ * (DN + DV)];
__device__ float g_attn[(size_t)BS * NH_ * DV];
__device__ __nv_bfloat16 g_a3[(size_t)4096 * 6144];  // activations: [hi | lo | hi]
__device__ __nv_bfloat16 g_b3[(size_t)3072 * 4608];  // weights:     [hi | hi | lo]
// flash operands (bf16 hi/lo)
__device__ __nv_bfloat16 g_qh[(size_t)BS * NH_ * DQK];
__device__ __nv_bfloat16 g_ql2[(size_t)BS * NH_ * DQK];
__device__ __nv_bfloat16 g_kh[(size_t)BS * NH_ * DQK];
__device__ __nv_bfloat16 g_kl[(size_t)BS * NH_ * DQK];
__device__ __nv_bfloat16 g_vth[(size_t)B_ * NH_ * DV * S_];  // [b][h][dv][s]
__device__ __nv_bfloat16 g_vtl[(size_t)B_ * NH_ * DV * S_];
__device__ float g_freq[32];

// ---------------------------------------------------------------------------
// Helpers
// ---------------------------------------------------------------------------
__device__ __forceinline__ uint32_t smem_u32(const void* p) {
    uint32_t a;
    asm("{ .reg .u64 t; cvta.to.shared.u64 t, %1; cvt.u32.u64 %0, t; }" : "=r"(a) : "l"(p));
    return a;
}
__device__ __forceinline__ void cp_async16(uint32_t dst, const void* src) {
    asm volatile("cp.async.cg.shared.global [%0], [%1], 16;" :: "r"(dst), "l"(src) : "memory");
}
#define CP_COMMIT() asm volatile("cp.async.commit_group;" ::: "memory")
#define CP_WAIT2()  asm volatile("cp.async.wait_group 2;" ::: "memory")
#define CP_WAIT1()  asm volatile("cp.async.wait_group 1;" ::: "memory")
#define CP_WAIT0()  asm volatile("cp.async.wait_group 0;" ::: "memory")

__device__ __forceinline__ void ldsm_x4(uint32_t& r0, uint32_t& r1, uint32_t& r2, uint32_t& r3,
                                        uint32_t addr) {
    asm volatile("ldmatrix.sync.aligned.m8n8.x4.shared.b16 {%0,%1,%2,%3}, [%4];"
                 : "=r"(r0), "=r"(r1), "=r"(r2), "=r"(r3) : "r"(addr));
}
__device__ __forceinline__ void mma_bf16(float* c, const uint32_t* a, const uint32_t* b) {
    asm volatile("mma.sync.aligned.m16n8k16.row.col.f32.bf16.bf16.f32 "
                 "{%0,%1,%2,%3}, {%4,%5,%6,%7}, {%8,%9}, {%0,%1,%2,%3};"
                 : "+f"(c[0]), "+f"(c[1]), "+f"(c[2]), "+f"(c[3])
                 : "r"(a[0]), "r"(a[1]), "r"(a[2]), "r"(a[3]), "r"(b[0]), "r"(b[1]));
}
__device__ __forceinline__ uint32_t swoff(int r, int c) {
    return (uint32_t)(r * 64 + ((c ^ ((r >> 1) & 3)) << 4));
}
__device__ __forceinline__ uint32_t pack_bf2(float x, float y) {
    __nv_bfloat162 t(__float2bfloat16(x), __float2bfloat16(y));
    return *(uint32_t*)&t;
}

// ---------------------------------------------------------------------------
// Split-3 conversion for GEMMs (proven in R4)
// ---------------------------------------------------------------------------
__global__ void conv3_kernel(const float* __restrict__ in, __nv_bfloat16* __restrict__ out,
                             int R, int Rpad, int Kin, int ldin, int mode)
{
    const int kq = Kin >> 2;
    const int idx = blockIdx.x * blockDim.x + threadIdx.x;
    if (idx >= Rpad * kq) return;
    const int row = idx / kq, cg = idx - row * kq;
    float4 v = make_float4(0.f, 0.f, 0.f, 0.f);
    if (row < R) v = *(const float4*)(in + (size_t)row * ldin + cg * 4);
    const float vv[4] = {v.x, v.y, v.z, v.w};
    __nv_bfloat16 hi[4], lo[4];
    #pragma unroll
    for (int i = 0; i < 4; i++) {
        hi[i] = __float2bfloat16(vv[i]);
        lo[i] = __float2bfloat16(vv[i] - __bfloat162float(hi[i]));
    }
    const int seg_lo = mode ? 2 : 1;
    const int seg_hi = mode ? 1 : 2;
    __nv_bfloat16* p = out + (size_t)row * (3 * Kin) + cg * 4;
    *(__nv_bfloat162*)(p + 0) = __nv_bfloat162(hi[0], hi[1]);
    *(__nv_bfloat162*)(p + 2) = __nv_bfloat162(hi[2], hi[3]);
    *(__nv_bfloat162*)(p + seg_lo * Kin + 0) = __nv_bfloat162(lo[0], lo[1]);
    *(__nv_bfloat162*)(p + seg_lo * Kin + 2) = __nv_bfloat162(lo[2], lo[3]);
    *(__nv_bfloat162*)(p + seg_hi * Kin + 0) = __nv_bfloat162(hi[0], hi[1]);
    *(__nv_bfloat162*)(p + seg_hi * Kin + 2) = __nv_bfloat162(hi[2], hi[3]);
}

// ---------------------------------------------------------------------------
// HMMA bf16 GEMM:  C[M,N](f32) = A3[M,K3] * B3[Npad,K3]^T
// CTA 128x64x32, 8 warps (4x2), warp tile 32x32, mma.sync m16n8k16,
// 4-stage cp.async pipeline, 2 CTAs/SM.
// ---------------------------------------------------------------------------
__global__ __launch_bounds__(256, 2)
void gemm_bf16_kernel(const __nv_bfloat16* __restrict__ A,
                      const __nv_bfloat16* __restrict__ Bw,
                      float* __restrict__ C, int N, int K3, int ldc)
{
    __shared__ __nv_bfloat16 smv[4][192 * 32]; // [stage][A(128x32) | B(64x32)]
    const int tid = threadIdx.x;
    const int warp = tid >> 5, lane = tid & 31;
    const int m0 = blockIdx.y * 128, n0 = blockIdx.x * 64;
    const int NC = K3 / 32;

    const uint32_t sbase = smem_u32(&smv[0][0]);
    constexpr uint32_t STG  = 192u * 32 * 2;  // bytes per stage
    constexpr uint32_t BOFF = 128u * 32 * 2;  // B tile offset within stage

    // loader: per thread 2 A chunks (rows lr0, lr0+64) + 1 B chunk (row lr0)
    const int lr0 = tid >> 2, lc0 = tid & 3;
    const uint32_t so0 = swoff(lr0, lc0);     // swizzle invariant under +64 rows
    const __nv_bfloat16* gA0 = A  + (size_t)(m0 + lr0) * K3 + lc0 * 8;
    const __nv_bfloat16* gB0 = Bw + (size_t)(n0 + lr0) * K3 + lc0 * 8;

    auto load_stage = [&](int kc, int s) {
        const uint32_t sb = sbase + s * STG;
        const size_t ko = (size_t)kc * 32;
        cp_async16(sb + so0,           gA0 + ko);
        cp_async16(sb + so0 + 64 * 64, gA0 + ko + (size_t)64 * K3);
        cp_async16(sb + BOFF + so0,    gB0 + ko);
    };

    // warp tile 32x32: 4 warps along M, 2 along N
    const int wm = (warp >> 1) * 32, wn = (warp & 1) * 32;
    const int rA = wm + (lane & 15), cA = lane >> 4;
    const int swzA = (rA >> 1) & 3;
    const int rB = wn + (lane & 7) + ((lane >> 4) << 3), cB = (lane >> 3) & 1;
    const int swzB = (rB >> 1) & 3;

    float acc[2][4][4];
    #pragma unroll
    for (int i = 0; i < 2; i++)
        #pragma unroll
        for (int j = 0; j < 4; j++)
            #pragma unroll
            for (int k = 0; k < 4; k++) acc[i][j][k] = 0.f;

    load_stage(0, 0); CP_COMMIT();
    load_stage(1, 1); CP_COMMIT();
    load_stage(2, 2); CP_COMMIT();
    CP_WAIT2();
    __syncthreads();

    for (int kc = 0; kc < NC; kc++) {
        if (kc + 3 < NC) load_stage(kc + 3, (kc + 3) & 3);
        CP_COMMIT();

        const uint32_t sb = sbase + (kc & 3) * STG;
        #pragma unroll
        for (int h = 0; h < 2; h++) {
            uint32_t a[2][4], b[4][2];
            #pragma unroll
            for (int i = 0; i < 2; i++)
                ldsm_x4(a[i][0], a[i][1], a[i][2], a[i][3],
                        sb + (uint32_t)((rA + 16 * i) * 64 + (((h * 2 + cA) ^ swzA) << 4)));
            #pragma unroll
            for (int j = 0; j < 2; j++) {
                uint32_t r0, r1, r2, r3;
                ldsm_x4(r0, r1, r2, r3,
                        sb + BOFF + (uint32_t)((rB + 16 * j) * 64 + (((h * 2 + cB) ^ swzB) << 4)));
                b[2 * j][0] = r0; b[2 * j][1] = r1;
                b[2 * j + 1][0] = r2; b[2 * j + 1][1] = r3;
            }
            #pragma unroll
            for (int i = 0; i < 2; i++)
                #pragma unroll
                for (int t = 0; t < 4; t++)
                    mma_bf16(acc[i][t], a[i], b[t]);
        }
        CP_WAIT2();
        __syncthreads();
    }

    const int gr = lane >> 2, gc = (lane & 3) * 2;
    #pragma unroll
    for (int i = 0; i < 2; i++) {
        const int row0 = m0 + wm + i * 16 + gr;
        #pragma unroll
        for (int t = 0; t < 4; t++) {
            const int col = n0 + wn + t * 8 + gc;
            if (col < N) {
                *(float2*)(C + (size_t)row0 * ldc + col) =
                    make_float2(acc[i][t][0], acc[i][t][1]);
                *(float2*)(C + (size_t)(row0 + 8) * ldc + col) =
                    make_float2(acc[i][t][2], acc[i][t][3]);
            }
        }
    }
}

// ---------------------------------------------------------------------------
// RMSNorm / RoPE
// ---------------------------------------------------------------------------
__global__ __launch_bounds__(256)
void rmsnorm_kernel(float* __restrict__ x, const float* __restrict__ w, int n, int ld)
{
    const int row = blockIdx.x;
    float* p = x + (size_t)row * ld;
    float ss = 0.f;
    for (int i = threadIdx.x; i < n; i += 256) { float v = p[i]; ss = fmaf(v, v, ss); }
    __shared__ float red[8];
    #pragma unroll
    for (int o = 16; o > 0; o >>= 1) ss += __shfl_xor_sync(0xffffffffu, ss, o);
    if ((threadIdx.x & 31) == 0) red[threadIdx.x >> 5] = ss;
    __syncthreads();
    __shared__ float s_inv;
    if (threadIdx.x == 0) {
        float t = 0.f;
        #pragma unroll
        for (int i = 0; i < 8; i++) t += red[i];
        s_inv = rsqrtf(t / (float)n + 1e-6f);
    }
    __syncthreads();
    const float inv = s_inv;
    for (int i = threadIdx.x; i < n; i += 256) p[i] = w[i] * p[i] * inv;
}

__global__ void freq_init_kernel()
{
    if (threadIdx.x < 32)
        g_freq[threadIdx.x] = (float)pow(10000.0, -(double)threadIdx.x / 32.0);
}

__device__ __forceinline__ void rope_pair(float* p, int pos, int i)
{
    const float f = (float)pos * g_freq[i];
    float sn, c;
    sincosf(f, &sn, &c);
    const float e = p[0], o = p[1];
    p[0] = e * c - o * sn;
    p[1] = e * sn + o * c;
}

__global__ void rope_q_kernel(float* __restrict__ q)
{
    const int idx = blockIdx.x * blockDim.x + threadIdx.x;
    const int i   = idx & 31;
    const int h   = (idx >> 5) & (NH_ - 1);
    const int row = idx >> 9;
    const int s   = row & (S_ - 1);
    rope_pair(q + (size_t)row * (NH_ * DQK) + h * DQK + DN + 2 * i, s, i);
}

__global__ void rope_k_kernel(float* __restrict__ kv)
{
    const int idx = blockIdx.x * blockDim.x + threadIdx.x;
    const int i   = idx & 31;
    const int row = idx >> 5;
    const int s   = row & (S_ - 1);
    rope_pair(kv + (size_t)row * (KVL + DR) + KVL + 2 * i, s, i);
}

// ---------------------------------------------------------------------------
// Flash prep conversions
// ---------------------------------------------------------------------------
__global__ void conv_hl_kernel(const float* __restrict__ in,
                               __nv_bfloat16* __restrict__ hi_o,
                               __nv_bfloat16* __restrict__ lo_o, int n4)
{
    const int idx = blockIdx.x * blockDim.x + threadIdx.x;
    if (idx >= n4) return;
    float4 v = *(const float4*)(in + (size_t)idx * 4);
    const float vv[4] = {v.x, v.y, v.z, v.w};
    __nv_bfloat16 hi[4], lo[4];
    #pragma unroll
    for (int i = 0; i < 4; i++) {
        hi[i] = __float2bfloat16(vv[i]);
        lo[i] = __float2bfloat16(vv[i] - __bfloat162float(hi[i]));
    }
    *(__nv_bfloat162*)(hi_o + (size_t)idx * 4 + 0) = __nv_bfloat162(hi[0], hi[1]);
    *(__nv_bfloat162*)(hi_o + (size_t)idx * 4 + 2) = __nv_bfloat162(hi[2], hi[3]);
    *(__nv_bfloat162*)(lo_o + (size_t)idx * 4 + 0) = __nv_bfloat162(lo[0], lo[1]);
    *(__nv_bfloat162*)(lo_o + (size_t)idx * 4 + 2) = __nv_bfloat162(lo[2], lo[3]);
}

// K assembly: [row][h][192] = kvx nope (per-head) | g_kv pe (shared) -> hi/lo
__global__ void convk_kernel(const float* __restrict__ kvx, const float* __restrict__ kv,
                             __nv_bfloat16* __restrict__ kh, __nv_bfloat16* __restrict__ kl)
{
    const int idx = blockIdx.x * blockDim.x + threadIdx.x; // (row, h, dg) dg in [0,48)
    if (idx >= BS * NH_ * 48) return;
    const int dg  = idx % 48;
    const int h   = (idx / 48) & (NH_ - 1);
    const int row = idx / (48 * NH_);
    float4 v;
    if (dg < 32) v = *(const float4*)(kvx + (size_t)row * (NH_ * 256) + h * 256 + dg * 4);
    else         v = *(const float4*)(kv + (size_t)row * (KVL + DR) + KVL + (dg - 32) * 4);
    const float vv[4] = {v.x, v.y, v.z, v.w};
    __nv_bfloat16 hi[4], lo[4];
    #pragma unroll
    for (int i = 0; i < 4; i++) {
        hi[i] = __float2bfloat16(vv[i]);
        lo[i] = __float2bfloat16(vv[i] - __bfloat162float(hi[i]));
    }
    const size_t o = ((size_t)row * NH_ + h) * 192 + dg * 4;
    *(__nv_bfloat162*)(kh + o + 0) = __nv_bfloat162(hi[0], hi[1]);
    *(__nv_bfloat162*)(kh + o + 2) = __nv_bfloat162(hi[2], hi[3]);
    *(__nv_bfloat162*)(kl + o + 0) = __nv_bfloat162(lo[0], lo[1]);
    *(__nv_bfloat162*)(kl + o + 2) = __nv_bfloat162(lo[2], lo[3]);
}

// V transpose: kvx[.,h,128+dv] (row=b*S+s) -> vt[b][h][dv][s], hi/lo
__global__ void convvt_kernel(const float* __restrict__ kvx,
                              __nv_bfloat16* __restrict__ vth, __nv_bfloat16* __restrict__ vtl)
{
    __shared__ float tile[32][33];
    const int bh = blockIdx.z;               // b*NH + h
    const int b = bh >> 4, h = bh & 15;
    const int s0 = blockIdx.x * 32, dv0 = blockIdx.y * 32;
    const int tx = threadIdx.x, ty = threadIdx.y;
    #pragma unroll
    for (int j = 0; j < 4; j++) {
        const int s = s0 + ty + 8 * j;
        tile[ty + 8 * j][tx] =
            kvx[(size_t)(b * S_ + s) * (NH_ * 256) + h * 256 + DN + dv0 + tx];
    }
    __syncthreads();
    #pragma unroll
    for (int j = 0; j < 4; j++) {
        const int dv = dv0 + ty + 8 * j;
        const float v = tile[tx][ty + 8 * j];
        const __nv_bfloat16 hi = __float2bfloat16(v);
        const __nv_bfloat16 lo = __float2bfloat16(v - __bfloat162float(hi));
        const size_t o = ((size_t)bh * DV + dv) * S_ + s0 + tx;
        vth[o] = hi; vtl[o] = lo;
    }
}

// ---------------------------------------------------------------------------
// Flash attention on HMMA (bf16 split-3 both phases)
// CTA: 128 q rows x (head, batch); 8 warps x 16 rows; key tiles of 64.
// V loads overlap QK compute via split commit groups.
// ---------------------------------------------------------------------------
__global__ __launch_bounds__(256, 1)
void flash_mma_kernel(const __nv_bfloat16* __restrict__ qh, const __nv_bfloat16* __restrict__ ql,
                      const __nv_bfloat16* __restrict__ kh, const __nv_bfloat16* __restrict__ kl,
                      const __nv_bfloat16* __restrict__ vth, const __nv_bfloat16* __restrict__ vtl,
                      float* __restrict__ out)
{
    extern __shared__ __align__(128) char sm[];
    const uint32_t sb = smem_u32(sm);
    const int tid = threadIdx.x, warp = tid >> 5, lane = tid & 31;
    const int h = blockIdx.y, b = blockIdx.z;
    const int q0 = blockIdx.x * 128;
    const int wr = warp * 16;

    // Q tiles -> smem (hi + lo), pitch 400 B
    for (int u = tid; u < 128 * 24; u += 256) {
        const int r = u / 24, c = u % 24;
        const size_t off = ((size_t)(b * S_ + q0 + r) * NH_ + h) * 192 + c * 8;
        cp_async16(sb + SM_QH + r * 400 + c * 16, qh + off);
        cp_async16(sb + SM_QL + r * 400 + c * 16, ql + off);
    }

    float oacc[16][4];
    #pragma unroll
    for (int i = 0; i < 16; i++)
        #pragma unroll
        for (int j = 0; j < 4; j++) oacc[i][j] = 0.f;
    float m0 = -1e30f, m1 = -1e30f, l0 = 0.f, l1 = 0.f;

    // ldmatrix lane addressing (same scheme as proven gemm)
    const uint32_t aQoff = (uint32_t)(wr + (lane & 15)) * 400 + ((lane >> 4) << 4);
    const int rB8  = (lane & 7) + ((lane >> 4) << 3);
    const uint32_t bKoff = (uint32_t)rB8 * 400 + (((lane >> 3) & 1) << 4);
    const uint32_t bVoff = (uint32_t)rB8 * 144 + (((lane >> 3) & 1) << 4);

    for (int kt = 0; kt < S_; kt += 64) {
        __syncthreads(); // previous tile fully consumed
        // K tile (hi+lo) -> group 1
        for (int u = tid; u < 64 * 24; u += 256) {
            const int r = u / 24, c = u % 24;
            const size_t off = ((size_t)(b * S_ + kt + r) * NH_ + h) * 192 + c * 8;
            cp_async16(sb + SM_KH + r * 400 + c * 16, kh + off);
            cp_async16(sb + SM_KL + r * 400 + c * 16, kl + off);
        }
        CP_COMMIT();
        // Vt tile (hi+lo) -> group 2 (overlaps with QK compute)
        for (int u = tid; u < 128 * 8; u += 256) {
            const int dv = u / 8, ck = u % 8;
            const size_t off = ((size_t)(b * NH_ + h) * DV + dv) * S_ + kt + ck * 8;
            cp_async16(sb + SM_VH + dv * 144 + ck * 16, vth + off);
            cp_async16(sb + SM_VL + dv * 144 + ck * 16, vtl + off);
        }
        CP_COMMIT();
        CP_WAIT1();   // K (and Q on first iter) ready; V still in flight
        __syncthreads();

        // ---- S = Q K^T (3 segments over d=192) ----
        float sacc[8][4];
        #pragma unroll
        for (int i = 0; i < 8; i++)
            #pragma unroll
            for (int j = 0; j < 4; j++) sacc[i][j] = 0.f;

        #pragma unroll
        for (int seg = 0; seg < 3; seg++) {
            const uint32_t qb = sb + (seg == 1 ? SM_QL : SM_QH);
            const uint32_t kb = sb + (seg == 2 ? SM_KL : SM_KH);
            #pragma unroll
            for (int ks = 0; ks < 12; ks++) {
                uint32_t a[4];
                ldsm_x4(a[0], a[1], a[2], a[3], qb + aQoff + ks * 32);
                #pragma unroll
                for (int g = 0; g < 4; g++) {
                    uint32_t r0, r1, r2, r3;
                    ldsm_x4(r0, r1, r2, r3, kb + bKoff + (uint32_t)g * 16 * 400 + ks * 32);
                    uint32_t b0[2] = {r0, r1}, b1[2] = {r2, r3};
                    mma_bf16(sacc[2 * g], a, b0);
                    mma_bf16(sacc[2 * g + 1], a, b1);
                }
            }
        }

        // ---- online softmax (rows gr and gr+8) ----
        float mx0 = -1e30f, mx1 = -1e30f;
        #pragma unroll
        for (int nt = 0; nt < 8; nt++) {
            #pragma unroll
            for (int j = 0; j < 4; j++) sacc[nt][j] *= SCALE;
            mx0 = fmaxf(mx0, fmaxf(sacc[nt][0], sacc[nt][1]));
            mx1 = fmaxf(mx1, fmaxf(sacc[nt][2], sacc[nt][3]));
        }
        mx0 = fmaxf(mx0, __shfl_xor_sync(0xffffffffu, mx0, 1));
        mx0 = fmaxf(mx0, __shfl_xor_sync(0xffffffffu, mx0, 2));
        mx1 = fmaxf(mx1, __shfl_xor_sync(0xffffffffu, mx1, 1));
        mx1 = fmaxf(mx1, __shfl_xor_sync(0xffffffffu, mx1, 2));
        const float mn0 = fmaxf(m0, mx0), mn1 = fmaxf(m1, mx1);
        const float al0 = __expf(m0 - mn0), al1 = __expf(m1 - mn1);
        float rs0 = 0.f, rs1 = 0.f;
        #pragma unroll
        for (int nt = 0; nt < 8; nt++) {
            sacc[nt][0] = __expf(sacc[nt][0] - mn0);
            sacc[nt][1] = __expf(sacc[nt][1] - mn0);
            sacc[nt][2] = __expf(sacc[nt][2] - mn1);
            sacc[nt][3] = __expf(sacc[nt][3] - mn1);
            rs0 += sacc[nt][0] + sacc[nt][1];
            rs1 += sacc[nt][2] + sacc[nt][3];
        }
        rs0 += __shfl_xor_sync(0xffffffffu, rs0, 1);
        rs0 += __shfl_xor_sync(0xffffffffu, rs0, 2);
        rs1 += __shfl_xor_sync(0xffffffffu, rs1, 1);
        rs1 += __shfl_xor_sync(0xffffffffu, rs1, 2);
        l0 = l0 * al0 + rs0; m0 = mn0;
        l1 = l1 * al1 + rs1; m1 = mn1;
        #pragma unroll
        for (int nt = 0; nt < 16; nt++) {
            oacc[nt][0] *= al0; oacc[nt][1] *= al0;
            oacc[nt][2] *= al1; oacc[nt][3] *= al1;
        }

        CP_WAIT0();   // V arrived
        __syncthreads();

        // ---- O += P V (P split hi/lo in regs, V hi/lo in smem) ----
        #pragma unroll
        for (int kk = 0; kk < 4; kk++) {
            uint32_t ah[4], alr[4];
            {
                const float* p0 = sacc[2 * kk];
                const float* p1 = sacc[2 * kk + 1];
                float h00 = __bfloat162float(__float2bfloat16(p0[0]));
                float h01 = __bfloat162float(__float2bfloat16(p0[1]));
                float h02 = __bfloat162float(__float2bfloat16(p0[2]));
                float h03 = __bfloat162float(__float2bfloat16(p0[3]));
                float h10 = __bfloat162float(__float2bfloat16(p1[0]));
                float h11 = __bfloat162float(__float2bfloat16(p1[1]));
                float h12 = __bfloat162float(__float2bfloat16(p1[2]));
                float h13 = __bfloat162float(__float2bfloat16(p1[3]));
                ah[0] = pack_bf2(p0[0], p0[1]);
                ah[1] = pack_bf2(p0[2], p0[3]);
                ah[2] = pack_bf2(p1[0], p1[1]);
                ah[3] = pack_bf2(p1[2], p1[3]);
                alr[0] = pack_bf2(p0[0] - h00, p0[1] - h01);
                alr[1] = pack_bf2(p0[2] - h02, p0[3] - h03);
                alr[2] = pack_bf2(p1[0] - h10, p1[1] - h11);
                alr[3] = pack_bf2(p1[2] - h12, p1[3] - h13);
            }
            #pragma unroll
            for (int half = 0; half < 2; half++) {
                uint32_t bv[8][2];
                #pragma unroll
                for (int g = 0; g < 4; g++) {
                    uint32_t r0, r1, r2, r3;
                    ldsm_x4(r0, r1, r2, r3,
                            sb + SM_VH + bVoff + (uint32_t)(half * 64 + g * 16) * 144 + kk * 32);
                    bv[2 * g][0] = r0; bv[2 * g][1] = r1;
                    bv[2 * g + 1][0] = r2; bv[2 * g + 1][1] = r3;
                }
                #pragma unroll
                for (int t = 0; t < 8; t++) {
                    mma_bf16(oacc[half * 8 + t], ah, bv[t]);
                    mma_bf16(oacc[half * 8 + t], alr, bv[t]);
                }
                #pragma unroll
                for (int g = 0; g < 4; g++) {
                    uint32_t r0, r1, r2, r3;
                    ldsm_x4(r0, r1, r2, r3,
                            sb + SM_VL + bVoff + (uint32_t)(half * 64 + g * 16) * 144 + kk * 32);
                    bv[2 * g][0] = r0; bv[2 * g][1] = r1;
                    bv[2 * g + 1][0] = r2; bv[2 * g + 1][1] = r3;
                }
                #pragma unroll
                for (int t = 0; t < 8; t++)
                    mma_bf16(oacc[half * 8 + t], ah, bv[t]);
            }
        }
    }

    // epilogue
    const float inv0 = 1.f / l0, inv1 = 1.f / l1;
    const int gr = lane >> 2, gc = (lane & 3) * 2;
    const int row0 = b * S_ + q0 + wr + gr;
    #pragma unroll
    for (int nt = 0; nt < 16; nt++) {
        const int col = h * DV + nt * 8 + gc;
        *(float2*)(out + (size_t)row0 * (NH_ * DV) + col) =
            make_float2(oacc[nt][0] * inv0, oacc[nt][1] * inv0);
        *(float2*)(out + (size_t)(row0 + 8) * (NH_ * DV) + col) =
            make_float2(oacc[nt][2] * inv1, oacc[nt][3] * inv1);
    }
}

// ---------------------------------------------------------------------------
// Launcher
// ---------------------------------------------------------------------------
static inline void run_conv3(const float* in, __nv_bfloat16* out, int R, int Rpad,
                             int Kin, int ldin, int mode)
{
    const int total = Rpad * (Kin / 4);
    conv3_kernel<<<(total + 255) / 256, 256>>>(in, out, R, Rpad, Kin, ldin, mode);
}

static inline void run_gemm(const __nv_bfloat16* A, const __nv_bfloat16* Bw, float* C,
                            int Npad, int N, int K3, int ldc)
{
    gemm_bf16_kernel<<<dim3(Npad / 64, BS / 128), 256>>>(A, Bw, C, N, K3, ldc);
}

extern "C" void kernel_launch(void* const* d_in, const int* in_sizes, int n_in,
                              void* d_out, int out_size)
{
    const float* hs    = (const float*)d_in[0];
    const float* wq_a  = (const float*)d_in[1];
    const float* qnw   = (const float*)d_in[2];
    const float* wq_b  = (const float*)d_in[3];
    const float* wkv_a = (const float*)d_in[4];
    const float* kvnw  = (const float*)d_in[5];
    const float* wkv_b = (const float*)d_in[6];
    const float* wo    = (const float*)d_in[7];
    float* out = (float*)d_out;

    void* p;
    cudaGetSymbolAddress(&p, g_qlora); float* qlora = (float*)p;
    cudaGetSymbolAddress(&p, g_q);     float* qbuf  = (float*)p;
    cudaGetSymbolAddress(&p, g_kv);    float* kvbuf = (float*)p;
    cudaGetSymbolAddress(&p, g_kvx);   float* kvx   = (float*)p;
    cudaGetSymbolAddress(&p, g_attn);  float* attn  = (float*)p;
    cudaGetSymbolAddress(&p, g_a3);    __nv_bfloat16* a3 = (__nv_bfloat16*)p;
    cudaGetSymbolAddress(&p, g_b3);    __nv_bfloat16* b3 = (__nv_bfloat16*)p;
    cudaGetSymbolAddress(&p, g_qh);    __nv_bfloat16* qh = (__nv_bfloat16*)p;
    cudaGetSymbolAddress(&p, g_ql2);   __nv_bfloat16* ql = (__nv_bfloat16*)p;
    cudaGetSymbolAddress(&p, g_kh);    __nv_bfloat16* kh = (__nv_bfloat16*)p;
    cudaGetSymbolAddress(&p, g_kl);    __nv_bfloat16* kl = (__nv_bfloat16*)p;
    cudaGetSymbolAddress(&p, g_vth);   __nv_bfloat16* vth = (__nv_bfloat16*)p;
    cudaGetSymbolAddress(&p, g_vtl);   __nv_bfloat16* vtl = (__nv_bfloat16*)p;

    cudaFuncSetAttribute(flash_mma_kernel, cudaFuncAttributeMaxDynamicSharedMemorySize,
                         FLASH_SMEM);

    freq_init_kernel<<<1, 32>>>();

    // 1) q_lora = hs @ wq_a^T        [4096, 1536]
    run_conv3(hs, a3, BS, BS, H_, H_, 0);
    run_conv3(wq_a, b3, QL, QL, H_, H_, 1);
    run_gemm(a3, b3, qlora, QL, QL, 3 * H_, QL);

    // 2) kv = hs @ wkv_a^T           [4096, 576] (Npad 640)
    run_conv3(wkv_a, b3, KVL + DR, 640, H_, H_, 1);
    run_gemm(a3, b3, kvbuf, 640, KVL + DR, 3 * H_, KVL + DR);

    // 3) norms + k rope
    rmsnorm_kernel<<<BS, 256>>>(qlora, qnw, QL, QL);
    rmsnorm_kernel<<<BS, 256>>>(kvbuf, kvnw, KVL, KVL + DR);
    rope_k_kernel<<<(BS * 32) / 256, 256>>>(kvbuf);

    // 4) q = q_lora @ wq_b^T         [4096, 3072]
    run_conv3(qlora, a3, BS, BS, QL, QL, 0);
    run_conv3(wq_b, b3, NH_ * DQK, NH_ * DQK, QL, QL, 1);
    run_gemm(a3, b3, qbuf, NH_ * DQK, NH_ * DQK, 3 * QL, NH_ * DQK);
    rope_q_kernel<<<(BS * NH_ * 32) / 256, 256>>>(qbuf);

    // 5) kv_x = kv_c @ wkv_b^T       [4096, 4096]
    run_conv3(kvbuf, a3, BS, BS, KVL, KVL + DR, 0);
    run_conv3(wkv_b, b3, NH_ * (DN + DV), NH_ * (DN + DV), KVL, KVL, 1);
    run_gemm(a3, b3, kvx, NH_ * (DN + DV), NH_ * (DN + DV), 3 * KVL, NH_ * (DN + DV));

    // 6) flash prep: Q/K hi-lo, V hi-lo transposed
    conv_hl_kernel<<<(BS * NH_ * DQK / 4 + 255) / 256, 256>>>(qbuf, qh, ql, BS * NH_ * DQK / 4);
    convk_kernel<<<(BS * NH_ * 48 + 255) / 256, 256>>>(kvx, kvbuf, kh, kl);
    convvt_kernel<<<dim3(S_ / 32, DV / 32, B_ * NH_), dim3(32, 8)>>>(kvx, vth, vtl);

    // 7) flash attention (HMMA) -> attn [4096, 2048]
    flash_mma_kernel<<<dim3(S_ / 128, NH_, B_), 256, FLASH_SMEM>>>(qh, ql, kh, kl, vth, vtl, attn);

    // 8) out = attn @ wo^T           [4096, 2048]
    run_conv3(attn, a3, BS, BS, NH_ * DV, NH_ * DV, 0);
    run_conv3(wo, b3, H_, H_, NH_ * DV, NH_ * DV, 1);
    run_gemm(a3, b3, out, H_, H_, 3 * NH_ * DV, H_);
}

// round 8
// speedup vs baseline: 3.5666x; 1.0544x over previous
#include <cuda_runtime.h>
#include <cuda_bf16.h>
#include <math.h>
#include <stdint.h>

// ---------------------------------------------------------------------------
// Problem constants (MLA prefill)
// ---------------------------------------------------------------------------
namespace {
constexpr int B_   = 2;
constexpr int S_   = 2048;
constexpr int H_   = 2048;
constexpr int NH_  = 16;
constexpr int QL   = 1536;
constexpr int KVL  = 512;
constexpr int DN   = 128;
constexpr int DR   = 64;
constexpr int DV   = 128;
constexpr int DQK  = 192;
constexpr int BS   = B_ * S_;
constexpr float SCALE = 0.07216878364870322f; // 1/sqrt(192)

// flash smem: Qh/Ql [128][pitch200], Kh/Kl [64][200], Vth/Vtl [128][72]
constexpr int SM_QH  = 0;
constexpr int SM_QL  = SM_QH + 128 * 400;
constexpr int SM_KH  = SM_QL + 128 * 400;
constexpr int SM_KL  = SM_KH + 64 * 400;
constexpr int SM_VH  = SM_KL + 64 * 400;
constexpr int SM_VL  = SM_VH + 128 * 144;
constexpr int FLASH_SMEM = SM_VL + 128 * 144; // 190,464 B
} // namespace

// ---------------------------------------------------------------------------
// Scratch (static device globals; no runtime allocation allowed)
// ---------------------------------------------------------------------------
__device__ float g_qlora[(size_t)BS * QL];
__device__ float g_q[(size_t)BS * NH_ * DQK];
__device__ float g_kv[(size_t)BS * (KVL + DR)];
__device__ float g_kvx[(size_t)BS * NH_ * (DN + DV)];
__device__ float g_attn[(size_t)BS * NH_ * DV];
__device__ __nv_bfloat16 g_a3[(size_t)4096 * 6144];  // activations: [hi | lo | hi]
__device__ __nv_bfloat16 g_b3[(size_t)3072 * 4608];  // weights:     [hi | hi | lo]
// flash operands (bf16 hi/lo)
__device__ __nv_bfloat16 g_qh[(size_t)BS * NH_ * DQK];
__device__ __nv_bfloat16 g_ql2[(size_t)BS * NH_ * DQK];
__device__ __nv_bfloat16 g_kh[(size_t)BS * NH_ * DQK];
__device__ __nv_bfloat16 g_kl[(size_t)BS * NH_ * DQK];
__device__ __nv_bfloat16 g_vth[(size_t)B_ * NH_ * DV * S_];  // [b][h][dv][s]
__device__ __nv_bfloat16 g_vtl[(size_t)B_ * NH_ * DV * S_];
__device__ float g_freq[32];

// ---------------------------------------------------------------------------
// Helpers
// ---------------------------------------------------------------------------
__device__ __forceinline__ uint32_t smem_u32(const void* p) {
    uint32_t a;
    asm("{ .reg .u64 t; cvta.to.shared.u64 t, %1; cvt.u32.u64 %0, t; }" : "=r"(a) : "l"(p));
    return a;
}
__device__ __forceinline__ void cp_async16(uint32_t dst, const void* src) {
    asm volatile("cp.async.cg.shared.global [%0], [%1], 16;" :: "r"(dst), "l"(src) : "memory");
}
#define CP_COMMIT() asm volatile("cp.async.commit_group;" ::: "memory")
#define CP_WAIT2()  asm volatile("cp.async.wait_group 2;" ::: "memory")
#define CP_WAIT1()  asm volatile("cp.async.wait_group 1;" ::: "memory")
#define CP_WAIT0()  asm volatile("cp.async.wait_group 0;" ::: "memory")

__device__ __forceinline__ void ldsm_x4(uint32_t& r0, uint32_t& r1, uint32_t& r2, uint32_t& r3,
                                        uint32_t addr) {
    asm volatile("ldmatrix.sync.aligned.m8n8.x4.shared.b16 {%0,%1,%2,%3}, [%4];"
                 : "=r"(r0), "=r"(r1), "=r"(r2), "=r"(r3) : "r"(addr));
}
__device__ __forceinline__ void mma_bf16(float* c, const uint32_t* a, const uint32_t* b) {
    asm volatile("mma.sync.aligned.m16n8k16.row.col.f32.bf16.bf16.f32 "
                 "{%0,%1,%2,%3}, {%4,%5,%6,%7}, {%8,%9}, {%0,%1,%2,%3};"
                 : "+f"(c[0]), "+f"(c[1]), "+f"(c[2]), "+f"(c[3])
                 : "r"(a[0]), "r"(a[1]), "r"(a[2]), "r"(a[3]), "r"(b[0]), "r"(b[1]));
}
__device__ __forceinline__ uint32_t swoff(int r, int c) {
    return (uint32_t)(r * 64 + ((c ^ ((r >> 1) & 3)) << 4));
}
__device__ __forceinline__ uint32_t pack_bf2(float x, float y) {
    __nv_bfloat162 t(__float2bfloat16(x), __float2bfloat16(y));
    return *(uint32_t*)&t;
}

// ---------------------------------------------------------------------------
// Split-3 conversion for GEMMs (proven in R4)
// ---------------------------------------------------------------------------
__global__ void conv3_kernel(const float* __restrict__ in, __nv_bfloat16* __restrict__ out,
                             int R, int Rpad, int Kin, int ldin, int mode)
{
    const int kq = Kin >> 2;
    const int idx = blockIdx.x * blockDim.x + threadIdx.x;
    if (idx >= Rpad * kq) return;
    const int row = idx / kq, cg = idx - row * kq;
    float4 v = make_float4(0.f, 0.f, 0.f, 0.f);
    if (row < R) v = *(const float4*)(in + (size_t)row * ldin + cg * 4);
    const float vv[4] = {v.x, v.y, v.z, v.w};
    __nv_bfloat16 hi[4], lo[4];
    #pragma unroll
    for (int i = 0; i < 4; i++) {
        hi[i] = __float2bfloat16(vv[i]);
        lo[i] = __float2bfloat16(vv[i] - __bfloat162float(hi[i]));
    }
    const int seg_lo = mode ? 2 : 1;
    const int seg_hi = mode ? 1 : 2;
    __nv_bfloat16* p = out + (size_t)row * (3 * Kin) + cg * 4;
    *(__nv_bfloat162*)(p + 0) = __nv_bfloat162(hi[0], hi[1]);
    *(__nv_bfloat162*)(p + 2) = __nv_bfloat162(hi[2], hi[3]);
    *(__nv_bfloat162*)(p + seg_lo * Kin + 0) = __nv_bfloat162(lo[0], lo[1]);
    *(__nv_bfloat162*)(p + seg_lo * Kin + 2) = __nv_bfloat162(lo[2], lo[3]);
    *(__nv_bfloat162*)(p + seg_hi * Kin + 0) = __nv_bfloat162(hi[0], hi[1]);
    *(__nv_bfloat162*)(p + seg_hi * Kin + 2) = __nv_bfloat162(hi[2], hi[3]);
}

// ---------------------------------------------------------------------------
// HMMA bf16 GEMM:  C[M,N](f32) = A3[M,K3] * B3[Npad,K3]^T
// CTA 128x64x32, 4 warps (2x2), warp tile 64x32 (R4-proven fragment math),
// 4-stage cp.async pipeline, 4 CTAs/SM.
// ---------------------------------------------------------------------------
__global__ __launch_bounds__(128, 4)
void gemm_bf16_kernel(const __nv_bfloat16* __restrict__ A,
                      const __nv_bfloat16* __restrict__ Bw,
                      float* __restrict__ C, int N, int K3, int ldc)
{
    __shared__ __nv_bfloat16 smv[4][192 * 32]; // [stage][A(128x32) | B(64x32)] = 48 KB
    const int tid = threadIdx.x;
    const int warp = tid >> 5, lane = tid & 31;
    const int m0 = blockIdx.y * 128, n0 = blockIdx.x * 64;
    const int NC = K3 / 32;

    const uint32_t sbase = smem_u32(&smv[0][0]);
    constexpr uint32_t STG  = 192u * 32 * 2;  // 12288 B per stage
    constexpr uint32_t BOFF = 128u * 32 * 2;  // B tile offset within stage

    // loader (128 threads): rows lr0, +32, +64, +96 for A; lr0, +32 for B
    const int lr0 = tid >> 2, lc0 = tid & 3;             // lr0 in [0,32)
    const uint32_t so0 = swoff(lr0, lc0);                // swizzle invariant under +32 rows
    const __nv_bfloat16* gA0 = A  + (size_t)(m0 + lr0) * K3 + lc0 * 8;
    const __nv_bfloat16* gB0 = Bw + (size_t)(n0 + lr0) * K3 + lc0 * 8;

    auto load_stage = [&](int kc, int s) {
        const uint32_t sb = sbase + s * STG;
        const size_t ko = (size_t)kc * 32;
        #pragma unroll
        for (int r = 0; r < 4; r++)
            cp_async16(sb + so0 + r * 32 * 64, gA0 + ko + (size_t)(r * 32) * K3);
        #pragma unroll
        for (int r = 0; r < 2; r++)
            cp_async16(sb + BOFF + so0 + r * 32 * 64, gB0 + ko + (size_t)(r * 32) * K3);
    };

    // 2x2 warp grid, warp tile 64x32 (fragment math identical to R4)
    const int wm = (warp >> 1) * 64, wn = (warp & 1) * 32;
    const int rA = wm + (lane & 15), cA = lane >> 4;
    const int swzA = (rA >> 1) & 3;
    const int rB = wn + (lane & 7) + ((lane >> 4) << 3), cB = (lane >> 3) & 1;
    const int swzB = (rB >> 1) & 3;

    float acc[4][4][4];
    #pragma unroll
    for (int i = 0; i < 4; i++)
        #pragma unroll
        for (int j = 0; j < 4; j++)
            #pragma unroll
            for (int k = 0; k < 4; k++) acc[i][j][k] = 0.f;

    load_stage(0, 0); CP_COMMIT();
    load_stage(1, 1); CP_COMMIT();
    load_stage(2, 2); CP_COMMIT();
    CP_WAIT2();
    __syncthreads();

    for (int kc = 0; kc < NC; kc++) {
        if (kc + 3 < NC) load_stage(kc + 3, (kc + 3) & 3);
        CP_COMMIT();

        const uint32_t sb = sbase + (kc & 3) * STG;
        #pragma unroll
        for (int h = 0; h < 2; h++) {
            uint32_t a[4][4], b[4][2];
            #pragma unroll
            for (int i = 0; i < 4; i++)
                ldsm_x4(a[i][0], a[i][1], a[i][2], a[i][3],
                        sb + (uint32_t)((rA + 16 * i) * 64 + (((h * 2 + cA) ^ swzA) << 4)));
            #pragma unroll
            for (int j = 0; j < 2; j++) {
                uint32_t r0, r1, r2, r3;
                ldsm_x4(r0, r1, r2, r3,
                        sb + BOFF + (uint32_t)((rB + 16 * j) * 64 + (((h * 2 + cB) ^ swzB) << 4)));
                b[2 * j][0] = r0; b[2 * j][1] = r1;
                b[2 * j + 1][0] = r2; b[2 * j + 1][1] = r3;
            }
            #pragma unroll
            for (int i = 0; i < 4; i++)
                #pragma unroll
                for (int t = 0; t < 4; t++)
                    mma_bf16(acc[i][t], a[i], b[t]);
        }
        CP_WAIT2();
        __syncthreads();
    }

    const int gr = lane >> 2, gc = (lane & 3) * 2;
    #pragma unroll
    for (int i = 0; i < 4; i++) {
        const int row0 = m0 + wm + i * 16 + gr;
        #pragma unroll
        for (int t = 0; t < 4; t++) {
            const int col = n0 + wn + t * 8 + gc;
            if (col < N) {
                *(float2*)(C + (size_t)row0 * ldc + col) =
                    make_float2(acc[i][t][0], acc[i][t][1]);
                *(float2*)(C + (size_t)(row0 + 8) * ldc + col) =
                    make_float2(acc[i][t][2], acc[i][t][3]);
            }
        }
    }
}

// ---------------------------------------------------------------------------
// RMSNorm / RoPE
// ---------------------------------------------------------------------------
__global__ __launch_bounds__(256)
void rmsnorm_kernel(float* __restrict__ x, const float* __restrict__ w, int n, int ld)
{
    const int row = blockIdx.x;
    float* p = x + (size_t)row * ld;
    float ss = 0.f;
    for (int i = threadIdx.x; i < n; i += 256) { float v = p[i]; ss = fmaf(v, v, ss); }
    __shared__ float red[8];
    #pragma unroll
    for (int o = 16; o > 0; o >>= 1) ss += __shfl_xor_sync(0xffffffffu, ss, o);
    if ((threadIdx.x & 31) == 0) red[threadIdx.x >> 5] = ss;
    __syncthreads();
    __shared__ float s_inv;
    if (threadIdx.x == 0) {
        float t = 0.f;
        #pragma unroll
        for (int i = 0; i < 8; i++) t += red[i];
        s_inv = rsqrtf(t / (float)n + 1e-6f);
    }
    __syncthreads();
    const float inv = s_inv;
    for (int i = threadIdx.x; i < n; i += 256) p[i] = w[i] * p[i] * inv;
}

__global__ void freq_init_kernel()
{
    if (threadIdx.x < 32)
        g_freq[threadIdx.x] = (float)pow(10000.0, -(double)threadIdx.x / 32.0);
}

__device__ __forceinline__ void rope_pair(float* p, int pos, int i)
{
    const float f = (float)pos * g_freq[i];
    float sn, c;
    sincosf(f, &sn, &c);
    const float e = p[0], o = p[1];
    p[0] = e * c - o * sn;
    p[1] = e * sn + o * c;
}

__global__ void rope_q_kernel(float* __restrict__ q)
{
    const int idx = blockIdx.x * blockDim.x + threadIdx.x;
    const int i   = idx & 31;
    const int h   = (idx >> 5) & (NH_ - 1);
    const int row = idx >> 9;
    const int s   = row & (S_ - 1);
    rope_pair(q + (size_t)row * (NH_ * DQK) + h * DQK + DN + 2 * i, s, i);
}

__global__ void rope_k_kernel(float* __restrict__ kv)
{
    const int idx = blockIdx.x * blockDim.x + threadIdx.x;
    const int i   = idx & 31;
    const int row = idx >> 5;
    const int s   = row & (S_ - 1);
    rope_pair(kv + (size_t)row * (KVL + DR) + KVL + 2 * i, s, i);
}

// ---------------------------------------------------------------------------
// Flash prep conversions
// ---------------------------------------------------------------------------
__global__ void conv_hl_kernel(const float* __restrict__ in,
                               __nv_bfloat16* __restrict__ hi_o,
                               __nv_bfloat16* __restrict__ lo_o, int n4)
{
    const int idx = blockIdx.x * blockDim.x + threadIdx.x;
    if (idx >= n4) return;
    float4 v = *(const float4*)(in + (size_t)idx * 4);
    const float vv[4] = {v.x, v.y, v.z, v.w};
    __nv_bfloat16 hi[4], lo[4];
    #pragma unroll
    for (int i = 0; i < 4; i++) {
        hi[i] = __float2bfloat16(vv[i]);
        lo[i] = __float2bfloat16(vv[i] - __bfloat162float(hi[i]));
    }
    *(__nv_bfloat162*)(hi_o + (size_t)idx * 4 + 0) = __nv_bfloat162(hi[0], hi[1]);
    *(__nv_bfloat162*)(hi_o + (size_t)idx * 4 + 2) = __nv_bfloat162(hi[2], hi[3]);
    *(__nv_bfloat162*)(lo_o + (size_t)idx * 4 + 0) = __nv_bfloat162(lo[0], lo[1]);
    *(__nv_bfloat162*)(lo_o + (size_t)idx * 4 + 2) = __nv_bfloat162(lo[2], lo[3]);
}

// K assembly: [row][h][192] = kvx nope (per-head) | g_kv pe (shared) -> hi/lo
__global__ void convk_kernel(const float* __restrict__ kvx, const float* __restrict__ kv,
                             __nv_bfloat16* __restrict__ kh, __nv_bfloat16* __restrict__ kl)
{
    const int idx = blockIdx.x * blockDim.x + threadIdx.x; // (row, h, dg) dg in [0,48)
    if (idx >= BS * NH_ * 48) return;
    const int dg  = idx % 48;
    const int h   = (idx / 48) & (NH_ - 1);
    const int row = idx / (48 * NH_);
    float4 v;
    if (dg < 32) v = *(const float4*)(kvx + (size_t)row * (NH_ * 256) + h * 256 + dg * 4);
    else         v = *(const float4*)(kv + (size_t)row * (KVL + DR) + KVL + (dg - 32) * 4);
    const float vv[4] = {v.x, v.y, v.z, v.w};
    __nv_bfloat16 hi[4], lo[4];
    #pragma unroll
    for (int i = 0; i < 4; i++) {
        hi[i] = __float2bfloat16(vv[i]);
        lo[i] = __float2bfloat16(vv[i] - __bfloat162float(hi[i]));
    }
    const size_t o = ((size_t)row * NH_ + h) * 192 + dg * 4;
    *(__nv_bfloat162*)(kh + o + 0) = __nv_bfloat162(hi[0], hi[1]);
    *(__nv_bfloat162*)(kh + o + 2) = __nv_bfloat162(hi[2], hi[3]);
    *(__nv_bfloat162*)(kl + o + 0) = __nv_bfloat162(lo[0], lo[1]);
    *(__nv_bfloat162*)(kl + o + 2) = __nv_bfloat162(lo[2], lo[3]);
}

// V transpose: kvx[.,h,128+dv] (row=b*S+s) -> vt[b][h][dv][s], hi/lo
__global__ void convvt_kernel(const float* __restrict__ kvx,
                              __nv_bfloat16* __restrict__ vth, __nv_bfloat16* __restrict__ vtl)
{
    __shared__ float tile[32][33];
    const int bh = blockIdx.z;               // b*NH + h
    const int b = bh >> 4, h = bh & 15;
    const int s0 = blockIdx.x * 32, dv0 = blockIdx.y * 32;
    const int tx = threadIdx.x, ty = threadIdx.y;
    #pragma unroll
    for (int j = 0; j < 4; j++) {
        const int s = s0 + ty + 8 * j;
        tile[ty + 8 * j][tx] =
            kvx[(size_t)(b * S_ + s) * (NH_ * 256) + h * 256 + DN + dv0 + tx];
    }
    __syncthreads();
    #pragma unroll
    for (int j = 0; j < 4; j++) {
        const int dv = dv0 + ty + 8 * j;
        const float v = tile[tx][ty + 8 * j];
        const __nv_bfloat16 hi = __float2bfloat16(v);
        const __nv_bfloat16 lo = __float2bfloat16(v - __bfloat162float(hi));
        const size_t o = ((size_t)bh * DV + dv) * S_ + s0 + tx;
        vth[o] = hi; vtl[o] = lo;
    }
}

// ---------------------------------------------------------------------------
// Flash attention on HMMA (bf16 split-3 both phases)
// CTA: 128 q rows x (head, batch); 8 warps x 16 rows; key tiles of 64.
// Full K/V software pipelining: K(i+1) loads during PV(i), V(i+1) during QK(i+1).
// ---------------------------------------------------------------------------
__global__ __launch_bounds__(256, 1)
void flash_mma_kernel(const __nv_bfloat16* __restrict__ qh, const __nv_bfloat16* __restrict__ ql,
                      const __nv_bfloat16* __restrict__ kh, const __nv_bfloat16* __restrict__ kl,
                      const __nv_bfloat16* __restrict__ vth, const __nv_bfloat16* __restrict__ vtl,
                      float* __restrict__ out)
{
    extern __shared__ __align__(128) char sm[];
    const uint32_t sb = smem_u32(sm);
    const int tid = threadIdx.x, warp = tid >> 5, lane = tid & 31;
    const int h = blockIdx.y, b = blockIdx.z;
    const int q0 = blockIdx.x * 128;
    const int wr = warp * 16;

    auto load_k = [&](int kt) {
        for (int u = tid; u < 64 * 24; u += 256) {
            const int r = u / 24, c = u % 24;
            const size_t off = ((size_t)(b * S_ + kt + r) * NH_ + h) * 192 + c * 8;
            cp_async16(sb + SM_KH + r * 400 + c * 16, kh + off);
            cp_async16(sb + SM_KL + r * 400 + c * 16, kl + off);
        }
    };
    auto load_v = [&](int kt) {
        for (int u = tid; u < 128 * 8; u += 256) {
            const int dv = u / 8, ck = u % 8;
            const size_t off = ((size_t)(b * NH_ + h) * DV + dv) * S_ + kt + ck * 8;
            cp_async16(sb + SM_VH + dv * 144 + ck * 16, vth + off);
            cp_async16(sb + SM_VL + dv * 144 + ck * 16, vtl + off);
        }
    };

    // preload: Q tiles + K0 (group 1), V0 (group 2)
    for (int u = tid; u < 128 * 24; u += 256) {
        const int r = u / 24, c = u % 24;
        const size_t off = ((size_t)(b * S_ + q0 + r) * NH_ + h) * 192 + c * 8;
        cp_async16(sb + SM_QH + r * 400 + c * 16, qh + off);
        cp_async16(sb + SM_QL + r * 400 + c * 16, ql + off);
    }
    load_k(0);
    CP_COMMIT();
    load_v(0);
    CP_COMMIT();

    float oacc[16][4];
    #pragma unroll
    for (int i = 0; i < 16; i++)
        #pragma unroll
        for (int j = 0; j < 4; j++) oacc[i][j] = 0.f;
    float m0 = -1e30f, m1 = -1e30f, l0 = 0.f, l1 = 0.f;

    // ldmatrix lane addressing (same scheme as proven gemm)
    const uint32_t aQoff = (uint32_t)(wr + (lane & 15)) * 400 + ((lane >> 4) << 4);
    const int rB8  = (lane & 7) + ((lane >> 4) << 3);
    const uint32_t bKoff = (uint32_t)rB8 * 400 + (((lane >> 3) & 1) << 4);
    const uint32_t bVoff = (uint32_t)rB8 * 144 + (((lane >> 3) & 1) << 4);

    for (int kt = 0; kt < S_; kt += 64) {
        const bool has_next = (kt + 64 < S_);
        CP_WAIT1();      // Q+K ready (V of this iter may still be in flight)
        __syncthreads();

        // ---- S = Q K^T (3 segments over d=192) ----
        float sacc[8][4];
        #pragma unroll
        for (int i = 0; i < 8; i++)
            #pragma unroll
            for (int j = 0; j < 4; j++) sacc[i][j] = 0.f;

        #pragma unroll
        for (int seg = 0; seg < 3; seg++) {
            const uint32_t qb = sb + (seg == 1 ? SM_QL : SM_QH);
            const uint32_t kb = sb + (seg == 2 ? SM_KL : SM_KH);
            #pragma unroll
            for (int ks = 0; ks < 12; ks++) {
                uint32_t a[4];
                ldsm_x4(a[0], a[1], a[2], a[3], qb + aQoff + ks * 32);
                #pragma unroll
                for (int g = 0; g < 4; g++) {
                    uint32_t r0, r1, r2, r3;
                    ldsm_x4(r0, r1, r2, r3, kb + bKoff + (uint32_t)g * 16 * 400 + ks * 32);
                    uint32_t b0[2] = {r0, r1}, b1[2] = {r2, r3};
                    mma_bf16(sacc[2 * g], a, b0);
                    mma_bf16(sacc[2 * g + 1], a, b1);
                }
            }
        }

        __syncthreads();               // K tile fully consumed by all warps
        if (has_next) load_k(kt + 64); // prefetch next K into freed buffer
        CP_COMMIT();

        // ---- online softmax (rows gr and gr+8); overlaps V arrival ----
        float mx0 = -1e30f, mx1 = -1e30f;
        #pragma unroll
        for (int nt = 0; nt < 8; nt++) {
            #pragma unroll
            for (int j = 0; j < 4; j++) sacc[nt][j] *= SCALE;
            mx0 = fmaxf(mx0, fmaxf(sacc[nt][0], sacc[nt][1]));
            mx1 = fmaxf(mx1, fmaxf(sacc[nt][2], sacc[nt][3]));
        }
        mx0 = fmaxf(mx0, __shfl_xor_sync(0xffffffffu, mx0, 1));
        mx0 = fmaxf(mx0, __shfl_xor_sync(0xffffffffu, mx0, 2));
        mx1 = fmaxf(mx1, __shfl_xor_sync(0xffffffffu, mx1, 1));
        mx1 = fmaxf(mx1, __shfl_xor_sync(0xffffffffu, mx1, 2));
        const float mn0 = fmaxf(m0, mx0), mn1 = fmaxf(m1, mx1);
        const float al0 = __expf(m0 - mn0), al1 = __expf(m1 - mn1);
        float rs0 = 0.f, rs1 = 0.f;
        #pragma unroll
        for (int nt = 0; nt < 8; nt++) {
            sacc[nt][0] = __expf(sacc[nt][0] - mn0);
            sacc[nt][1] = __expf(sacc[nt][1] - mn0);
            sacc[nt][2] = __expf(sacc[nt][2] - mn1);
            sacc[nt][3] = __expf(sacc[nt][3] - mn1);
            rs0 += sacc[nt][0] + sacc[nt][1];
            rs1 += sacc[nt][2] + sacc[nt][3];
        }
        rs0 += __shfl_xor_sync(0xffffffffu, rs0, 1);
        rs0 += __shfl_xor_sync(0xffffffffu, rs0, 2);
        rs1 += __shfl_xor_sync(0xffffffffu, rs1, 1);
        rs1 += __shfl_xor_sync(0xffffffffu, rs1, 2);
        l0 = l0 * al0 + rs0; m0 = mn0;
        l1 = l1 * al1 + rs1; m1 = mn1;
        #pragma unroll
        for (int nt = 0; nt < 16; nt++) {
            oacc[nt][0] *= al0; oacc[nt][1] *= al0;
            oacc[nt][2] *= al1; oacc[nt][3] *= al1;
        }

        if (has_next) { CP_WAIT1(); } else { CP_WAIT0(); }  // V ready
        __syncthreads();

        // ---- O += P V (P split hi/lo in regs, V hi/lo in smem) ----
        #pragma unroll
        for (int kk = 0; kk < 4; kk++) {
            uint32_t ah[4], alr[4];
            {
                const float* p0 = sacc[2 * kk];
                const float* p1 = sacc[2 * kk + 1];
                float h00 = __bfloat162float(__float2bfloat16(p0[0]));
                float h01 = __bfloat162float(__float2bfloat16(p0[1]));
                float h02 = __bfloat162float(__float2bfloat16(p0[2]));
                float h03 = __bfloat162float(__float2bfloat16(p0[3]));
                float h10 = __bfloat162float(__float2bfloat16(p1[0]));
                float h11 = __bfloat162float(__float2bfloat16(p1[1]));
                float h12 = __bfloat162float(__float2bfloat16(p1[2]));
                float h13 = __bfloat162float(__float2bfloat16(p1[3]));
                ah[0] = pack_bf2(p0[0], p0[1]);
                ah[1] = pack_bf2(p0[2], p0[3]);
                ah[2] = pack_bf2(p1[0], p1[1]);
                ah[3] = pack_bf2(p1[2], p1[3]);
                alr[0] = pack_bf2(p0[0] - h00, p0[1] - h01);
                alr[1] = pack_bf2(p0[2] - h02, p0[3] - h03);
                alr[2] = pack_bf2(p1[0] - h10, p1[1] - h11);
                alr[3] = pack_bf2(p1[2] - h12, p1[3] - h13);
            }
            #pragma unroll
            for (int half = 0; half < 2; half++) {
                uint32_t bv[8][2];
                #pragma unroll
                for (int g = 0; g < 4; g++) {
                    uint32_t r0, r1, r2, r3;
                    ldsm_x4(r0, r1, r2, r3,
                            sb + SM_VH + bVoff + (uint32_t)(half * 64 + g * 16) * 144 + kk * 32);
                    bv[2 * g][0] = r0; bv[2 * g][1] = r1;
                    bv[2 * g + 1][0] = r2; bv[2 * g + 1][1] = r3;
                }
                #pragma unroll
                for (int t = 0; t < 8; t++) {
                    mma_bf16(oacc[half * 8 + t], ah, bv[t]);
                    mma_bf16(oacc[half * 8 + t], alr, bv[t]);
                }
                #pragma unroll
                for (int g = 0; g < 4; g++) {
                    uint32_t r0, r1, r2, r3;
                    ldsm_x4(r0, r1, r2, r3,
                            sb + SM_VL + bVoff + (uint32_t)(half * 64 + g * 16) * 144 + kk * 32);
                    bv[2 * g][0] = r0; bv[2 * g][1] = r1;
                    bv[2 * g + 1][0] = r2; bv[2 * g + 1][1] = r3;
                }
                #pragma unroll
                for (int t = 0; t < 8; t++)
                    mma_bf16(oacc[half * 8 + t], ah, bv[t]);
            }
        }

        __syncthreads();               // V tile fully consumed
        if (has_next) load_v(kt + 64); // prefetch next V into freed buffer
        CP_COMMIT();
    }

    // epilogue
    const float inv0 = 1.f / l0, inv1 = 1.f / l1;
    const int gr = lane >> 2, gc = (lane & 3) * 2;
    const int row0 = b * S_ + q0 + wr + gr;
    #pragma unroll
    for (int nt = 0; nt < 16; nt++) {
        const int col = h * DV + nt * 8 + gc;
        *(float2*)(out + (size_t)row0 * (NH_ * DV) + col) =
            make_float2(oacc[nt][0] * inv0, oacc[nt][1] * inv0);
        *(float2*)(out + (size_t)(row0 + 8) * (NH_ * DV) + col) =
            make_float2(oacc[nt][2] * inv1, oacc[nt][3] * inv1);
    }
}

// ---------------------------------------------------------------------------
// Launcher
// ---------------------------------------------------------------------------
static inline void run_conv3(const float* in, __nv_bfloat16* out, int R, int Rpad,
                             int Kin, int ldin, int mode)
{
    const int total = Rpad * (Kin / 4);
    conv3_kernel<<<(total + 255) / 256, 256>>>(in, out, R, Rpad, Kin, ldin, mode);
}

static inline void run_gemm(const __nv_bfloat16* A, const __nv_bfloat16* Bw, float* C,
                            int Npad, int N, int K3, int ldc)
{
    gemm_bf16_kernel<<<dim3(Npad / 64, BS / 128), 128>>>(A, Bw, C, N, K3, ldc);
}

extern "C" void kernel_launch(void* const* d_in, const int* in_sizes, int n_in,
                              void* d_out, int out_size)
{
    const float* hs    = (const float*)d_in[0];
    const float* wq_a  = (const float*)d_in[1];
    const float* qnw   = (const float*)d_in[2];
    const float* wq_b  = (const float*)d_in[3];
    const float* wkv_a = (const float*)d_in[4];
    const float* kvnw  = (const float*)d_in[5];
    const float* wkv_b = (const float*)d_in[6];
    const float* wo    = (const float*)d_in[7];
    float* out = (float*)d_out;

    void* p;
    cudaGetSymbolAddress(&p, g_qlora); float* qlora = (float*)p;
    cudaGetSymbolAddress(&p, g_q);     float* qbuf  = (float*)p;
    cudaGetSymbolAddress(&p, g_kv);    float* kvbuf = (float*)p;
    cudaGetSymbolAddress(&p, g_kvx);   float* kvx   = (float*)p;
    cudaGetSymbolAddress(&p, g_attn);  float* attn  = (float*)p;
    cudaGetSymbolAddress(&p, g_a3);    __nv_bfloat16* a3 = (__nv_bfloat16*)p;
    cudaGetSymbolAddress(&p, g_b3);    __nv_bfloat16* b3 = (__nv_bfloat16*)p;
    cudaGetSymbolAddress(&p, g_qh);    __nv_bfloat16* qh = (__nv_bfloat16*)p;
    cudaGetSymbolAddress(&p, g_ql2);   __nv_bfloat16* ql = (__nv_bfloat16*)p;
    cudaGetSymbolAddress(&p, g_kh);    __nv_bfloat16* kh = (__nv_bfloat16*)p;
    cudaGetSymbolAddress(&p, g_kl);    __nv_bfloat16* kl = (__nv_bfloat16*)p;
    cudaGetSymbolAddress(&p, g_vth);   __nv_bfloat16* vth = (__nv_bfloat16*)p;
    cudaGetSymbolAddress(&p, g_vtl);   __nv_bfloat16* vtl = (__nv_bfloat16*)p;

    cudaFuncSetAttribute(flash_mma_kernel, cudaFuncAttributeMaxDynamicSharedMemorySize,
                         FLASH_SMEM);

    freq_init_kernel<<<1, 32>>>();

    // 1) q_lora = hs @ wq_a^T        [4096, 1536]
    run_conv3(hs, a3, BS, BS, H_, H_, 0);
    run_conv3(wq_a, b3, QL, QL, H_, H_, 1);
    run_gemm(a3, b3, qlora, QL, QL, 3 * H_, QL);

    // 2) kv = hs @ wkv_a^T           [4096, 576] (Npad 640)
    run_conv3(wkv_a, b3, KVL + DR, 640, H_, H_, 1);
    run_gemm(a3, b3, kvbuf, 640, KVL + DR, 3 * H_, KVL + DR);

    // 3) norms + k rope
    rmsnorm_kernel<<<BS, 256>>>(qlora, qnw, QL, QL);
    rmsnorm_kernel<<<BS, 256>>>(kvbuf, kvnw, KVL, KVL + DR);
    rope_k_kernel<<<(BS * 32) / 256, 256>>>(kvbuf);

    // 4) q = q_lora @ wq_b^T         [4096, 3072]
    run_conv3(qlora, a3, BS, BS, QL, QL, 0);
    run_conv3(wq_b, b3, NH_ * DQK, NH_ * DQK, QL, QL, 1);
    run_gemm(a3, b3, qbuf, NH_ * DQK, NH_ * DQK, 3 * QL, NH_ * DQK);
    rope_q_kernel<<<(BS * NH_ * 32) / 256, 256>>>(qbuf);

    // 5) kv_x = kv_c @ wkv_b^T       [4096, 4096]
    run_conv3(kvbuf, a3, BS, BS, KVL, KVL + DR, 0);
    run_conv3(wkv_b, b3, NH_ * (DN + DV), NH_ * (DN + DV), KVL, KVL, 1);
    run_gemm(a3, b3, kvx, NH_ * (DN + DV), NH_ * (DN + DV), 3 * KVL, NH_ * (DN + DV));

    // 6) flash prep: Q/K hi-lo, V hi-lo transposed
    conv_hl_kernel<<<(BS * NH_ * DQK / 4 + 255) / 256, 256>>>(qbuf, qh, ql, BS * NH_ * DQK / 4);
    convk_kernel<<<(BS * NH_ * 48 + 255) / 256, 256>>>(kvx, kvbuf, kh, kl);
    convvt_kernel<<<dim3(S_ / 32, DV / 32, B_ * NH_), dim3(32, 8)>>>(kvx, vth, vtl);

    // 7) flash attention (HMMA) -> attn [4096, 2048]
    flash_mma_kernel<<<dim3(S_ / 128, NH_, B_), 256, FLASH_SMEM>>>(qh, ql, kh, kl, vth, vtl, attn);

    // 8) out = attn @ wo^T           [4096, 2048]
    run_conv3(attn, a3, BS, BS, NH_ * DV, NH_ * DV, 0);
    run_conv3(wo, b3, H_, H_, NH_ * DV, NH_ * DV, 1);
    run_gemm(a3, b3, out, H_, H_, 3 * NH_ * DV, H_);
}

// round 9
// speedup vs baseline: 3.6608x; 1.0264x over previous
#include <cuda_runtime.h>
#include <cuda_bf16.h>
#include <math.h>
#include <stdint.h>

// ---------------------------------------------------------------------------
// Problem constants (MLA prefill)
// ---------------------------------------------------------------------------
namespace {
constexpr int B_   = 2;
constexpr int S_   = 2048;
constexpr int H_   = 2048;
constexpr int NH_  = 16;
constexpr int QL   = 1536;
constexpr int KVL  = 512;
constexpr int DN   = 128;
constexpr int DR   = 64;
constexpr int DV   = 128;
constexpr int DQK  = 192;
constexpr int BS   = B_ * S_;
constexpr float SCALE = 0.07216878364870322f; // 1/sqrt(192)

// flash smem: Qh/Ql [128][pitch200], Kh/Kl [64][200], Vth/Vtl [128][72]
constexpr int SM_QH  = 0;
constexpr int SM_QL  = SM_QH + 128 * 400;
constexpr int SM_KH  = SM_QL + 128 * 400;
constexpr int SM_KL  = SM_KH + 64 * 400;
constexpr int SM_VH  = SM_KL + 64 * 400;
constexpr int SM_VL  = SM_VH + 128 * 144;
constexpr int FLASH_SMEM = SM_VL + 128 * 144; // 190,464 B
} // namespace

// ---------------------------------------------------------------------------
// Scratch (static device globals; no runtime allocation allowed)
// ---------------------------------------------------------------------------
__device__ float g_qlora[(size_t)BS * QL];
__device__ float g_kv[(size_t)BS * (KVL + DR)];
__device__ float g_kvx[(size_t)BS * NH_ * (DN + DV)];
__device__ __nv_bfloat16 g_a3[(size_t)BS * 6144];    // activations [hi | lo]
__device__ __nv_bfloat16 g_b3[(size_t)3072 * 4608];  // weights     [hi | lo]
// flash operands (bf16 hi/lo)
__device__ __nv_bfloat16 g_qh[(size_t)BS * NH_ * DQK];
__device__ __nv_bfloat16 g_ql2[(size_t)BS * NH_ * DQK];
__device__ __nv_bfloat16 g_kh[(size_t)BS * NH_ * DQK];
__device__ __nv_bfloat16 g_kl[(size_t)BS * NH_ * DQK];
__device__ __nv_bfloat16 g_vth[(size_t)B_ * NH_ * DV * S_];  // [b][h][dv][s]
__device__ __nv_bfloat16 g_vtl[(size_t)B_ * NH_ * DV * S_];
__device__ float g_freq[32];

// ---------------------------------------------------------------------------
// Helpers
// ---------------------------------------------------------------------------
__device__ __forceinline__ uint32_t smem_u32(const void* p) {
    uint32_t a;
    asm("{ .reg .u64 t; cvta.to.shared.u64 t, %1; cvt.u32.u64 %0, t; }" : "=r"(a) : "l"(p));
    return a;
}
__device__ __forceinline__ void cp_async16(uint32_t dst, const void* src) {
    asm volatile("cp.async.cg.shared.global [%0], [%1], 16;" :: "r"(dst), "l"(src) : "memory");
}
#define CP_COMMIT() asm volatile("cp.async.commit_group;" ::: "memory")
#define CP_WAIT2()  asm volatile("cp.async.wait_group 2;" ::: "memory")
#define CP_WAIT1()  asm volatile("cp.async.wait_group 1;" ::: "memory")
#define CP_WAIT0()  asm volatile("cp.async.wait_group 0;" ::: "memory")

__device__ __forceinline__ void ldsm_x4(uint32_t& r0, uint32_t& r1, uint32_t& r2, uint32_t& r3,
                                        uint32_t addr) {
    asm volatile("ldmatrix.sync.aligned.m8n8.x4.shared.b16 {%0,%1,%2,%3}, [%4];"
                 : "=r"(r0), "=r"(r1), "=r"(r2), "=r"(r3) : "r"(addr));
}
__device__ __forceinline__ void mma_bf16(float* c, const uint32_t* a, const uint32_t* b) {
    asm volatile("mma.sync.aligned.m16n8k16.row.col.f32.bf16.bf16.f32 "
                 "{%0,%1,%2,%3}, {%4,%5,%6,%7}, {%8,%9}, {%0,%1,%2,%3};"
                 : "+f"(c[0]), "+f"(c[1]), "+f"(c[2]), "+f"(c[3])
                 : "r"(a[0]), "r"(a[1]), "r"(a[2]), "r"(a[3]), "r"(b[0]), "r"(b[1]));
}
__device__ __forceinline__ uint32_t swoff(int r, int c) {
    return (uint32_t)(r * 64 + ((c ^ ((r >> 1) & 3)) << 4));
}
__device__ __forceinline__ uint32_t pack_bf2(float x, float y) {
    __nv_bfloat162 t(__float2bfloat16(x), __float2bfloat16(y));
    return *(uint32_t*)&t;
}
__device__ __forceinline__ void hl_split2(float v0, float v1,
                                          __nv_bfloat162& hi, __nv_bfloat162& lo) {
    __nv_bfloat16 h0 = __float2bfloat16(v0), h1 = __float2bfloat16(v1);
    hi = __nv_bfloat162(h0, h1);
    lo = __nv_bfloat162(__float2bfloat16(v0 - __bfloat162float(h0)),
                        __float2bfloat16(v1 - __bfloat162float(h1)));
}

// ---------------------------------------------------------------------------
// hi/lo split conversion: in[R rows of ldin] -> hi_o/lo_o [Rpad rows of Kin]
// Rows in [R, Rpad) are zero-filled.
// ---------------------------------------------------------------------------
__global__ void conv_hl_kernel(const float* __restrict__ in,
                               __nv_bfloat16* __restrict__ hi_o,
                               __nv_bfloat16* __restrict__ lo_o,
                               int R, int Rpad, int Kin, int ldin)
{
    const int kq = Kin >> 2;
    const int idx = blockIdx.x * blockDim.x + threadIdx.x;
    if (idx >= Rpad * kq) return;
    const int row = idx / kq, cg = idx - row * kq;
    float4 v = make_float4(0.f, 0.f, 0.f, 0.f);
    if (row < R) v = *(const float4*)(in + (size_t)row * ldin + cg * 4);
    __nv_bfloat162 hiA, loA, hiB, loB;
    hl_split2(v.x, v.y, hiA, loA);
    hl_split2(v.z, v.w, hiB, loB);
    const size_t o = (size_t)row * Kin + cg * 4;
    *(__nv_bfloat162*)(hi_o + o + 0) = hiA;
    *(__nv_bfloat162*)(hi_o + o + 2) = hiB;
    *(__nv_bfloat162*)(lo_o + o + 0) = loA;
    *(__nv_bfloat162*)(lo_o + o + 2) = loB;
}

// ---------------------------------------------------------------------------
// HMMA bf16 GEMM with split-2 operands:
//   C = Ahi.Bhi^T + Alo.Bhi^T + Ahi.Blo^T  (segments mapped over 3K/32 chunks)
// CTA 128x64x32, 4 warps (2x2), warp tile 64x32, 4-stage cp.async, 4 CTAs/SM.
// mode 0: fp32 C.  mode 1: rope(d>=128) + hi/lo bf16 out (Chi/Clo), ldc cols.
// ---------------------------------------------------------------------------
__global__ __launch_bounds__(128, 4)
void gemm_bf16_kernel(const __nv_bfloat16* __restrict__ A,
                      const __nv_bfloat16* __restrict__ Bw,
                      size_t aSegOff, size_t bSegOff,
                      float* __restrict__ C,
                      __nv_bfloat16* __restrict__ Chi, __nv_bfloat16* __restrict__ Clo,
                      int N, int K, int ldc, int mode)
{
    __shared__ __nv_bfloat16 smv[4][192 * 32]; // [stage][A(128x32) | B(64x32)] = 48 KB
    const int tid = threadIdx.x;
    const int warp = tid >> 5, lane = tid & 31;
    const int m0 = blockIdx.y * 128, n0 = blockIdx.x * 64;
    const int KC = K / 32, NC = 3 * KC;

    const uint32_t sbase = smem_u32(&smv[0][0]);
    constexpr uint32_t STG  = 192u * 32 * 2;
    constexpr uint32_t BOFF = 128u * 32 * 2;

    const int lr0 = tid >> 2, lc0 = tid & 3;   // lr0 in [0,32)
    const uint32_t so0 = swoff(lr0, lc0);

    auto load_stage = [&](int kc, int s) {
        const uint32_t sb = sbase + s * STG;
        const int seg = (kc >= 2 * KC) ? 2 : (kc >= KC ? 1 : 0);
        const int within = kc - seg * KC;
        const __nv_bfloat16* Ab = A + (seg == 1 ? aSegOff : 0)
                                  + (size_t)(m0 + lr0) * K + within * 32 + lc0 * 8;
        const __nv_bfloat16* Bb = Bw + (seg == 2 ? bSegOff : 0)
                                  + (size_t)(n0 + lr0) * K + within * 32 + lc0 * 8;
        #pragma unroll
        for (int r = 0; r < 4; r++)
            cp_async16(sb + so0 + r * 32 * 64, Ab + (size_t)(r * 32) * K);
        #pragma unroll
        for (int r = 0; r < 2; r++)
            cp_async16(sb + BOFF + so0 + r * 32 * 64, Bb + (size_t)(r * 32) * K);
    };

    const int wm = (warp >> 1) * 64, wn = (warp & 1) * 32;
    const int rA = wm + (lane & 15), cA = lane >> 4;
    const int swzA = (rA >> 1) & 3;
    const int rB = wn + (lane & 7) + ((lane >> 4) << 3), cB = (lane >> 3) & 1;
    const int swzB = (rB >> 1) & 3;

    float acc[4][4][4];
    #pragma unroll
    for (int i = 0; i < 4; i++)
        #pragma unroll
        for (int j = 0; j < 4; j++)
            #pragma unroll
            for (int k = 0; k < 4; k++) acc[i][j][k] = 0.f;

    load_stage(0, 0); CP_COMMIT();
    load_stage(1, 1); CP_COMMIT();
    load_stage(2, 2); CP_COMMIT();
    CP_WAIT2();
    __syncthreads();

    for (int kc = 0; kc < NC; kc++) {
        if (kc + 3 < NC) load_stage(kc + 3, (kc + 3) & 3);
        CP_COMMIT();

        const uint32_t sb = sbase + (kc & 3) * STG;
        #pragma unroll
        for (int h = 0; h < 2; h++) {
            uint32_t a[4][4], b[4][2];
            #pragma unroll
            for (int i = 0; i < 4; i++)
                ldsm_x4(a[i][0], a[i][1], a[i][2], a[i][3],
                        sb + (uint32_t)((rA + 16 * i) * 64 + (((h * 2 + cA) ^ swzA) << 4)));
            #pragma unroll
            for (int j = 0; j < 2; j++) {
                uint32_t r0, r1, r2, r3;
                ldsm_x4(r0, r1, r2, r3,
                        sb + BOFF + (uint32_t)((rB + 16 * j) * 64 + (((h * 2 + cB) ^ swzB) << 4)));
                b[2 * j][0] = r0; b[2 * j][1] = r1;
                b[2 * j + 1][0] = r2; b[2 * j + 1][1] = r3;
            }
            #pragma unroll
            for (int i = 0; i < 4; i++)
                #pragma unroll
                for (int t = 0; t < 4; t++)
                    mma_bf16(acc[i][t], a[i], b[t]);
        }
        CP_WAIT2();
        __syncthreads();
    }

    const int gr = lane >> 2, gc = (lane & 3) * 2;
    if (mode == 0) {
        #pragma unroll
        for (int i = 0; i < 4; i++) {
            const int row0 = m0 + wm + i * 16 + gr;
            #pragma unroll
            for (int t = 0; t < 4; t++) {
                const int col = n0 + wn + t * 8 + gc;
                if (col < N) {
                    *(float2*)(C + (size_t)row0 * ldc + col) =
                        make_float2(acc[i][t][0], acc[i][t][1]);
                    *(float2*)(C + (size_t)(row0 + 8) * ldc + col) =
                        make_float2(acc[i][t][2], acc[i][t][3]);
                }
            }
        }
    } else {
        // rope on d>=128 within each 192-wide head, then hi/lo bf16 stores
        #pragma unroll
        for (int i = 0; i < 4; i++) {
            const int row0 = m0 + wm + i * 16 + gr;
            #pragma unroll
            for (int t = 0; t < 4; t++) {
                const int col = n0 + wn + t * 8 + gc;
                const int d = col % DQK;
                #pragma unroll
                for (int rr = 0; rr < 2; rr++) {
                    const int row = row0 + rr * 8;
                    float v0 = acc[i][t][rr * 2 + 0];
                    float v1 = acc[i][t][rr * 2 + 1];
                    if (d >= DN) {
                        const int fi = (d - DN) >> 1;
                        const float f = (float)(row & (S_ - 1)) * g_freq[fi];
                        float sn, cs;
                        sincosf(f, &sn, &cs);
                        const float e = v0, o = v1;
                        v0 = e * cs - o * sn;
                        v1 = e * sn + o * cs;
                    }
                    __nv_bfloat162 hi, lo;
                    hl_split2(v0, v1, hi, lo);
                    *(__nv_bfloat162*)(Chi + (size_t)row * ldc + col) = hi;
                    *(__nv_bfloat162*)(Clo + (size_t)row * ldc + col) = lo;
                }
            }
        }
    }
}

// ---------------------------------------------------------------------------
// RMSNorm / RoPE(K) / freq init
// ---------------------------------------------------------------------------
__global__ __launch_bounds__(256)
void rmsnorm_kernel(float* __restrict__ x, const float* __restrict__ w, int n, int ld)
{
    const int row = blockIdx.x;
    float* p = x + (size_t)row * ld;
    float ss = 0.f;
    for (int i = threadIdx.x; i < n; i += 256) { float v = p[i]; ss = fmaf(v, v, ss); }
    __shared__ float red[8];
    #pragma unroll
    for (int o = 16; o > 0; o >>= 1) ss += __shfl_xor_sync(0xffffffffu, ss, o);
    if ((threadIdx.x & 31) == 0) red[threadIdx.x >> 5] = ss;
    __syncthreads();
    __shared__ float s_inv;
    if (threadIdx.x == 0) {
        float t = 0.f;
        #pragma unroll
        for (int i = 0; i < 8; i++) t += red[i];
        s_inv = rsqrtf(t / (float)n + 1e-6f);
    }
    __syncthreads();
    const float inv = s_inv;
    for (int i = threadIdx.x; i < n; i += 256) p[i] = w[i] * p[i] * inv;
}

__global__ void freq_init_kernel()
{
    if (threadIdx.x < 32)
        g_freq[threadIdx.x] = (float)pow(10000.0, -(double)threadIdx.x / 32.0);
}

__global__ void rope_k_kernel(float* __restrict__ kv)
{
    const int idx = blockIdx.x * blockDim.x + threadIdx.x;
    const int i   = idx & 31;
    const int row = idx >> 5;
    const int s   = row & (S_ - 1);
    float* p = kv + (size_t)row * (KVL + DR) + KVL + 2 * i;
    const float f = (float)s * g_freq[i];
    float sn, c;
    sincosf(f, &sn, &c);
    const float e = p[0], o = p[1];
    p[0] = e * c - o * sn;
    p[1] = e * sn + o * c;
}

// ---------------------------------------------------------------------------
// Flash prep: K assembly + V transpose (hi/lo)
// ---------------------------------------------------------------------------
__global__ void convk_kernel(const float* __restrict__ kvx, const float* __restrict__ kv,
                             __nv_bfloat16* __restrict__ kh, __nv_bfloat16* __restrict__ kl)
{
    const int idx = blockIdx.x * blockDim.x + threadIdx.x; // (row, h, dg) dg in [0,48)
    if (idx >= BS * NH_ * 48) return;
    const int dg  = idx % 48;
    const int h   = (idx / 48) & (NH_ - 1);
    const int row = idx / (48 * NH_);
    float4 v;
    if (dg < 32) v = *(const float4*)(kvx + (size_t)row * (NH_ * 256) + h * 256 + dg * 4);
    else         v = *(const float4*)(kv + (size_t)row * (KVL + DR) + KVL + (dg - 32) * 4);
    __nv_bfloat162 hiA, loA, hiB, loB;
    hl_split2(v.x, v.y, hiA, loA);
    hl_split2(v.z, v.w, hiB, loB);
    const size_t o = ((size_t)row * NH_ + h) * 192 + dg * 4;
    *(__nv_bfloat162*)(kh + o + 0) = hiA;
    *(__nv_bfloat162*)(kh + o + 2) = hiB;
    *(__nv_bfloat162*)(kl + o + 0) = loA;
    *(__nv_bfloat162*)(kl + o + 2) = loB;
}

__global__ void convvt_kernel(const float* __restrict__ kvx,
                              __nv_bfloat16* __restrict__ vth, __nv_bfloat16* __restrict__ vtl)
{
    __shared__ float tile[32][33];
    const int bh = blockIdx.z;               // b*NH + h
    const int b = bh >> 4, h = bh & 15;
    const int s0 = blockIdx.x * 32, dv0 = blockIdx.y * 32;
    const int tx = threadIdx.x, ty = threadIdx.y;
    #pragma unroll
    for (int j = 0; j < 4; j++) {
        const int s = s0 + ty + 8 * j;
        tile[ty + 8 * j][tx] =
            kvx[(size_t)(b * S_ + s) * (NH_ * 256) + h * 256 + DN + dv0 + tx];
    }
    __syncthreads();
    #pragma unroll
    for (int j = 0; j < 4; j++) {
        const int dv = dv0 + ty + 8 * j;
        const float v = tile[tx][ty + 8 * j];
        const __nv_bfloat16 hi = __float2bfloat16(v);
        const __nv_bfloat16 lo = __float2bfloat16(v - __bfloat162float(hi));
        const size_t o = ((size_t)bh * DV + dv) * S_ + s0 + tx;
        vth[o] = hi; vtl[o] = lo;
    }
}

// ---------------------------------------------------------------------------
// Flash attention on HMMA; epilogue writes hi/lo bf16 directly (split-2 A for
// the final GEMM). Pipelined K/V loads as in R8.
// ---------------------------------------------------------------------------
__global__ __launch_bounds__(256, 1)
void flash_mma_kernel(const __nv_bfloat16* __restrict__ qh, const __nv_bfloat16* __restrict__ ql,
                      const __nv_bfloat16* __restrict__ kh, const __nv_bfloat16* __restrict__ kl,
                      const __nv_bfloat16* __restrict__ vth, const __nv_bfloat16* __restrict__ vtl,
                      __nv_bfloat16* __restrict__ ohi, __nv_bfloat16* __restrict__ olo)
{
    extern __shared__ __align__(128) char sm[];
    const uint32_t sb = smem_u32(sm);
    const int tid = threadIdx.x, warp = tid >> 5, lane = tid & 31;
    const int h = blockIdx.y, b = blockIdx.z;
    const int q0 = blockIdx.x * 128;
    const int wr = warp * 16;

    auto load_k = [&](int kt) {
        for (int u = tid; u < 64 * 24; u += 256) {
            const int r = u / 24, c = u % 24;
            const size_t off = ((size_t)(b * S_ + kt + r) * NH_ + h) * 192 + c * 8;
            cp_async16(sb + SM_KH + r * 400 + c * 16, kh + off);
            cp_async16(sb + SM_KL + r * 400 + c * 16, kl + off);
        }
    };
    auto load_v = [&](int kt) {
        for (int u = tid; u < 128 * 8; u += 256) {
            const int dv = u / 8, ck = u % 8;
            const size_t off = ((size_t)(b * NH_ + h) * DV + dv) * S_ + kt + ck * 8;
            cp_async16(sb + SM_VH + dv * 144 + ck * 16, vth + off);
            cp_async16(sb + SM_VL + dv * 144 + ck * 16, vtl + off);
        }
    };

    for (int u = tid; u < 128 * 24; u += 256) {
        const int r = u / 24, c = u % 24;
        const size_t off = ((size_t)(b * S_ + q0 + r) * NH_ + h) * 192 + c * 8;
        cp_async16(sb + SM_QH + r * 400 + c * 16, qh + off);
        cp_async16(sb + SM_QL + r * 400 + c * 16, ql + off);
    }
    load_k(0);
    CP_COMMIT();
    load_v(0);
    CP_COMMIT();

    float oacc[16][4];
    #pragma unroll
    for (int i = 0; i < 16; i++)
        #pragma unroll
        for (int j = 0; j < 4; j++) oacc[i][j] = 0.f;
    float m0 = -1e30f, m1 = -1e30f, l0 = 0.f, l1 = 0.f;

    const uint32_t aQoff = (uint32_t)(wr + (lane & 15)) * 400 + ((lane >> 4) << 4);
    const int rB8  = (lane & 7) + ((lane >> 4) << 3);
    const uint32_t bKoff = (uint32_t)rB8 * 400 + (((lane >> 3) & 1) << 4);
    const uint32_t bVoff = (uint32_t)rB8 * 144 + (((lane >> 3) & 1) << 4);

    for (int kt = 0; kt < S_; kt += 64) {
        const bool has_next = (kt + 64 < S_);
        CP_WAIT1();
        __syncthreads();

        float sacc[8][4];
        #pragma unroll
        for (int i = 0; i < 8; i++)
            #pragma unroll
            for (int j = 0; j < 4; j++) sacc[i][j] = 0.f;

        #pragma unroll
        for (int seg = 0; seg < 3; seg++) {
            const uint32_t qb = sb + (seg == 1 ? SM_QL : SM_QH);
            const uint32_t kb = sb + (seg == 2 ? SM_KL : SM_KH);
            #pragma unroll
            for (int ks = 0; ks < 12; ks++) {
                uint32_t a[4];
                ldsm_x4(a[0], a[1], a[2], a[3], qb + aQoff + ks * 32);
                #pragma unroll
                for (int g = 0; g < 4; g++) {
                    uint32_t r0, r1, r2, r3;
                    ldsm_x4(r0, r1, r2, r3, kb + bKoff + (uint32_t)g * 16 * 400 + ks * 32);
                    uint32_t b0[2] = {r0, r1}, b1[2] = {r2, r3};
                    mma_bf16(sacc[2 * g], a, b0);
                    mma_bf16(sacc[2 * g + 1], a, b1);
                }
            }
        }

        __syncthreads();
        if (has_next) load_k(kt + 64);
        CP_COMMIT();

        float mx0 = -1e30f, mx1 = -1e30f;
        #pragma unroll
        for (int nt = 0; nt < 8; nt++) {
            #pragma unroll
            for (int j = 0; j < 4; j++) sacc[nt][j] *= SCALE;
            mx0 = fmaxf(mx0, fmaxf(sacc[nt][0], sacc[nt][1]));
            mx1 = fmaxf(mx1, fmaxf(sacc[nt][2], sacc[nt][3]));
        }
        mx0 = fmaxf(mx0, __shfl_xor_sync(0xffffffffu, mx0, 1));
        mx0 = fmaxf(mx0, __shfl_xor_sync(0xffffffffu, mx0, 2));
        mx1 = fmaxf(mx1, __shfl_xor_sync(0xffffffffu, mx1, 1));
        mx1 = fmaxf(mx1, __shfl_xor_sync(0xffffffffu, mx1, 2));
        const float mn0 = fmaxf(m0, mx0), mn1 = fmaxf(m1, mx1);
        const float al0 = __expf(m0 - mn0), al1 = __expf(m1 - mn1);
        float rs0 = 0.f, rs1 = 0.f;
        #pragma unroll
        for (int nt = 0; nt < 8; nt++) {
            sacc[nt][0] = __expf(sacc[nt][0] - mn0);
            sacc[nt][1] = __expf(sacc[nt][1] - mn0);
            sacc[nt][2] = __expf(sacc[nt][2] - mn1);
            sacc[nt][3] = __expf(sacc[nt][3] - mn1);
            rs0 += sacc[nt][0] + sacc[nt][1];
            rs1 += sacc[nt][2] + sacc[nt][3];
        }
        rs0 += __shfl_xor_sync(0xffffffffu, rs0, 1);
        rs0 += __shfl_xor_sync(0xffffffffu, rs0, 2);
        rs1 += __shfl_xor_sync(0xffffffffu, rs1, 1);
        rs1 += __shfl_xor_sync(0xffffffffu, rs1, 2);
        l0 = l0 * al0 + rs0; m0 = mn0;
        l1 = l1 * al1 + rs1; m1 = mn1;
        #pragma unroll
        for (int nt = 0; nt < 16; nt++) {
            oacc[nt][0] *= al0; oacc[nt][1] *= al0;
            oacc[nt][2] *= al1; oacc[nt][3] *= al1;
        }

        if (has_next) { CP_WAIT1(); } else { CP_WAIT0(); }
        __syncthreads();

        #pragma unroll
        for (int kk = 0; kk < 4; kk++) {
            uint32_t ah[4], alr[4];
            {
                const float* p0 = sacc[2 * kk];
                const float* p1 = sacc[2 * kk + 1];
                float h00 = __bfloat162float(__float2bfloat16(p0[0]));
                float h01 = __bfloat162float(__float2bfloat16(p0[1]));
                float h02 = __bfloat162float(__float2bfloat16(p0[2]));
                float h03 = __bfloat162float(__float2bfloat16(p0[3]));
                float h10 = __bfloat162float(__float2bfloat16(p1[0]));
                float h11 = __bfloat162float(__float2bfloat16(p1[1]));
                float h12 = __bfloat162float(__float2bfloat16(p1[2]));
                float h13 = __bfloat162float(__float2bfloat16(p1[3]));
                ah[0] = pack_bf2(p0[0], p0[1]);
                ah[1] = pack_bf2(p0[2], p0[3]);
                ah[2] = pack_bf2(p1[0], p1[1]);
                ah[3] = pack_bf2(p1[2], p1[3]);
                alr[0] = pack_bf2(p0[0] - h00, p0[1] - h01);
                alr[1] = pack_bf2(p0[2] - h02, p0[3] - h03);
                alr[2] = pack_bf2(p1[0] - h10, p1[1] - h11);
                alr[3] = pack_bf2(p1[2] - h12, p1[3] - h13);
            }
            #pragma unroll
            for (int half = 0; half < 2; half++) {
                uint32_t bv[8][2];
                #pragma unroll
                for (int g = 0; g < 4; g++) {
                    uint32_t r0, r1, r2, r3;
                    ldsm_x4(r0, r1, r2, r3,
                            sb + SM_VH + bVoff + (uint32_t)(half * 64 + g * 16) * 144 + kk * 32);
                    bv[2 * g][0] = r0; bv[2 * g][1] = r1;
                    bv[2 * g + 1][0] = r2; bv[2 * g + 1][1] = r3;
                }
                #pragma unroll
                for (int t = 0; t < 8; t++) {
                    mma_bf16(oacc[half * 8 + t], ah, bv[t]);
                    mma_bf16(oacc[half * 8 + t], alr, bv[t]);
                }
                #pragma unroll
                for (int g = 0; g < 4; g++) {
                    uint32_t r0, r1, r2, r3;
                    ldsm_x4(r0, r1, r2, r3,
                            sb + SM_VL + bVoff + (uint32_t)(half * 64 + g * 16) * 144 + kk * 32);
                    bv[2 * g][0] = r0; bv[2 * g][1] = r1;
                    bv[2 * g + 1][0] = r2; bv[2 * g + 1][1] = r3;
                }
                #pragma unroll
                for (int t = 0; t < 8; t++)
                    mma_bf16(oacc[half * 8 + t], ah, bv[t]);
            }
        }

        __syncthreads();
        if (has_next) load_v(kt + 64);
        CP_COMMIT();
    }

    // epilogue: hi/lo bf16 directly into final-GEMM A layout [row][2048]
    const float inv0 = 1.f / l0, inv1 = 1.f / l1;
    const int gr = lane >> 2, gc = (lane & 3) * 2;
    const int row0 = b * S_ + q0 + wr + gr;
    #pragma unroll
    for (int nt = 0; nt < 16; nt++) {
        const int col = h * DV + nt * 8 + gc;
        __nv_bfloat162 hi, lo;
        hl_split2(oacc[nt][0] * inv0, oacc[nt][1] * inv0, hi, lo);
        *(__nv_bfloat162*)(ohi + (size_t)row0 * (NH_ * DV) + col) = hi;
        *(__nv_bfloat162*)(olo + (size_t)row0 * (NH_ * DV) + col) = lo;
        hl_split2(oacc[nt][2] * inv1, oacc[nt][3] * inv1, hi, lo);
        *(__nv_bfloat162*)(ohi + (size_t)(row0 + 8) * (NH_ * DV) + col) = hi;
        *(__nv_bfloat162*)(olo + (size_t)(row0 + 8) * (NH_ * DV) + col) = lo;
    }
}

// ---------------------------------------------------------------------------
// Launcher
// ---------------------------------------------------------------------------
static inline void run_conv(const float* in, __nv_bfloat16* hi, __nv_bfloat16* lo,
                            int R, int Rpad, int Kin, int ldin)
{
    const int total = Rpad * (Kin / 4);
    conv_hl_kernel<<<(total + 255) / 256, 256>>>(in, hi, lo, R, Rpad, Kin, ldin);
}

extern "C" void kernel_launch(void* const* d_in, const int* in_sizes, int n_in,
                              void* d_out, int out_size)
{
    const float* hs    = (const float*)d_in[0];
    const float* wq_a  = (const float*)d_in[1];
    const float* qnw   = (const float*)d_in[2];
    const float* wq_b  = (const float*)d_in[3];
    const float* wkv_a = (const float*)d_in[4];
    const float* kvnw  = (const float*)d_in[5];
    const float* wkv_b = (const float*)d_in[6];
    const float* wo    = (const float*)d_in[7];
    float* out = (float*)d_out;

    void* p;
    cudaGetSymbolAddress(&p, g_qlora); float* qlora = (float*)p;
    cudaGetSymbolAddress(&p, g_kv);    float* kvbuf = (float*)p;
    cudaGetSymbolAddress(&p, g_kvx);   float* kvx   = (float*)p;
    cudaGetSymbolAddress(&p, g_a3);    __nv_bfloat16* a3 = (__nv_bfloat16*)p;
    cudaGetSymbolAddress(&p, g_b3);    __nv_bfloat16* b3 = (__nv_bfloat16*)p;
    cudaGetSymbolAddress(&p, g_qh);    __nv_bfloat16* qh = (__nv_bfloat16*)p;
    cudaGetSymbolAddress(&p, g_ql2);   __nv_bfloat16* ql = (__nv_bfloat16*)p;
    cudaGetSymbolAddress(&p, g_kh);    __nv_bfloat16* kh = (__nv_bfloat16*)p;
    cudaGetSymbolAddress(&p, g_kl);    __nv_bfloat16* kl = (__nv_bfloat16*)p;
    cudaGetSymbolAddress(&p, g_vth);   __nv_bfloat16* vth = (__nv_bfloat16*)p;
    cudaGetSymbolAddress(&p, g_vtl);   __nv_bfloat16* vtl = (__nv_bfloat16*)p;

    cudaFuncSetAttribute(flash_mma_kernel, cudaFuncAttributeMaxDynamicSharedMemorySize,
                         FLASH_SMEM);

    freq_init_kernel<<<1, 32>>>();

    // 1) q_lora = hs @ wq_a^T        [4096, 1536], K=2048
    run_conv(hs, a3, a3 + (size_t)BS * H_, BS, BS, H_, H_);
    run_conv(wq_a, b3, b3 + (size_t)QL * H_, QL, QL, H_, H_);
    gemm_bf16_kernel<<<dim3(QL / 64, BS / 128), 128>>>(
        a3, b3, (size_t)BS * H_, (size_t)QL * H_, qlora, nullptr, nullptr, QL, H_, QL, 0);

    // 2) kv = hs @ wkv_a^T           [4096, 576] (Npad 640), same A
    run_conv(wkv_a, b3, b3 + (size_t)640 * H_, KVL + DR, 640, H_, H_);
    gemm_bf16_kernel<<<dim3(640 / 64, BS / 128), 128>>>(
        a3, b3, (size_t)BS * H_, (size_t)640 * H_, kvbuf, nullptr, nullptr,
        KVL + DR, H_, KVL + DR, 0);

    // 3) norms + k rope
    rmsnorm_kernel<<<BS, 256>>>(qlora, qnw, QL, QL);
    rmsnorm_kernel<<<BS, 256>>>(kvbuf, kvnw, KVL, KVL + DR);
    rope_k_kernel<<<(BS * 32) / 256, 256>>>(kvbuf);

    // 4) q = q_lora @ wq_b^T         [4096, 3072], K=1536; fused rope + hi/lo out
    run_conv(qlora, a3, a3 + (size_t)BS * QL, BS, BS, QL, QL);
    run_conv(wq_b, b3, b3 + (size_t)3072 * QL, NH_ * DQK, NH_ * DQK, QL, QL);
    gemm_bf16_kernel<<<dim3((NH_ * DQK) / 64, BS / 128), 128>>>(
        a3, b3, (size_t)BS * QL, (size_t)3072 * QL, nullptr, qh, ql,
        NH_ * DQK, QL, NH_ * DQK, 1);

    // 5) kv_x = kv_c @ wkv_b^T       [4096, 4096], K=512 (A ld 576)
    run_conv(kvbuf, a3, a3 + (size_t)BS * KVL, BS, BS, KVL, KVL + DR);
    run_conv(wkv_b, b3, b3 + (size_t)4096 * KVL, NH_ * (DN + DV), NH_ * (DN + DV), KVL, KVL);
    gemm_bf16_kernel<<<dim3((NH_ * (DN + DV)) / 64, BS / 128), 128>>>(
        a3, b3, (size_t)BS * KVL, (size_t)4096 * KVL, kvx, nullptr, nullptr,
        NH_ * (DN + DV), KVL, NH_ * (DN + DV), 0);

    // 6) flash prep: K assembly + V transpose (hi/lo)
    convk_kernel<<<(BS * NH_ * 48 + 255) / 256, 256>>>(kvx, kvbuf, kh, kl);
    convvt_kernel<<<dim3(S_ / 32, DV / 32, B_ * NH_), dim3(32, 8)>>>(kvx, vth, vtl);

    // 7) flash attention -> a3 hi/lo directly (split-2 A for final GEMM)
    flash_mma_kernel<<<dim3(S_ / 128, NH_, B_), 256, FLASH_SMEM>>>(
        qh, ql, kh, kl, vth, vtl, a3, a3 + (size_t)BS * (NH_ * DV));

    // 8) out = attn @ wo^T           [4096, 2048], K=2048
    run_conv(wo, b3, b3 + (size_t)H_ * (NH_ * DV), H_, H_, NH_ * DV, NH_ * DV);
    gemm_bf16_kernel<<<dim3(H_ / 64, BS / 128), 128>>>(
        a3, b3, (size_t)BS * (NH_ * DV), (size_t)H_ * (NH_ * DV), out, nullptr, nullptr,
        H_, NH_ * DV, H_, 0);
}

// round 10
// speedup vs baseline: 3.6651x; 1.0012x over previous
#include <cuda_runtime.h>
#include <cuda_bf16.h>
#include <math.h>
#include <stdint.h>

// ---------------------------------------------------------------------------
// Problem constants (MLA prefill)
// ---------------------------------------------------------------------------
namespace {
constexpr int B_   = 2;
constexpr int S_   = 2048;
constexpr int H_   = 2048;
constexpr int NH_  = 16;
constexpr int QL   = 1536;
constexpr int KVL  = 512;
constexpr int DN   = 128;
constexpr int DR   = 64;
constexpr int DV   = 128;
constexpr int DQK  = 192;
constexpr int BS   = B_ * S_;
constexpr float SCALE = 0.07216878364870322f; // 1/sqrt(192)

constexpr int SM_QH  = 0;
constexpr int SM_QL  = SM_QH + 128 * 400;
constexpr int SM_KH  = SM_QL + 128 * 400;
constexpr int SM_KL  = SM_KH + 64 * 400;
constexpr int SM_VH  = SM_KL + 64 * 400;
constexpr int SM_VL  = SM_VH + 128 * 144;
constexpr int FLASH_SMEM = SM_VL + 128 * 144; // 190,464 B
} // namespace

// ---------------------------------------------------------------------------
// Scratch (static device globals; no runtime allocation allowed)
// ---------------------------------------------------------------------------
__device__ float g_qlora[(size_t)BS * QL];
__device__ float g_kv[(size_t)BS * (KVL + DR)];
__device__ float g_kvx[(size_t)BS * NH_ * (DN + DV)];
__device__ __nv_bfloat16 g_a3[(size_t)BS * 6144];    // activations [hi | lo]
__device__ __nv_bfloat16 g_b3[(size_t)3072 * 4608];  // weights     [hi | lo]
__device__ __nv_bfloat16 g_qh[(size_t)BS * NH_ * DQK];
__device__ __nv_bfloat16 g_ql2[(size_t)BS * NH_ * DQK];
__device__ __nv_bfloat16 g_kh[(size_t)BS * NH_ * DQK];
__device__ __nv_bfloat16 g_kl[(size_t)BS * NH_ * DQK];
__device__ __nv_bfloat16 g_vth[(size_t)B_ * NH_ * DV * S_];  // [b][h][dv][s]
__device__ __nv_bfloat16 g_vtl[(size_t)B_ * NH_ * DV * S_];
__device__ float g_freq[32];

// ---------------------------------------------------------------------------
// Helpers
// ---------------------------------------------------------------------------
__device__ __forceinline__ uint32_t smem_u32(const void* p) {
    uint32_t a;
    asm("{ .reg .u64 t; cvta.to.shared.u64 t, %1; cvt.u32.u64 %0, t; }" : "=r"(a) : "l"(p));
    return a;
}
__device__ __forceinline__ void cp_async16(uint32_t dst, const void* src) {
    asm volatile("cp.async.cg.shared.global [%0], [%1], 16;" :: "r"(dst), "l"(src) : "memory");
}
#define CP_COMMIT() asm volatile("cp.async.commit_group;" ::: "memory")
#define CP_WAIT2()  asm volatile("cp.async.wait_group 2;" ::: "memory")
#define CP_WAIT1()  asm volatile("cp.async.wait_group 1;" ::: "memory")
#define CP_WAIT0()  asm volatile("cp.async.wait_group 0;" ::: "memory")

__device__ __forceinline__ void ldsm_x4(uint32_t& r0, uint32_t& r1, uint32_t& r2, uint32_t& r3,
                                        uint32_t addr) {
    asm volatile("ldmatrix.sync.aligned.m8n8.x4.shared.b16 {%0,%1,%2,%3}, [%4];"
                 : "=r"(r0), "=r"(r1), "=r"(r2), "=r"(r3) : "r"(addr));
}
__device__ __forceinline__ void mma_bf16(float* c, const uint32_t* a, const uint32_t* b) {
    asm volatile("mma.sync.aligned.m16n8k16.row.col.f32.bf16.bf16.f32 "
                 "{%0,%1,%2,%3}, {%4,%5,%6,%7}, {%8,%9}, {%0,%1,%2,%3};"
                 : "+f"(c[0]), "+f"(c[1]), "+f"(c[2]), "+f"(c[3])
                 : "r"(a[0]), "r"(a[1]), "r"(a[2]), "r"(a[3]), "r"(b[0]), "r"(b[1]));
}
__device__ __forceinline__ uint32_t swoff(int r, int c) {
    return (uint32_t)(r * 64 + ((c ^ ((r >> 1) & 3)) << 4));
}
__device__ __forceinline__ uint32_t pack_bf2(float x, float y) {
    __nv_bfloat162 t(__float2bfloat16(x), __float2bfloat16(y));
    return *(uint32_t*)&t;
}
__device__ __forceinline__ void hl_split2(float v0, float v1,
                                          __nv_bfloat162& hi, __nv_bfloat162& lo) {
    __nv_bfloat16 h0 = __float2bfloat16(v0), h1 = __float2bfloat16(v1);
    hi = __nv_bfloat162(h0, h1);
    lo = __nv_bfloat162(__float2bfloat16(v0 - __bfloat162float(h0)),
                        __float2bfloat16(v1 - __bfloat162float(h1)));
}

// ---------------------------------------------------------------------------
// hi/lo split conversion (plain): rows [R, Rpad) zero-filled
// ---------------------------------------------------------------------------
__global__ void conv_hl_kernel(const float* __restrict__ in,
                               __nv_bfloat16* __restrict__ hi_o,
                               __nv_bfloat16* __restrict__ lo_o,
                               int R, int Rpad, int Kin, int ldin)
{
    const int kq = Kin >> 2;
    const int idx = blockIdx.x * blockDim.x + threadIdx.x;
    if (idx >= Rpad * kq) return;
    const int row = idx / kq, cg = idx - row * kq;
    float4 v = make_float4(0.f, 0.f, 0.f, 0.f);
    if (row < R) v = *(const float4*)(in + (size_t)row * ldin + cg * 4);
    __nv_bfloat162 hiA, loA, hiB, loB;
    hl_split2(v.x, v.y, hiA, loA);
    hl_split2(v.z, v.w, hiB, loB);
    const size_t o = (size_t)row * Kin + cg * 4;
    *(__nv_bfloat162*)(hi_o + o + 0) = hiA;
    *(__nv_bfloat162*)(hi_o + o + 2) = hiB;
    *(__nv_bfloat162*)(lo_o + o + 0) = loA;
    *(__nv_bfloat162*)(lo_o + o + 2) = loB;
}

// ---------------------------------------------------------------------------
// Fused RMSNorm + hi/lo split: one block per row; out rows of stride n
// ---------------------------------------------------------------------------
__global__ __launch_bounds__(256)
void rms_conv_hl_kernel(const float* __restrict__ x, const float* __restrict__ w,
                        __nv_bfloat16* __restrict__ hi_o, __nv_bfloat16* __restrict__ lo_o,
                        int n, int ld)
{
    const int row = blockIdx.x;
    const float* p = x + (size_t)row * ld;
    float ss = 0.f;
    for (int i = threadIdx.x; i < n; i += 256) { float v = p[i]; ss = fmaf(v, v, ss); }
    __shared__ float red[8];
    #pragma unroll
    for (int o = 16; o > 0; o >>= 1) ss += __shfl_xor_sync(0xffffffffu, ss, o);
    if ((threadIdx.x & 31) == 0) red[threadIdx.x >> 5] = ss;
    __syncthreads();
    __shared__ float s_inv;
    if (threadIdx.x == 0) {
        float t = 0.f;
        #pragma unroll
        for (int i = 0; i < 8; i++) t += red[i];
        s_inv = rsqrtf(t / (float)n + 1e-6f);
    }
    __syncthreads();
    const float inv = s_inv;
    for (int i = threadIdx.x * 2; i < n; i += 512) {
        const float v0 = w[i] * p[i] * inv;
        const float v1 = w[i + 1] * p[i + 1] * inv;
        __nv_bfloat162 hi, lo;
        hl_split2(v0, v1, hi, lo);
        *(__nv_bfloat162*)(hi_o + (size_t)row * n + i) = hi;
        *(__nv_bfloat162*)(lo_o + (size_t)row * n + i) = lo;
    }
}

// ---------------------------------------------------------------------------
// HMMA bf16 GEMM, split-2 operands; incremental-pointer loader.
//   C = Ahi.Bhi^T + Alo.Bhi^T + Ahi.Blo^T   over 3*K/32 chunks
// CTA 128x64x32, 4 warps (2x2), warp tile 64x32, 4-stage cp.async, 4 CTAs/SM.
// mode 0: fp32 C.  mode 1: rope(d>=128) + hi/lo bf16 out.
// ---------------------------------------------------------------------------
__global__ __launch_bounds__(128, 4)
void gemm_bf16_kernel(const __nv_bfloat16* __restrict__ A,
                      const __nv_bfloat16* __restrict__ Bw,
                      size_t aSegOff, size_t bSegOff,
                      float* __restrict__ C,
                      __nv_bfloat16* __restrict__ Chi, __nv_bfloat16* __restrict__ Clo,
                      int N, int K, int ldc, int mode)
{
    __shared__ __nv_bfloat16 smv[4][192 * 32]; // 48 KB
    const int tid = threadIdx.x;
    const int warp = tid >> 5, lane = tid & 31;
    const int m0 = blockIdx.y * 128, n0 = blockIdx.x * 64;
    const int KC = K / 32, NC = 3 * KC;

    const uint32_t sbase = smem_u32(&smv[0][0]);
    constexpr uint32_t STG  = 192u * 32 * 2;
    constexpr uint32_t BOFF = 128u * 32 * 2;

    const int lr0 = tid >> 2, lc0 = tid & 3;   // lr0 in [0,32)
    const uint32_t so0 = swoff(lr0, lc0);

    // incremental loader state (monotonic chunk sequence)
    const __nv_bfloat16* pA = A  + (size_t)(m0 + lr0) * K + lc0 * 8;
    const __nv_bfloat16* pB = Bw + (size_t)(n0 + lr0) * K + lc0 * 8;
    int nextKc = 0;
    const size_t aRow = (size_t)32 * K, bRow = (size_t)32 * K;

    auto load_stage = [&](int s) {
        const uint32_t sb = sbase + s * STG;
        cp_async16(sb + so0 + 0 * 2048, pA);
        cp_async16(sb + so0 + 1 * 2048, pA + aRow);
        cp_async16(sb + so0 + 2 * 2048, pA + 2 * aRow);
        cp_async16(sb + so0 + 3 * 2048, pA + 3 * aRow);
        cp_async16(sb + BOFF + so0 + 0 * 2048, pB);
        cp_async16(sb + BOFF + so0 + 1 * 2048, pB + bRow);
        nextKc++;
        pA += 32; pB += 32;
        if (nextKc == KC)          { pA += aSegOff - K; pB -= K; }
        else if (nextKc == 2 * KC) { pA -= aSegOff + K; pB += bSegOff - K; }
    };

    const int wm = (warp >> 1) * 64, wn = (warp & 1) * 32;
    const int rA = wm + (lane & 15), cA = lane >> 4;
    const int swzA = (rA >> 1) & 3;
    const int rB = wn + (lane & 7) + ((lane >> 4) << 3), cB = (lane >> 3) & 1;
    const int swzB = (rB >> 1) & 3;

    float acc[4][4][4];
    #pragma unroll
    for (int i = 0; i < 4; i++)
        #pragma unroll
        for (int j = 0; j < 4; j++)
            #pragma unroll
            for (int k = 0; k < 4; k++) acc[i][j][k] = 0.f;

    load_stage(0); CP_COMMIT();
    load_stage(1); CP_COMMIT();
    load_stage(2); CP_COMMIT();
    CP_WAIT2();
    __syncthreads();

    for (int kc = 0; kc < NC; kc++) {
        if (kc + 3 < NC) load_stage((kc + 3) & 3);
        CP_COMMIT();

        const uint32_t sb = sbase + (kc & 3) * STG;
        #pragma unroll
        for (int h = 0; h < 2; h++) {
            uint32_t a[4][4], b[4][2];
            #pragma unroll
            for (int i = 0; i < 4; i++)
                ldsm_x4(a[i][0], a[i][1], a[i][2], a[i][3],
                        sb + (uint32_t)((rA + 16 * i) * 64 + (((h * 2 + cA) ^ swzA) << 4)));
            #pragma unroll
            for (int j = 0; j < 2; j++) {
                uint32_t r0, r1, r2, r3;
                ldsm_x4(r0, r1, r2, r3,
                        sb + BOFF + (uint32_t)((rB + 16 * j) * 64 + (((h * 2 + cB) ^ swzB) << 4)));
                b[2 * j][0] = r0; b[2 * j][1] = r1;
                b[2 * j + 1][0] = r2; b[2 * j + 1][1] = r3;
            }
            #pragma unroll
            for (int i = 0; i < 4; i++)
                #pragma unroll
                for (int t = 0; t < 4; t++)
                    mma_bf16(acc[i][t], a[i], b[t]);
        }
        CP_WAIT2();
        __syncthreads();
    }

    const int gr = lane >> 2, gc = (lane & 3) * 2;
    if (mode == 0) {
        #pragma unroll
        for (int i = 0; i < 4; i++) {
            const int row0 = m0 + wm + i * 16 + gr;
            #pragma unroll
            for (int t = 0; t < 4; t++) {
                const int col = n0 + wn + t * 8 + gc;
                if (col < N) {
                    *(float2*)(C + (size_t)row0 * ldc + col) =
                        make_float2(acc[i][t][0], acc[i][t][1]);
                    *(float2*)(C + (size_t)(row0 + 8) * ldc + col) =
                        make_float2(acc[i][t][2], acc[i][t][3]);
                }
            }
        }
    } else {
        #pragma unroll
        for (int i = 0; i < 4; i++) {
            const int row0 = m0 + wm + i * 16 + gr;
            #pragma unroll
            for (int t = 0; t < 4; t++) {
                const int col = n0 + wn + t * 8 + gc;
                const int d = col % DQK;
                #pragma unroll
                for (int rr = 0; rr < 2; rr++) {
                    const int row = row0 + rr * 8;
                    float v0 = acc[i][t][rr * 2 + 0];
                    float v1 = acc[i][t][rr * 2 + 1];
                    if (d >= DN) {
                        const int fi = (d - DN) >> 1;
                        const float f = (float)(row & (S_ - 1)) * g_freq[fi];
                        float sn, cs;
                        sincosf(f, &sn, &cs);
                        const float e = v0, o = v1;
                        v0 = e * cs - o * sn;
                        v1 = e * sn + o * cs;
                    }
                    __nv_bfloat162 hi, lo;
                    hl_split2(v0, v1, hi, lo);
                    *(__nv_bfloat162*)(Chi + (size_t)row * ldc + col) = hi;
                    *(__nv_bfloat162*)(Clo + (size_t)row * ldc + col) = lo;
                }
            }
        }
    }
}

// ---------------------------------------------------------------------------
// freq init / RoPE(K)
// ---------------------------------------------------------------------------
__global__ void freq_init_kernel()
{
    if (threadIdx.x < 32)
        g_freq[threadIdx.x] = (float)pow(10000.0, -(double)threadIdx.x / 32.0);
}

__global__ void rope_k_kernel(float* __restrict__ kv)
{
    const int idx = blockIdx.x * blockDim.x + threadIdx.x;
    const int i   = idx & 31;
    const int row = idx >> 5;
    const int s   = row & (S_ - 1);
    float* p = kv + (size_t)row * (KVL + DR) + KVL + 2 * i;
    const float f = (float)s * g_freq[i];
    float sn, c;
    sincosf(f, &sn, &c);
    const float e = p[0], o = p[1];
    p[0] = e * c - o * sn;
    p[1] = e * sn + o * c;
}

// ---------------------------------------------------------------------------
// Flash prep: K assembly + V transpose (hi/lo)
// ---------------------------------------------------------------------------
__global__ void convk_kernel(const float* __restrict__ kvx, const float* __restrict__ kv,
                             __nv_bfloat16* __restrict__ kh, __nv_bfloat16* __restrict__ kl)
{
    const int idx = blockIdx.x * blockDim.x + threadIdx.x;
    if (idx >= BS * NH_ * 48) return;
    const int dg  = idx % 48;
    const int h   = (idx / 48) & (NH_ - 1);
    const int row = idx / (48 * NH_);
    float4 v;
    if (dg < 32) v = *(const float4*)(kvx + (size_t)row * (NH_ * 256) + h * 256 + dg * 4);
    else         v = *(const float4*)(kv + (size_t)row * (KVL + DR) + KVL + (dg - 32) * 4);
    __nv_bfloat162 hiA, loA, hiB, loB;
    hl_split2(v.x, v.y, hiA, loA);
    hl_split2(v.z, v.w, hiB, loB);
    const size_t o = ((size_t)row * NH_ + h) * 192 + dg * 4;
    *(__nv_bfloat162*)(kh + o + 0) = hiA;
    *(__nv_bfloat162*)(kh + o + 2) = hiB;
    *(__nv_bfloat162*)(kl + o + 0) = loA;
    *(__nv_bfloat162*)(kl + o + 2) = loB;
}

__global__ void convvt_kernel(const float* __restrict__ kvx,
                              __nv_bfloat16* __restrict__ vth, __nv_bfloat16* __restrict__ vtl)
{
    __shared__ float tile[32][33];
    const int bh = blockIdx.z;
    const int b = bh >> 4, h = bh & 15;
    const int s0 = blockIdx.x * 32, dv0 = blockIdx.y * 32;
    const int tx = threadIdx.x, ty = threadIdx.y;
    #pragma unroll
    for (int j = 0; j < 4; j++) {
        const int s = s0 + ty + 8 * j;
        tile[ty + 8 * j][tx] =
            kvx[(size_t)(b * S_ + s) * (NH_ * 256) + h * 256 + DN + dv0 + tx];
    }
    __syncthreads();
    #pragma unroll
    for (int j = 0; j < 4; j++) {
        const int dv = dv0 + ty + 8 * j;
        const float v = tile[tx][ty + 8 * j];
        const __nv_bfloat16 hi = __float2bfloat16(v);
        const __nv_bfloat16 lo = __float2bfloat16(v - __bfloat162float(hi));
        const size_t o = ((size_t)bh * DV + dv) * S_ + s0 + tx;
        vth[o] = hi; vtl[o] = lo;
    }
}

// ---------------------------------------------------------------------------
// Flash attention on HMMA (unchanged from R9)
// ---------------------------------------------------------------------------
__global__ __launch_bounds__(256, 1)
void flash_mma_kernel(const __nv_bfloat16* __restrict__ qh, const __nv_bfloat16* __restrict__ ql,
                      const __nv_bfloat16* __restrict__ kh, const __nv_bfloat16* __restrict__ kl,
                      const __nv_bfloat16* __restrict__ vth, const __nv_bfloat16* __restrict__ vtl,
                      __nv_bfloat16* __restrict__ ohi, __nv_bfloat16* __restrict__ olo)
{
    extern __shared__ __align__(128) char sm[];
    const uint32_t sb = smem_u32(sm);
    const int tid = threadIdx.x, warp = tid >> 5, lane = tid & 31;
    const int h = blockIdx.y, b = blockIdx.z;
    const int q0 = blockIdx.x * 128;
    const int wr = warp * 16;

    auto load_k = [&](int kt) {
        for (int u = tid; u < 64 * 24; u += 256) {
            const int r = u / 24, c = u % 24;
            const size_t off = ((size_t)(b * S_ + kt + r) * NH_ + h) * 192 + c * 8;
            cp_async16(sb + SM_KH + r * 400 + c * 16, kh + off);
            cp_async16(sb + SM_KL + r * 400 + c * 16, kl + off);
        }
    };
    auto load_v = [&](int kt) {
        for (int u = tid; u < 128 * 8; u += 256) {
            const int dv = u / 8, ck = u % 8;
            const size_t off = ((size_t)(b * NH_ + h) * DV + dv) * S_ + kt + ck * 8;
            cp_async16(sb + SM_VH + dv * 144 + ck * 16, vth + off);
            cp_async16(sb + SM_VL + dv * 144 + ck * 16, vtl + off);
        }
    };

    for (int u = tid; u < 128 * 24; u += 256) {
        const int r = u / 24, c = u % 24;
        const size_t off = ((size_t)(b * S_ + q0 + r) * NH_ + h) * 192 + c * 8;
        cp_async16(sb + SM_QH + r * 400 + c * 16, qh + off);
        cp_async16(sb + SM_QL + r * 400 + c * 16, ql + off);
    }
    load_k(0);
    CP_COMMIT();
    load_v(0);
    CP_COMMIT();

    float oacc[16][4];
    #pragma unroll
    for (int i = 0; i < 16; i++)
        #pragma unroll
        for (int j = 0; j < 4; j++) oacc[i][j] = 0.f;
    float m0 = -1e30f, m1 = -1e30f, l0 = 0.f, l1 = 0.f;

    const uint32_t aQoff = (uint32_t)(wr + (lane & 15)) * 400 + ((lane >> 4) << 4);
    const int rB8  = (lane & 7) + ((lane >> 4) << 3);
    const uint32_t bKoff = (uint32_t)rB8 * 400 + (((lane >> 3) & 1) << 4);
    const uint32_t bVoff = (uint32_t)rB8 * 144 + (((lane >> 3) & 1) << 4);

    for (int kt = 0; kt < S_; kt += 64) {
        const bool has_next = (kt + 64 < S_);
        CP_WAIT1();
        __syncthreads();

        float sacc[8][4];
        #pragma unroll
        for (int i = 0; i < 8; i++)
            #pragma unroll
            for (int j = 0; j < 4; j++) sacc[i][j] = 0.f;

        #pragma unroll
        for (int seg = 0; seg < 3; seg++) {
            const uint32_t qb = sb + (seg == 1 ? SM_QL : SM_QH);
            const uint32_t kb = sb + (seg == 2 ? SM_KL : SM_KH);
            #pragma unroll
            for (int ks = 0; ks < 12; ks++) {
                uint32_t a[4];
                ldsm_x4(a[0], a[1], a[2], a[3], qb + aQoff + ks * 32);
                #pragma unroll
                for (int g = 0; g < 4; g++) {
                    uint32_t r0, r1, r2, r3;
                    ldsm_x4(r0, r1, r2, r3, kb + bKoff + (uint32_t)g * 16 * 400 + ks * 32);
                    uint32_t b0[2] = {r0, r1}, b1[2] = {r2, r3};
                    mma_bf16(sacc[2 * g], a, b0);
                    mma_bf16(sacc[2 * g + 1], a, b1);
                }
            }
        }

        __syncthreads();
        if (has_next) load_k(kt + 64);
        CP_COMMIT();

        float mx0 = -1e30f, mx1 = -1e30f;
        #pragma unroll
        for (int nt = 0; nt < 8; nt++) {
            #pragma unroll
            for (int j = 0; j < 4; j++) sacc[nt][j] *= SCALE;
            mx0 = fmaxf(mx0, fmaxf(sacc[nt][0], sacc[nt][1]));
            mx1 = fmaxf(mx1, fmaxf(sacc[nt][2], sacc[nt][3]));
        }
        mx0 = fmaxf(mx0, __shfl_xor_sync(0xffffffffu, mx0, 1));
        mx0 = fmaxf(mx0, __shfl_xor_sync(0xffffffffu, mx0, 2));
        mx1 = fmaxf(mx1, __shfl_xor_sync(0xffffffffu, mx1, 1));
        mx1 = fmaxf(mx1, __shfl_xor_sync(0xffffffffu, mx1, 2));
        const float mn0 = fmaxf(m0, mx0), mn1 = fmaxf(m1, mx1);
        const float al0 = __expf(m0 - mn0), al1 = __expf(m1 - mn1);
        float rs0 = 0.f, rs1 = 0.f;
        #pragma unroll
        for (int nt = 0; nt < 8; nt++) {
            sacc[nt][0] = __expf(sacc[nt][0] - mn0);
            sacc[nt][1] = __expf(sacc[nt][1] - mn0);
            sacc[nt][2] = __expf(sacc[nt][2] - mn1);
            sacc[nt][3] = __expf(sacc[nt][3] - mn1);
            rs0 += sacc[nt][0] + sacc[nt][1];
            rs1 += sacc[nt][2] + sacc[nt][3];
        }
        rs0 += __shfl_xor_sync(0xffffffffu, rs0, 1);
        rs0 += __shfl_xor_sync(0xffffffffu, rs0, 2);
        rs1 += __shfl_xor_sync(0xffffffffu, rs1, 1);
        rs1 += __shfl_xor_sync(0xffffffffu, rs1, 2);
        l0 = l0 * al0 + rs0; m0 = mn0;
        l1 = l1 * al1 + rs1; m1 = mn1;
        #pragma unroll
        for (int nt = 0; nt < 16; nt++) {
            oacc[nt][0] *= al0; oacc[nt][1] *= al0;
            oacc[nt][2] *= al1; oacc[nt][3] *= al1;
        }

        if (has_next) { CP_WAIT1(); } else { CP_WAIT0(); }
        __syncthreads();

        #pragma unroll
        for (int kk = 0; kk < 4; kk++) {
            uint32_t ah[4], alr[4];
            {
                const float* p0 = sacc[2 * kk];
                const float* p1 = sacc[2 * kk + 1];
                float h00 = __bfloat162float(__float2bfloat16(p0[0]));
                float h01 = __bfloat162float(__float2bfloat16(p0[1]));
                float h02 = __bfloat162float(__float2bfloat16(p0[2]));
                float h03 = __bfloat162float(__float2bfloat16(p0[3]));
                float h10 = __bfloat162float(__float2bfloat16(p1[0]));
                float h11 = __bfloat162float(__float2bfloat16(p1[1]));
                float h12 = __bfloat162float(__float2bfloat16(p1[2]));
                float h13 = __bfloat162float(__float2bfloat16(p1[3]));
                ah[0] = pack_bf2(p0[0], p0[1]);
                ah[1] = pack_bf2(p0[2], p0[3]);
                ah[2] = pack_bf2(p1[0], p1[1]);
                ah[3] = pack_bf2(p1[2], p1[3]);
                alr[0] = pack_bf2(p0[0] - h00, p0[1] - h01);
                alr[1] = pack_bf2(p0[2] - h02, p0[3] - h03);
                alr[2] = pack_bf2(p1[0] - h10, p1[1] - h11);
                alr[3] = pack_bf2(p1[2] - h12, p1[3] - h13);
            }
            #pragma unroll
            for (int half = 0; half < 2; half++) {
                uint32_t bv[8][2];
                #pragma unroll
                for (int g = 0; g < 4; g++) {
                    uint32_t r0, r1, r2, r3;
                    ldsm_x4(r0, r1, r2, r3,
                            sb + SM_VH + bVoff + (uint32_t)(half * 64 + g * 16) * 144 + kk * 32);
                    bv[2 * g][0] = r0; bv[2 * g][1] = r1;
                    bv[2 * g + 1][0] = r2; bv[2 * g + 1][1] = r3;
                }
                #pragma unroll
                for (int t = 0; t < 8; t++) {
                    mma_bf16(oacc[half * 8 + t], ah, bv[t]);
                    mma_bf16(oacc[half * 8 + t], alr, bv[t]);
                }
                #pragma unroll
                for (int g = 0; g < 4; g++) {
                    uint32_t r0, r1, r2, r3;
                    ldsm_x4(r0, r1, r2, r3,
                            sb + SM_VL + bVoff + (uint32_t)(half * 64 + g * 16) * 144 + kk * 32);
                    bv[2 * g][0] = r0; bv[2 * g][1] = r1;
                    bv[2 * g + 1][0] = r2; bv[2 * g + 1][1] = r3;
                }
                #pragma unroll
                for (int t = 0; t < 8; t++)
                    mma_bf16(oacc[half * 8 + t], ah, bv[t]);
            }
        }

        __syncthreads();
        if (has_next) load_v(kt + 64);
        CP_COMMIT();
    }

    const float inv0 = 1.f / l0, inv1 = 1.f / l1;
    const int gr = lane >> 2, gc = (lane & 3) * 2;
    const int row0 = b * S_ + q0 + wr + gr;
    #pragma unroll
    for (int nt = 0; nt < 16; nt++) {
        const int col = h * DV + nt * 8 + gc;
        __nv_bfloat162 hi, lo;
        hl_split2(oacc[nt][0] * inv0, oacc[nt][1] * inv0, hi, lo);
        *(__nv_bfloat162*)(ohi + (size_t)row0 * (NH_ * DV) + col) = hi;
        *(__nv_bfloat162*)(olo + (size_t)row0 * (NH_ * DV) + col) = lo;
        hl_split2(oacc[nt][2] * inv1, oacc[nt][3] * inv1, hi, lo);
        *(__nv_bfloat162*)(ohi + (size_t)(row0 + 8) * (NH_ * DV) + col) = hi;
        *(__nv_bfloat162*)(olo + (size_t)(row0 + 8) * (NH_ * DV) + col) = lo;
    }
}

// ---------------------------------------------------------------------------
// Launcher
// ---------------------------------------------------------------------------
static inline void run_conv(const float* in, __nv_bfloat16* hi, __nv_bfloat16* lo,
                            int R, int Rpad, int Kin, int ldin)
{
    const int total = Rpad * (Kin / 4);
    conv_hl_kernel<<<(total + 255) / 256, 256>>>(in, hi, lo, R, Rpad, Kin, ldin);
}

extern "C" void kernel_launch(void* const* d_in, const int* in_sizes, int n_in,
                              void* d_out, int out_size)
{
    const float* hs    = (const float*)d_in[0];
    const float* wq_a  = (const float*)d_in[1];
    const float* qnw   = (const float*)d_in[2];
    const float* wq_b  = (const float*)d_in[3];
    const float* wkv_a = (const float*)d_in[4];
    const float* kvnw  = (const float*)d_in[5];
    const float* wkv_b = (const float*)d_in[6];
    const float* wo    = (const float*)d_in[7];
    float* out = (float*)d_out;

    void* p;
    cudaGetSymbolAddress(&p, g_qlora); float* qlora = (float*)p;
    cudaGetSymbolAddress(&p, g_kv);    float* kvbuf = (float*)p;
    cudaGetSymbolAddress(&p, g_kvx);   float* kvx   = (float*)p;
    cudaGetSymbolAddress(&p, g_a3);    __nv_bfloat16* a3 = (__nv_bfloat16*)p;
    cudaGetSymbolAddress(&p, g_b3);    __nv_bfloat16* b3 = (__nv_bfloat16*)p;
    cudaGetSymbolAddress(&p, g_qh);    __nv_bfloat16* qh = (__nv_bfloat16*)p;
    cudaGetSymbolAddress(&p, g_ql2);   __nv_bfloat16* ql = (__nv_bfloat16*)p;
    cudaGetSymbolAddress(&p, g_kh);    __nv_bfloat16* kh = (__nv_bfloat16*)p;
    cudaGetSymbolAddress(&p, g_kl);    __nv_bfloat16* kl = (__nv_bfloat16*)p;
    cudaGetSymbolAddress(&p, g_vth);   __nv_bfloat16* vth = (__nv_bfloat16*)p;
    cudaGetSymbolAddress(&p, g_vtl);   __nv_bfloat16* vtl = (__nv_bfloat16*)p;

    cudaFuncSetAttribute(flash_mma_kernel, cudaFuncAttributeMaxDynamicSharedMemorySize,
                         FLASH_SMEM);

    freq_init_kernel<<<1, 32>>>();

    // 1) q_lora = hs @ wq_a^T        [4096, 1536], K=2048
    run_conv(hs, a3, a3 + (size_t)BS * H_, BS, BS, H_, H_);
    run_conv(wq_a, b3, b3 + (size_t)QL * H_, QL, QL, H_, H_);
    gemm_bf16_kernel<<<dim3(QL / 64, BS / 128), 128>>>(
        a3, b3, (size_t)BS * H_, (size_t)QL * H_, qlora, nullptr, nullptr, QL, H_, QL, 0);

    // 2) kv = hs @ wkv_a^T           [4096, 576] (Npad 640), same A
    run_conv(wkv_a, b3, b3 + (size_t)640 * H_, KVL + DR, 640, H_, H_);
    gemm_bf16_kernel<<<dim3(640 / 64, BS / 128), 128>>>(
        a3, b3, (size_t)BS * H_, (size_t)640 * H_, kvbuf, nullptr, nullptr,
        KVL + DR, H_, KVL + DR, 0);

    // 3) k rope (in place, pe cols only)
    rope_k_kernel<<<(BS * 32) / 256, 256>>>(kvbuf);

    // 4) q = q_lora @ wq_b^T         [4096, 3072], K=1536 (A via fused rms+split)
    rms_conv_hl_kernel<<<BS, 256>>>(qlora, qnw, a3, a3 + (size_t)BS * QL, QL, QL);
    run_conv(wq_b, b3, b3 + (size_t)3072 * QL, NH_ * DQK, NH_ * DQK, QL, QL);
    gemm_bf16_kernel<<<dim3((NH_ * DQK) / 64, BS / 128), 128>>>(
        a3, b3, (size_t)BS * QL, (size_t)3072 * QL, nullptr, qh, ql,
        NH_ * DQK, QL, NH_ * DQK, 1);

    // 5) kv_x = kv_c @ wkv_b^T       [4096, 4096], K=512 (A via fused rms+split)
    rms_conv_hl_kernel<<<BS, 256>>>(kvbuf, kvnw, a3, a3 + (size_t)BS * KVL, KVL, KVL + DR);
    run_conv(wkv_b, b3, b3 + (size_t)4096 * KVL, NH_ * (DN + DV), NH_ * (DN + DV), KVL, KVL);
    gemm_bf16_kernel<<<dim3((NH_ * (DN + DV)) / 64, BS / 128), 128>>>(
        a3, b3, (size_t)BS * KVL, (size_t)4096 * KVL, kvx, nullptr, nullptr,
        NH_ * (DN + DV), KVL, NH_ * (DN + DV), 0);

    // 6) flash prep: K assembly + V transpose (hi/lo)
    convk_kernel<<<(BS * NH_ * 48 + 255) / 256, 256>>>(kvx, kvbuf, kh, kl);
    convvt_kernel<<<dim3(S_ / 32, DV / 32, B_ * NH_), dim3(32, 8)>>>(kvx, vth, vtl);

    // 7) flash attention -> a3 hi/lo directly (split-2 A for final GEMM)
    flash_mma_kernel<<<dim3(S_ / 128, NH_, B_), 256, FLASH_SMEM>>>(
        qh, ql, kh, kl, vth, vtl, a3, a3 + (size_t)BS * (NH_ * DV));

    // 8) out = attn @ wo^T           [4096, 2048], K=2048
    run_conv(wo, b3, b3 + (size_t)H_ * (NH_ * DV), H_, H_, NH_ * DV, NH_ * DV);
    gemm_bf16_kernel<<<dim3(H_ / 64, BS / 128), 128>>>(
        a3, b3, (size_t)BS * (NH_ * DV), (size_t)H_ * (NH_ * DV), out, nullptr, nullptr,
        H_, NH_ * DV, H_, 0);
}

// round 11
// speedup vs baseline: 4.1632x; 1.1359x over previous
#include <cuda_runtime.h>
#include <cuda_bf16.h>
#include <math.h>
#include <stdint.h>

// ---------------------------------------------------------------------------
// Problem constants (MLA prefill)
// ---------------------------------------------------------------------------
namespace {
constexpr int B_   = 2;
constexpr int S_   = 2048;
constexpr int H_   = 2048;
constexpr int NH_  = 16;
constexpr int QL   = 1536;
constexpr int KVL  = 512;
constexpr int DN   = 128;
constexpr int DR   = 64;
constexpr int DV   = 128;
constexpr int DQK  = 192;
constexpr int BS   = B_ * S_;
constexpr float SCALE = 0.07216878364870322f; // 1/sqrt(192)

constexpr int SM_QH  = 0;
constexpr int SM_QL  = SM_QH + 128 * 400;
constexpr int SM_KH  = SM_QL + 128 * 400;
constexpr int SM_KL  = SM_KH + 64 * 400;
constexpr int SM_VH  = SM_KL + 64 * 400;
constexpr int SM_VL  = SM_VH + 128 * 144;
constexpr int FLASH_SMEM = SM_VL + 128 * 144; // 190,464 B
} // namespace

// ---------------------------------------------------------------------------
// Scratch (static device globals; no runtime allocation allowed)
// ---------------------------------------------------------------------------
__device__ float g_qlora[(size_t)BS * QL];
__device__ float g_kv[(size_t)BS * (KVL + DR)];
__device__ float g_kvx[(size_t)BS * NH_ * (DN + DV)];
__device__ __nv_bfloat16 g_a3[(size_t)BS * 6144];    // activations [hi | lo]
__device__ __nv_bfloat16 g_b3[(size_t)3072 * 4608];  // weights     [hi | lo]
__device__ __nv_bfloat16 g_qh[(size_t)BS * NH_ * DQK];
__device__ __nv_bfloat16 g_ql2[(size_t)BS * NH_ * DQK];
__device__ __nv_bfloat16 g_kh[(size_t)BS * NH_ * DQK];
__device__ __nv_bfloat16 g_kl[(size_t)BS * NH_ * DQK];
__device__ __nv_bfloat16 g_vth[(size_t)B_ * NH_ * DV * S_];  // [b][h][dv][s]
__device__ __nv_bfloat16 g_vtl[(size_t)B_ * NH_ * DV * S_];
__device__ float g_freq[32];

// ---------------------------------------------------------------------------
// Helpers
// ---------------------------------------------------------------------------
__device__ __forceinline__ uint32_t smem_u32(const void* p) {
    uint32_t a;
    asm("{ .reg .u64 t; cvta.to.shared.u64 t, %1; cvt.u32.u64 %0, t; }" : "=r"(a) : "l"(p));
    return a;
}
__device__ __forceinline__ void cp_async16(uint32_t dst, const void* src) {
    asm volatile("cp.async.cg.shared.global [%0], [%1], 16;" :: "r"(dst), "l"(src) : "memory");
}
#define CP_COMMIT() asm volatile("cp.async.commit_group;" ::: "memory")
#define CP_WAIT2()  asm volatile("cp.async.wait_group 2;" ::: "memory")
#define CP_WAIT1()  asm volatile("cp.async.wait_group 1;" ::: "memory")
#define CP_WAIT0()  asm volatile("cp.async.wait_group 0;" ::: "memory")

__device__ __forceinline__ void ldsm_x4(uint32_t& r0, uint32_t& r1, uint32_t& r2, uint32_t& r3,
                                        uint32_t addr) {
    asm volatile("ldmatrix.sync.aligned.m8n8.x4.shared.b16 {%0,%1,%2,%3}, [%4];"
                 : "=r"(r0), "=r"(r1), "=r"(r2), "=r"(r3) : "r"(addr));
}
__device__ __forceinline__ void mma_bf16(float* c, const uint32_t* a, const uint32_t* b) {
    asm volatile("mma.sync.aligned.m16n8k16.row.col.f32.bf16.bf16.f32 "
                 "{%0,%1,%2,%3}, {%4,%5,%6,%7}, {%8,%9}, {%0,%1,%2,%3};"
                 : "+f"(c[0]), "+f"(c[1]), "+f"(c[2]), "+f"(c[3])
                 : "r"(a[0]), "r"(a[1]), "r"(a[2]), "r"(a[3]), "r"(b[0]), "r"(b[1]));
}
__device__ __forceinline__ uint32_t swoff(int r, int c) {
    return (uint32_t)(r * 64 + ((c ^ ((r >> 1) & 3)) << 4));
}
__device__ __forceinline__ uint32_t pack_bf2(float x, float y) {
    __nv_bfloat162 t(__float2bfloat16(x), __float2bfloat16(y));
    return *(uint32_t*)&t;
}
__device__ __forceinline__ void hl_split2(float v0, float v1,
                                          __nv_bfloat162& hi, __nv_bfloat162& lo) {
    __nv_bfloat16 h0 = __float2bfloat16(v0), h1 = __float2bfloat16(v1);
    hi = __nv_bfloat162(h0, h1);
    lo = __nv_bfloat162(__float2bfloat16(v0 - __bfloat162float(h0)),
                        __float2bfloat16(v1 - __bfloat162float(h1)));
}

// ---------------------------------------------------------------------------
// hi/lo split conversion (plain)
// ---------------------------------------------------------------------------
__global__ void conv_hl_kernel(const float* __restrict__ in,
                               __nv_bfloat16* __restrict__ hi_o,
                               __nv_bfloat16* __restrict__ lo_o,
                               int R, int Rpad, int Kin, int ldin)
{
    const int kq = Kin >> 2;
    const int idx = blockIdx.x * blockDim.x + threadIdx.x;
    if (idx >= Rpad * kq) return;
    const int row = idx / kq, cg = idx - row * kq;
    float4 v = make_float4(0.f, 0.f, 0.f, 0.f);
    if (row < R) v = *(const float4*)(in + (size_t)row * ldin + cg * 4);
    __nv_bfloat162 hiA, loA, hiB, loB;
    hl_split2(v.x, v.y, hiA, loA);
    hl_split2(v.z, v.w, hiB, loB);
    const size_t o = (size_t)row * Kin + cg * 4;
    *(__nv_bfloat162*)(hi_o + o + 0) = hiA;
    *(__nv_bfloat162*)(hi_o + o + 2) = hiB;
    *(__nv_bfloat162*)(lo_o + o + 0) = loA;
    *(__nv_bfloat162*)(lo_o + o + 2) = loB;
}

// ---------------------------------------------------------------------------
// Fused RMSNorm + hi/lo split
// ---------------------------------------------------------------------------
__global__ __launch_bounds__(256)
void rms_conv_hl_kernel(const float* __restrict__ x, const float* __restrict__ w,
                        __nv_bfloat16* __restrict__ hi_o, __nv_bfloat16* __restrict__ lo_o,
                        int n, int ld)
{
    const int row = blockIdx.x;
    const float* p = x + (size_t)row * ld;
    float ss = 0.f;
    for (int i = threadIdx.x; i < n; i += 256) { float v = p[i]; ss = fmaf(v, v, ss); }
    __shared__ float red[8];
    #pragma unroll
    for (int o = 16; o > 0; o >>= 1) ss += __shfl_xor_sync(0xffffffffu, ss, o);
    if ((threadIdx.x & 31) == 0) red[threadIdx.x >> 5] = ss;
    __syncthreads();
    __shared__ float s_inv;
    if (threadIdx.x == 0) {
        float t = 0.f;
        #pragma unroll
        for (int i = 0; i < 8; i++) t += red[i];
        s_inv = rsqrtf(t / (float)n + 1e-6f);
    }
    __syncthreads();
    const float inv = s_inv;
    for (int i = threadIdx.x * 2; i < n; i += 512) {
        const float v0 = w[i] * p[i] * inv;
        const float v1 = w[i + 1] * p[i + 1] * inv;
        __nv_bfloat162 hi, lo;
        hl_split2(v0, v1, hi, lo);
        *(__nv_bfloat162*)(hi_o + (size_t)row * n + i) = hi;
        *(__nv_bfloat162*)(lo_o + (size_t)row * n + i) = lo;
    }
}

// ---------------------------------------------------------------------------
// HMMA bf16 GEMM, split-2 operands; incremental-pointer loader (unchanged R10)
// ---------------------------------------------------------------------------
__global__ __launch_bounds__(128, 4)
void gemm_bf16_kernel(const __nv_bfloat16* __restrict__ A,
                      const __nv_bfloat16* __restrict__ Bw,
                      size_t aSegOff, size_t bSegOff,
                      float* __restrict__ C,
                      __nv_bfloat16* __restrict__ Chi, __nv_bfloat16* __restrict__ Clo,
                      int N, int K, int ldc, int mode)
{
    __shared__ __nv_bfloat16 smv[4][192 * 32]; // 48 KB
    const int tid = threadIdx.x;
    const int warp = tid >> 5, lane = tid & 31;
    const int m0 = blockIdx.y * 128, n0 = blockIdx.x * 64;
    const int KC = K / 32, NC = 3 * KC;

    const uint32_t sbase = smem_u32(&smv[0][0]);
    constexpr uint32_t STG  = 192u * 32 * 2;
    constexpr uint32_t BOFF = 128u * 32 * 2;

    const int lr0 = tid >> 2, lc0 = tid & 3;
    const uint32_t so0 = swoff(lr0, lc0);

    const __nv_bfloat16* pA = A  + (size_t)(m0 + lr0) * K + lc0 * 8;
    const __nv_bfloat16* pB = Bw + (size_t)(n0 + lr0) * K + lc0 * 8;
    int nextKc = 0;
    const size_t aRow = (size_t)32 * K, bRow = (size_t)32 * K;

    auto load_stage = [&](int s) {
        const uint32_t sb = sbase + s * STG;
        cp_async16(sb + so0 + 0 * 2048, pA);
        cp_async16(sb + so0 + 1 * 2048, pA + aRow);
        cp_async16(sb + so0 + 2 * 2048, pA + 2 * aRow);
        cp_async16(sb + so0 + 3 * 2048, pA + 3 * aRow);
        cp_async16(sb + BOFF + so0 + 0 * 2048, pB);
        cp_async16(sb + BOFF + so0 + 1 * 2048, pB + bRow);
        nextKc++;
        pA += 32; pB += 32;
        if (nextKc == KC)          { pA += aSegOff - K; pB -= K; }
        else if (nextKc == 2 * KC) { pA -= aSegOff + K; pB += bSegOff - K; }
    };

    const int wm = (warp >> 1) * 64, wn = (warp & 1) * 32;
    const int rA = wm + (lane & 15), cA = lane >> 4;
    const int swzA = (rA >> 1) & 3;
    const int rB = wn + (lane & 7) + ((lane >> 4) << 3), cB = (lane >> 3) & 1;
    const int swzB = (rB >> 1) & 3;

    float acc[4][4][4];
    #pragma unroll
    for (int i = 0; i < 4; i++)
        #pragma unroll
        for (int j = 0; j < 4; j++)
            #pragma unroll
            for (int k = 0; k < 4; k++) acc[i][j][k] = 0.f;

    load_stage(0); CP_COMMIT();
    load_stage(1); CP_COMMIT();
    load_stage(2); CP_COMMIT();
    CP_WAIT2();
    __syncthreads();

    for (int kc = 0; kc < NC; kc++) {
        if (kc + 3 < NC) load_stage((kc + 3) & 3);
        CP_COMMIT();

        const uint32_t sb = sbase + (kc & 3) * STG;
        #pragma unroll
        for (int h = 0; h < 2; h++) {
            uint32_t a[4][4], b[4][2];
            #pragma unroll
            for (int i = 0; i < 4; i++)
                ldsm_x4(a[i][0], a[i][1], a[i][2], a[i][3],
                        sb + (uint32_t)((rA + 16 * i) * 64 + (((h * 2 + cA) ^ swzA) << 4)));
            #pragma unroll
            for (int j = 0; j < 2; j++) {
                uint32_t r0, r1, r2, r3;
                ldsm_x4(r0, r1, r2, r3,
                        sb + BOFF + (uint32_t)((rB + 16 * j) * 64 + (((h * 2 + cB) ^ swzB) << 4)));
                b[2 * j][0] = r0; b[2 * j][1] = r1;
                b[2 * j + 1][0] = r2; b[2 * j + 1][1] = r3;
            }
            #pragma unroll
            for (int i = 0; i < 4; i++)
                #pragma unroll
                for (int t = 0; t < 4; t++)
                    mma_bf16(acc[i][t], a[i], b[t]);
        }
        CP_WAIT2();
        __syncthreads();
    }

    const int gr = lane >> 2, gc = (lane & 3) * 2;
    if (mode == 0) {
        #pragma unroll
        for (int i = 0; i < 4; i++) {
            const int row0 = m0 + wm + i * 16 + gr;
            #pragma unroll
            for (int t = 0; t < 4; t++) {
                const int col = n0 + wn + t * 8 + gc;
                if (col < N) {
                    *(float2*)(C + (size_t)row0 * ldc + col) =
                        make_float2(acc[i][t][0], acc[i][t][1]);
                    *(float2*)(C + (size_t)(row0 + 8) * ldc + col) =
                        make_float2(acc[i][t][2], acc[i][t][3]);
                }
            }
        }
    } else {
        #pragma unroll
        for (int i = 0; i < 4; i++) {
            const int row0 = m0 + wm + i * 16 + gr;
            #pragma unroll
            for (int t = 0; t < 4; t++) {
                const int col = n0 + wn + t * 8 + gc;
                const int d = col % DQK;
                #pragma unroll
                for (int rr = 0; rr < 2; rr++) {
                    const int row = row0 + rr * 8;
                    float v0 = acc[i][t][rr * 2 + 0];
                    float v1 = acc[i][t][rr * 2 + 1];
                    if (d >= DN) {
                        const int fi = (d - DN) >> 1;
                        const float f = (float)(row & (S_ - 1)) * g_freq[fi];
                        float sn, cs;
                        sincosf(f, &sn, &cs);
                        const float e = v0, o = v1;
                        v0 = e * cs - o * sn;
                        v1 = e * sn + o * cs;
                    }
                    __nv_bfloat162 hi, lo;
                    hl_split2(v0, v1, hi, lo);
                    *(__nv_bfloat162*)(Chi + (size_t)row * ldc + col) = hi;
                    *(__nv_bfloat162*)(Clo + (size_t)row * ldc + col) = lo;
                }
            }
        }
    }
}

// ---------------------------------------------------------------------------
// freq init / RoPE(K)
// ---------------------------------------------------------------------------
__global__ void freq_init_kernel()
{
    if (threadIdx.x < 32)
        g_freq[threadIdx.x] = (float)pow(10000.0, -(double)threadIdx.x / 32.0);
}

__global__ void rope_k_kernel(float* __restrict__ kv)
{
    const int idx = blockIdx.x * blockDim.x + threadIdx.x;
    const int i   = idx & 31;
    const int row = idx >> 5;
    const int s   = row & (S_ - 1);
    float* p = kv + (size_t)row * (KVL + DR) + KVL + 2 * i;
    const float f = (float)s * g_freq[i];
    float sn, c;
    sincosf(f, &sn, &c);
    const float e = p[0], o = p[1];
    p[0] = e * c - o * sn;
    p[1] = e * sn + o * c;
}

// ---------------------------------------------------------------------------
// Flash prep: K assembly + V transpose (hi/lo)
// ---------------------------------------------------------------------------
__global__ void convk_kernel(const float* __restrict__ kvx, const float* __restrict__ kv,
                             __nv_bfloat16* __restrict__ kh, __nv_bfloat16* __restrict__ kl)
{
    const int idx = blockIdx.x * blockDim.x + threadIdx.x;
    if (idx >= BS * NH_ * 48) return;
    const int dg  = idx % 48;
    const int h   = (idx / 48) & (NH_ - 1);
    const int row = idx / (48 * NH_);
    float4 v;
    if (dg < 32) v = *(const float4*)(kvx + (size_t)row * (NH_ * 256) + h * 256 + dg * 4);
    else         v = *(const float4*)(kv + (size_t)row * (KVL + DR) + KVL + (dg - 32) * 4);
    __nv_bfloat162 hiA, loA, hiB, loB;
    hl_split2(v.x, v.y, hiA, loA);
    hl_split2(v.z, v.w, hiB, loB);
    const size_t o = ((size_t)row * NH_ + h) * 192 + dg * 4;
    *(__nv_bfloat162*)(kh + o + 0) = hiA;
    *(__nv_bfloat162*)(kh + o + 2) = hiB;
    *(__nv_bfloat162*)(kl + o + 0) = loA;
    *(__nv_bfloat162*)(kl + o + 2) = loB;
}

__global__ void convvt_kernel(const float* __restrict__ kvx,
                              __nv_bfloat16* __restrict__ vth, __nv_bfloat16* __restrict__ vtl)
{
    __shared__ float tile[32][33];
    const int bh = blockIdx.z;
    const int b = bh >> 4, h = bh & 15;
    const int s0 = blockIdx.x * 32, dv0 = blockIdx.y * 32;
    const int tx = threadIdx.x, ty = threadIdx.y;
    #pragma unroll
    for (int j = 0; j < 4; j++) {
        const int s = s0 + ty + 8 * j;
        tile[ty + 8 * j][tx] =
            kvx[(size_t)(b * S_ + s) * (NH_ * 256) + h * 256 + DN + dv0 + tx];
    }
    __syncthreads();
    #pragma unroll
    for (int j = 0; j < 4; j++) {
        const int dv = dv0 + ty + 8 * j;
        const float v = tile[tx][ty + 8 * j];
        const __nv_bfloat16 hi = __float2bfloat16(v);
        const __nv_bfloat16 lo = __float2bfloat16(v - __bfloat162float(hi));
        const size_t o = ((size_t)bh * DV + dv) * S_ + s0 + tx;
        vth[o] = hi; vtl[o] = lo;
    }
}

// ---------------------------------------------------------------------------
// Flash attention on HMMA. QK phase restructured: per k-slice, Qh/Ql a-frags
// and Kh/Kl b-frags each loaded ONCE and reused across the 3 split passes
// (ldsm per warp-tile: 180 -> 120). MMA set identical to R10.
// ---------------------------------------------------------------------------
__global__ __launch_bounds__(256, 1)
void flash_mma_kernel(const __nv_bfloat16* __restrict__ qh, const __nv_bfloat16* __restrict__ ql,
                      const __nv_bfloat16* __restrict__ kh, const __nv_bfloat16* __restrict__ kl,
                      const __nv_bfloat16* __restrict__ vth, const __nv_bfloat16* __restrict__ vtl,
                      __nv_bfloat16* __restrict__ ohi, __nv_bfloat16* __restrict__ olo)
{
    extern __shared__ __align__(128) char sm[];
    const uint32_t sb = smem_u32(sm);
    const int tid = threadIdx.x, warp = tid >> 5, lane = tid & 31;
    const int h = blockIdx.y, b = blockIdx.z;
    const int q0 = blockIdx.x * 128;
    const int wr = warp * 16;

    auto load_k = [&](int kt) {
        for (int u = tid; u < 64 * 24; u += 256) {
            const int r = u / 24, c = u % 24;
            const size_t off = ((size_t)(b * S_ + kt + r) * NH_ + h) * 192 + c * 8;
            cp_async16(sb + SM_KH + r * 400 + c * 16, kh + off);
            cp_async16(sb + SM_KL + r * 400 + c * 16, kl + off);
        }
    };
    auto load_v = [&](int kt) {
        for (int u = tid; u < 128 * 8; u += 256) {
            const int dv = u / 8, ck = u % 8;
            const size_t off = ((size_t)(b * NH_ + h) * DV + dv) * S_ + kt + ck * 8;
            cp_async16(sb + SM_VH + dv * 144 + ck * 16, vth + off);
            cp_async16(sb + SM_VL + dv * 144 + ck * 16, vtl + off);
        }
    };

    for (int u = tid; u < 128 * 24; u += 256) {
        const int r = u / 24, c = u % 24;
        const size_t off = ((size_t)(b * S_ + q0 + r) * NH_ + h) * 192 + c * 8;
        cp_async16(sb + SM_QH + r * 400 + c * 16, qh + off);
        cp_async16(sb + SM_QL + r * 400 + c * 16, ql + off);
    }
    load_k(0);
    CP_COMMIT();
    load_v(0);
    CP_COMMIT();

    float oacc[16][4];
    #pragma unroll
    for (int i = 0; i < 16; i++)
        #pragma unroll
        for (int j = 0; j < 4; j++) oacc[i][j] = 0.f;
    float m0 = -1e30f, m1 = -1e30f, l0 = 0.f, l1 = 0.f;

    const uint32_t aQoff = (uint32_t)(wr + (lane & 15)) * 400 + ((lane >> 4) << 4);
    const int rB8  = (lane & 7) + ((lane >> 4) << 3);
    const uint32_t bKoff = (uint32_t)rB8 * 400 + (((lane >> 3) & 1) << 4);
    const uint32_t bVoff = (uint32_t)rB8 * 144 + (((lane >> 3) & 1) << 4);

    for (int kt = 0; kt < S_; kt += 64) {
        const bool has_next = (kt + 64 < S_);
        CP_WAIT1();
        __syncthreads();

        // ---- S = Q K^T: per k-slice, reuse Qh across (Kh,Kl) and Kh across (Qh,Ql)
        float sacc[8][4];
        #pragma unroll
        for (int i = 0; i < 8; i++)
            #pragma unroll
            for (int j = 0; j < 4; j++) sacc[i][j] = 0.f;

        #pragma unroll
        for (int ks = 0; ks < 12; ks++) {
            uint32_t ah[4], al[4];
            ldsm_x4(ah[0], ah[1], ah[2], ah[3], sb + SM_QH + aQoff + ks * 32);
            ldsm_x4(al[0], al[1], al[2], al[3], sb + SM_QL + aQoff + ks * 32);
            #pragma unroll
            for (int g = 0; g < 4; g++) {
                uint32_t h0, h1, h2, h3, l0r, l1r, l2r, l3r;
                ldsm_x4(h0, h1, h2, h3,
                        sb + SM_KH + bKoff + (uint32_t)g * 16 * 400 + ks * 32);
                ldsm_x4(l0r, l1r, l2r, l3r,
                        sb + SM_KL + bKoff + (uint32_t)g * 16 * 400 + ks * 32);
                uint32_t bh0[2] = {h0, h1}, bh1[2] = {h2, h3};
                uint32_t bl0[2] = {l0r, l1r}, bl1[2] = {l2r, l3r};
                mma_bf16(sacc[2 * g],     ah, bh0);
                mma_bf16(sacc[2 * g + 1], ah, bh1);
                mma_bf16(sacc[2 * g],     al, bh0);
                mma_bf16(sacc[2 * g + 1], al, bh1);
                mma_bf16(sacc[2 * g],     ah, bl0);
                mma_bf16(sacc[2 * g + 1], ah, bl1);
            }
        }

        __syncthreads();
        if (has_next) load_k(kt + 64);
        CP_COMMIT();

        float mx0 = -1e30f, mx1 = -1e30f;
        #pragma unroll
        for (int nt = 0; nt < 8; nt++) {
            #pragma unroll
            for (int j = 0; j < 4; j++) sacc[nt][j] *= SCALE;
            mx0 = fmaxf(mx0, fmaxf(sacc[nt][0], sacc[nt][1]));
            mx1 = fmaxf(mx1, fmaxf(sacc[nt][2], sacc[nt][3]));
        }
        mx0 = fmaxf(mx0, __shfl_xor_sync(0xffffffffu, mx0, 1));
        mx0 = fmaxf(mx0, __shfl_xor_sync(0xffffffffu, mx0, 2));
        mx1 = fmaxf(mx1, __shfl_xor_sync(0xffffffffu, mx1, 1));
        mx1 = fmaxf(mx1, __shfl_xor_sync(0xffffffffu, mx1, 2));
        const float mn0 = fmaxf(m0, mx0), mn1 = fmaxf(m1, mx1);
        const float al0 = __expf(m0 - mn0), al1 = __expf(m1 - mn1);
        float rs0 = 0.f, rs1 = 0.f;
        #pragma unroll
        for (int nt = 0; nt < 8; nt++) {
            sacc[nt][0] = __expf(sacc[nt][0] - mn0);
            sacc[nt][1] = __expf(sacc[nt][1] - mn0);
            sacc[nt][2] = __expf(sacc[nt][2] - mn1);
            sacc[nt][3] = __expf(sacc[nt][3] - mn1);
            rs0 += sacc[nt][0] + sacc[nt][1];
            rs1 += sacc[nt][2] + sacc[nt][3];
        }
        rs0 += __shfl_xor_sync(0xffffffffu, rs0, 1);
        rs0 += __shfl_xor_sync(0xffffffffu, rs0, 2);
        rs1 += __shfl_xor_sync(0xffffffffu, rs1, 1);
        rs1 += __shfl_xor_sync(0xffffffffu, rs1, 2);
        l0 = l0 * al0 + rs0; m0 = mn0;
        l1 = l1 * al1 + rs1; m1 = mn1;
        #pragma unroll
        for (int nt = 0; nt < 16; nt++) {
            oacc[nt][0] *= al0; oacc[nt][1] *= al0;
            oacc[nt][2] *= al1; oacc[nt][3] *= al1;
        }

        if (has_next) { CP_WAIT1(); } else { CP_WAIT0(); }
        __syncthreads();

        #pragma unroll
        for (int kk = 0; kk < 4; kk++) {
            uint32_t ah[4], alr[4];
            {
                const float* p0 = sacc[2 * kk];
                const float* p1 = sacc[2 * kk + 1];
                float h00 = __bfloat162float(__float2bfloat16(p0[0]));
                float h01 = __bfloat162float(__float2bfloat16(p0[1]));
                float h02 = __bfloat162float(__float2bfloat16(p0[2]));
                float h03 = __bfloat162float(__float2bfloat16(p0[3]));
                float h10 = __bfloat162float(__float2bfloat16(p1[0]));
                float h11 = __bfloat162float(__float2bfloat16(p1[1]));
                float h12 = __bfloat162float(__float2bfloat16(p1[2]));
                float h13 = __bfloat162float(__float2bfloat16(p1[3]));
                ah[0] = pack_bf2(p0[0], p0[1]);
                ah[1] = pack_bf2(p0[2], p0[3]);
                ah[2] = pack_bf2(p1[0], p1[1]);
                ah[3] = pack_bf2(p1[2], p1[3]);
                alr[0] = pack_bf2(p0[0] - h00, p0[1] - h01);
                alr[1] = pack_bf2(p0[2] - h02, p0[3] - h03);
                alr[2] = pack_bf2(p1[0] - h10, p1[1] - h11);
                alr[3] = pack_bf2(p1[2] - h12, p1[3] - h13);
            }
            #pragma unroll
            for (int half = 0; half < 2; half++) {
                uint32_t bv[8][2];
                #pragma unroll
                for (int g = 0; g < 4; g++) {
                    uint32_t r0, r1, r2, r3;
                    ldsm_x4(r0, r1, r2, r3,
                            sb + SM_VH + bVoff + (uint32_t)(half * 64 + g * 16) * 144 + kk * 32);
                    bv[2 * g][0] = r0; bv[2 * g][1] = r1;
                    bv[2 * g + 1][0] = r2; bv[2 * g + 1][1] = r3;
                }
                #pragma unroll
                for (int t = 0; t < 8; t++) {
                    mma_bf16(oacc[half * 8 + t], ah, bv[t]);
                    mma_bf16(oacc[half * 8 + t], alr, bv[t]);
                }
                #pragma unroll
                for (int g = 0; g < 4; g++) {
                    uint32_t r0, r1, r2, r3;
                    ldsm_x4(r0, r1, r2, r3,
                            sb + SM_VL + bVoff + (uint32_t)(half * 64 + g * 16) * 144 + kk * 32);
                    bv[2 * g][0] = r0; bv[2 * g][1] = r1;
                    bv[2 * g + 1][0] = r2; bv[2 * g + 1][1] = r3;
                }
                #pragma unroll
                for (int t = 0; t < 8; t++)
                    mma_bf16(oacc[half * 8 + t], ah, bv[t]);
            }
        }

        __syncthreads();
        if (has_next) load_v(kt + 64);
        CP_COMMIT();
    }

    const float inv0 = 1.f / l0, inv1 = 1.f / l1;
    const int gr = lane >> 2, gc = (lane & 3) * 2;
    const int row0 = b * S_ + q0 + wr + gr;
    #pragma unroll
    for (int nt = 0; nt < 16; nt++) {
        const int col = h * DV + nt * 8 + gc;
        __nv_bfloat162 hi, lo;
        hl_split2(oacc[nt][0] * inv0, oacc[nt][1] * inv0, hi, lo);
        *(__nv_bfloat162*)(ohi + (size_t)row0 * (NH_ * DV) + col) = hi;
        *(__nv_bfloat162*)(olo + (size_t)row0 * (NH_ * DV) + col) = lo;
        hl_split2(oacc[nt][2] * inv1, oacc[nt][3] * inv1, hi, lo);
        *(__nv_bfloat162*)(ohi + (size_t)(row0 + 8) * (NH_ * DV) + col) = hi;
        *(__nv_bfloat162*)(olo + (size_t)(row0 + 8) * (NH_ * DV) + col) = lo;
    }
}

// ---------------------------------------------------------------------------
// Launcher
// ---------------------------------------------------------------------------
static inline void run_conv(const float* in, __nv_bfloat16* hi, __nv_bfloat16* lo,
                            int R, int Rpad, int Kin, int ldin)
{
    const int total = Rpad * (Kin / 4);
    conv_hl_kernel<<<(total + 255) / 256, 256>>>(in, hi, lo, R, Rpad, Kin, ldin);
}

extern "C" void kernel_launch(void* const* d_in, const int* in_sizes, int n_in,
                              void* d_out, int out_size)
{
    const float* hs    = (const float*)d_in[0];
    const float* wq_a  = (const float*)d_in[1];
    const float* qnw   = (const float*)d_in[2];
    const float* wq_b  = (const float*)d_in[3];
    const float* wkv_a = (const float*)d_in[4];
    const float* kvnw  = (const float*)d_in[5];
    const float* wkv_b = (const float*)d_in[6];
    const float* wo    = (const float*)d_in[7];
    float* out = (float*)d_out;

    void* p;
    cudaGetSymbolAddress(&p, g_qlora); float* qlora = (float*)p;
    cudaGetSymbolAddress(&p, g_kv);    float* kvbuf = (float*)p;
    cudaGetSymbolAddress(&p, g_kvx);   float* kvx   = (float*)p;
    cudaGetSymbolAddress(&p, g_a3);    __nv_bfloat16* a3 = (__nv_bfloat16*)p;
    cudaGetSymbolAddress(&p, g_b3);    __nv_bfloat16* b3 = (__nv_bfloat16*)p;
    cudaGetSymbolAddress(&p, g_qh);    __nv_bfloat16* qh = (__nv_bfloat16*)p;
    cudaGetSymbolAddress(&p, g_ql2);   __nv_bfloat16* ql = (__nv_bfloat16*)p;
    cudaGetSymbolAddress(&p, g_kh);    __nv_bfloat16* kh = (__nv_bfloat16*)p;
    cudaGetSymbolAddress(&p, g_kl);    __nv_bfloat16* kl = (__nv_bfloat16*)p;
    cudaGetSymbolAddress(&p, g_vth);   __nv_bfloat16* vth = (__nv_bfloat16*)p;
    cudaGetSymbolAddress(&p, g_vtl);   __nv_bfloat16* vtl = (__nv_bfloat16*)p;

    cudaFuncSetAttribute(flash_mma_kernel, cudaFuncAttributeMaxDynamicSharedMemorySize,
                         FLASH_SMEM);

    freq_init_kernel<<<1, 32>>>();

    // 1) q_lora = hs @ wq_a^T        [4096, 1536], K=2048
    run_conv(hs, a3, a3 + (size_t)BS * H_, BS, BS, H_, H_);
    run_conv(wq_a, b3, b3 + (size_t)QL * H_, QL, QL, H_, H_);
    gemm_bf16_kernel<<<dim3(QL / 64, BS / 128), 128>>>(
        a3, b3, (size_t)BS * H_, (size_t)QL * H_, qlora, nullptr, nullptr, QL, H_, QL, 0);

    // 2) kv = hs @ wkv_a^T           [4096, 576] (Npad 640), same A
    run_conv(wkv_a, b3, b3 + (size_t)640 * H_, KVL + DR, 640, H_, H_);
    gemm_bf16_kernel<<<dim3(640 / 64, BS / 128), 128>>>(
        a3, b3, (size_t)BS * H_, (size_t)640 * H_, kvbuf, nullptr, nullptr,
        KVL + DR, H_, KVL + DR, 0);

    // 3) k rope (in place, pe cols only)
    rope_k_kernel<<<(BS * 32) / 256, 256>>>(kvbuf);

    // 4) q = q_lora @ wq_b^T         [4096, 3072], K=1536 (A via fused rms+split)
    rms_conv_hl_kernel<<<BS, 256>>>(qlora, qnw, a3, a3 + (size_t)BS * QL, QL, QL);
    run_conv(wq_b, b3, b3 + (size_t)3072 * QL, NH_ * DQK, NH_ * DQK, QL, QL);
    gemm_bf16_kernel<<<dim3((NH_ * DQK) / 64, BS / 128), 128>>>(
        a3, b3, (size_t)BS * QL, (size_t)3072 * QL, nullptr, qh, ql,
        NH_ * DQK, QL, NH_ * DQK, 1);

    // 5) kv_x = kv_c @ wkv_b^T       [4096, 4096], K=512 (A via fused rms+split)
    rms_conv_hl_kernel<<<BS, 256>>>(kvbuf, kvnw, a3, a3 + (size_t)BS * KVL, KVL, KVL + DR);
    run_conv(wkv_b, b3, b3 + (size_t)4096 * KVL, NH_ * (DN + DV), NH_ * (DN + DV), KVL, KVL);
    gemm_bf16_kernel<<<dim3((NH_ * (DN + DV)) / 64, BS / 128), 128>>>(
        a3, b3, (size_t)BS * KVL, (size_t)4096 * KVL, kvx, nullptr, nullptr,
        NH_ * (DN + DV), KVL, NH_ * (DN + DV), 0);

    // 6) flash prep: K assembly + V transpose (hi/lo)
    convk_kernel<<<(BS * NH_ * 48 + 255) / 256, 256>>>(kvx, kvbuf, kh, kl);
    convvt_kernel<<<dim3(S_ / 32, DV / 32, B_ * NH_), dim3(32, 8)>>>(kvx, vth, vtl);

    // 7) flash attention -> a3 hi/lo directly (split-2 A for final GEMM)
    flash_mma_kernel<<<dim3(S_ / 128, NH_, B_), 256, FLASH_SMEM>>>(
        qh, ql, kh, kl, vth, vtl, a3, a3 + (size_t)BS * (NH_ * DV));

    // 8) out = attn @ wo^T           [4096, 2048], K=2048
    run_conv(wo, b3, b3 + (size_t)H_ * (NH_ * DV), H_, H_, NH_ * DV, NH_ * DV);
    gemm_bf16_kernel<<<dim3(H_ / 64, BS / 128), 128>>>(
        a3, b3, (size_t)BS * (NH_ * DV), (size_t)H_ * (NH_ * DV), out, nullptr, nullptr,
        H_, NH_ * DV, H_, 0);
}

// round 12
// speedup vs baseline: 4.4254x; 1.0630x over previous
#include <cuda_runtime.h>
#include <cuda_bf16.h>
#include <math.h>
#include <stdint.h>

// ---------------------------------------------------------------------------
// Problem constants (MLA prefill)
// ---------------------------------------------------------------------------
namespace {
constexpr int B_   = 2;
constexpr int S_   = 2048;
constexpr int H_   = 2048;
constexpr int NH_  = 16;
constexpr int QL   = 1536;
constexpr int KVL  = 512;
constexpr int DN   = 128;
constexpr int DR   = 64;
constexpr int DV   = 128;
constexpr int DQK  = 192;
constexpr int BS   = B_ * S_;
constexpr float SCALE = 0.07216878364870322f; // 1/sqrt(192)

constexpr int SM_QH  = 0;
constexpr int SM_QL  = SM_QH + 128 * 400;
constexpr int SM_KH  = SM_QL + 128 * 400;
constexpr int SM_KL  = SM_KH + 64 * 400;
constexpr int SM_VH  = SM_KL + 64 * 400;
constexpr int SM_VL  = SM_VH + 128 * 144;
constexpr int FLASH_SMEM = SM_VL + 128 * 144; // 190,464 B

// GEMM stage layout (bytes within one stage)
constexpr uint32_t G_AH = 0;       // 128 x 64B
constexpr uint32_t G_AL = 8192;    // 128 x 64B
constexpr uint32_t G_BH = 16384;   //  64 x 64B
constexpr uint32_t G_BL = 20480;   //  64 x 64B
constexpr uint32_t G_STG = 24576;  // 24 KB per stage, 2 stages = 48 KB
} // namespace

// ---------------------------------------------------------------------------
// Scratch (static device globals; no runtime allocation allowed)
// ---------------------------------------------------------------------------
__device__ float g_qlora[(size_t)BS * QL];
__device__ float g_kv[(size_t)BS * (KVL + DR)];
__device__ float g_kvx[(size_t)BS * NH_ * (DN + DV)];
__device__ __nv_bfloat16 g_a3[(size_t)BS * 6144];    // activations [hi | lo]
__device__ __nv_bfloat16 g_b3[(size_t)3072 * 4608];  // weights     [hi | lo]
__device__ __nv_bfloat16 g_qh[(size_t)BS * NH_ * DQK];
__device__ __nv_bfloat16 g_ql2[(size_t)BS * NH_ * DQK];
__device__ __nv_bfloat16 g_kh[(size_t)BS * NH_ * DQK];
__device__ __nv_bfloat16 g_kl[(size_t)BS * NH_ * DQK];
__device__ __nv_bfloat16 g_vth[(size_t)B_ * NH_ * DV * S_];  // [b][h][dv][s]
__device__ __nv_bfloat16 g_vtl[(size_t)B_ * NH_ * DV * S_];
__device__ float g_freq[32];

// ---------------------------------------------------------------------------
// Helpers
// ---------------------------------------------------------------------------
__device__ __forceinline__ uint32_t smem_u32(const void* p) {
    uint32_t a;
    asm("{ .reg .u64 t; cvta.to.shared.u64 t, %1; cvt.u32.u64 %0, t; }" : "=r"(a) : "l"(p));
    return a;
}
__device__ __forceinline__ void cp_async16(uint32_t dst, const void* src) {
    asm volatile("cp.async.cg.shared.global [%0], [%1], 16;" :: "r"(dst), "l"(src) : "memory");
}
#define CP_COMMIT() asm volatile("cp.async.commit_group;" ::: "memory")
#define CP_WAIT1()  asm volatile("cp.async.wait_group 1;" ::: "memory")
#define CP_WAIT0()  asm volatile("cp.async.wait_group 0;" ::: "memory")

__device__ __forceinline__ void ldsm_x4(uint32_t& r0, uint32_t& r1, uint32_t& r2, uint32_t& r3,
                                        uint32_t addr) {
    asm volatile("ldmatrix.sync.aligned.m8n8.x4.shared.b16 {%0,%1,%2,%3}, [%4];"
                 : "=r"(r0), "=r"(r1), "=r"(r2), "=r"(r3) : "r"(addr));
}
__device__ __forceinline__ void mma_bf16(float* c, const uint32_t* a, const uint32_t* b) {
    asm volatile("mma.sync.aligned.m16n8k16.row.col.f32.bf16.bf16.f32 "
                 "{%0,%1,%2,%3}, {%4,%5,%6,%7}, {%8,%9}, {%0,%1,%2,%3};"
                 : "+f"(c[0]), "+f"(c[1]), "+f"(c[2]), "+f"(c[3])
                 : "r"(a[0]), "r"(a[1]), "r"(a[2]), "r"(a[3]), "r"(b[0]), "r"(b[1]));
}
__device__ __forceinline__ uint32_t swoff(int r, int c) {
    return (uint32_t)(r * 64 + ((c ^ ((r >> 1) & 3)) << 4));
}
__device__ __forceinline__ uint32_t pack_bf2(float x, float y) {
    __nv_bfloat162 t(__float2bfloat16(x), __float2bfloat16(y));
    return *(uint32_t*)&t;
}
__device__ __forceinline__ void hl_split2(float v0, float v1,
                                          __nv_bfloat162& hi, __nv_bfloat162& lo) {
    __nv_bfloat16 h0 = __float2bfloat16(v0), h1 = __float2bfloat16(v1);
    hi = __nv_bfloat162(h0, h1);
    lo = __nv_bfloat162(__float2bfloat16(v0 - __bfloat162float(h0)),
                        __float2bfloat16(v1 - __bfloat162float(h1)));
}

// ---------------------------------------------------------------------------
// hi/lo split conversion (plain)
// ---------------------------------------------------------------------------
__global__ void conv_hl_kernel(const float* __restrict__ in,
                               __nv_bfloat16* __restrict__ hi_o,
                               __nv_bfloat16* __restrict__ lo_o,
                               int R, int Rpad, int Kin, int ldin)
{
    const int kq = Kin >> 2;
    const int idx = blockIdx.x * blockDim.x + threadIdx.x;
    if (idx >= Rpad * kq) return;
    const int row = idx / kq, cg = idx - row * kq;
    float4 v = make_float4(0.f, 0.f, 0.f, 0.f);
    if (row < R) v = *(const float4*)(in + (size_t)row * ldin + cg * 4);
    __nv_bfloat162 hiA, loA, hiB, loB;
    hl_split2(v.x, v.y, hiA, loA);
    hl_split2(v.z, v.w, hiB, loB);
    const size_t o = (size_t)row * Kin + cg * 4;
    *(__nv_bfloat162*)(hi_o + o + 0) = hiA;
    *(__nv_bfloat162*)(hi_o + o + 2) = hiB;
    *(__nv_bfloat162*)(lo_o + o + 0) = loA;
    *(__nv_bfloat162*)(lo_o + o + 2) = loB;
}

// ---------------------------------------------------------------------------
// Fused RMSNorm + hi/lo split
// ---------------------------------------------------------------------------
__global__ __launch_bounds__(256)
void rms_conv_hl_kernel(const float* __restrict__ x, const float* __restrict__ w,
                        __nv_bfloat16* __restrict__ hi_o, __nv_bfloat16* __restrict__ lo_o,
                        int n, int ld)
{
    const int row = blockIdx.x;
    const float* p = x + (size_t)row * ld;
    float ss = 0.f;
    for (int i = threadIdx.x; i < n; i += 256) { float v = p[i]; ss = fmaf(v, v, ss); }
    __shared__ float red[8];
    #pragma unroll
    for (int o = 16; o > 0; o >>= 1) ss += __shfl_xor_sync(0xffffffffu, ss, o);
    if ((threadIdx.x & 31) == 0) red[threadIdx.x >> 5] = ss;
    __syncthreads();
    __shared__ float s_inv;
    if (threadIdx.x == 0) {
        float t = 0.f;
        #pragma unroll
        for (int i = 0; i < 8; i++) t += red[i];
        s_inv = rsqrtf(t / (float)n + 1e-6f);
    }
    __syncthreads();
    const float inv = s_inv;
    for (int i = threadIdx.x * 2; i < n; i += 512) {
        const float v0 = w[i] * p[i] * inv;
        const float v1 = w[i + 1] * p[i + 1] * inv;
        __nv_bfloat162 hi, lo;
        hl_split2(v0, v1, hi, lo);
        *(__nv_bfloat162*)(hi_o + (size_t)row * n + i) = hi;
        *(__nv_bfloat162*)(lo_o + (size_t)row * n + i) = lo;
    }
}

// ---------------------------------------------------------------------------
// HMMA bf16 GEMM, split-2 operands, FUSED segments:
// per chunk stage {Ah, Al, Bh, Bl}; per fragment pair issue Ah.Bh + Al.Bh + Ah.Bl.
// CTA 128x64x32, 4 warps (2x2), warp tile 64x32, 2-stage cp.async, 4 CTAs/SM.
// mode 0: fp32 C.  mode 1: rope(d>=128) + hi/lo bf16 out.
// ---------------------------------------------------------------------------
__global__ __launch_bounds__(128, 4)
void gemm_bf16_kernel(const __nv_bfloat16* __restrict__ Ah_g,
                      const __nv_bfloat16* __restrict__ Al_g,
                      const __nv_bfloat16* __restrict__ Bh_g,
                      const __nv_bfloat16* __restrict__ Bl_g,
                      float* __restrict__ C,
                      __nv_bfloat16* __restrict__ Chi, __nv_bfloat16* __restrict__ Clo,
                      int N, int K, int ldc, int mode)
{
    __shared__ __nv_bfloat16 smv[2][G_STG / 2]; // 48 KB total
    const int tid = threadIdx.x;
    const int warp = tid >> 5, lane = tid & 31;
    const int m0 = blockIdx.y * 128, n0 = blockIdx.x * 64;
    const int KC = K / 32;

    const uint32_t sbase = smem_u32(&smv[0][0]);

    const int lr0 = tid >> 2, lc0 = tid & 3;   // lr0 in [0,32)
    const uint32_t so0 = swoff(lr0, lc0);

    const __nv_bfloat16* pAh = Ah_g + (size_t)(m0 + lr0) * K + lc0 * 8;
    const __nv_bfloat16* pAl = Al_g + (size_t)(m0 + lr0) * K + lc0 * 8;
    const __nv_bfloat16* pBh = Bh_g + (size_t)(n0 + lr0) * K + lc0 * 8;
    const __nv_bfloat16* pBl = Bl_g + (size_t)(n0 + lr0) * K + lc0 * 8;
    const size_t row32 = (size_t)32 * K;

    auto load_stage = [&](int s) {
        const uint32_t sb = sbase + s * G_STG;
        #pragma unroll
        for (int r = 0; r < 4; r++) {
            cp_async16(sb + G_AH + so0 + r * 2048, pAh + r * row32);
            cp_async16(sb + G_AL + so0 + r * 2048, pAl + r * row32);
        }
        #pragma unroll
        for (int r = 0; r < 2; r++) {
            cp_async16(sb + G_BH + so0 + r * 2048, pBh + r * row32);
            cp_async16(sb + G_BL + so0 + r * 2048, pBl + r * row32);
        }
        pAh += 32; pAl += 32; pBh += 32; pBl += 32;
    };

    const int wm = (warp >> 1) * 64, wn = (warp & 1) * 32;
    const int rA = wm + (lane & 15), cA = lane >> 4;
    const int swzA = (rA >> 1) & 3;
    const int rB = wn + (lane & 7) + ((lane >> 4) << 3), cB = (lane >> 3) & 1;
    const int swzB = (rB >> 1) & 3;

    float acc[4][4][4];
    #pragma unroll
    for (int i = 0; i < 4; i++)
        #pragma unroll
        for (int j = 0; j < 4; j++)
            #pragma unroll
            for (int k = 0; k < 4; k++) acc[i][j][k] = 0.f;

    load_stage(0); CP_COMMIT();
    load_stage(1); CP_COMMIT();
    CP_WAIT1();
    __syncthreads();

    for (int kc = 0; kc < KC; kc++) {
        const uint32_t sb = sbase + (kc & 1) * G_STG;
        #pragma unroll
        for (int h = 0; h < 2; h++) {
            const uint32_t aoff = (uint32_t)rA * 64 + (uint32_t)(((h * 2 + cA) ^ swzA) << 4);
            const uint32_t boff = (uint32_t)rB * 64 + (uint32_t)(((h * 2 + cB) ^ swzB) << 4);
            uint32_t ah[4][4], al[4][4], bh[4][2], bl[4][2];
            #pragma unroll
            for (int i = 0; i < 4; i++) {
                ldsm_x4(ah[i][0], ah[i][1], ah[i][2], ah[i][3],
                        sb + G_AH + aoff + (uint32_t)(16 * i) * 64);
                ldsm_x4(al[i][0], al[i][1], al[i][2], al[i][3],
                        sb + G_AL + aoff + (uint32_t)(16 * i) * 64);
            }
            #pragma unroll
            for (int j = 0; j < 2; j++) {
                uint32_t r0, r1, r2, r3;
                ldsm_x4(r0, r1, r2, r3, sb + G_BH + boff + (uint32_t)(16 * j) * 64);
                bh[2 * j][0] = r0; bh[2 * j][1] = r1;
                bh[2 * j + 1][0] = r2; bh[2 * j + 1][1] = r3;
                ldsm_x4(r0, r1, r2, r3, sb + G_BL + boff + (uint32_t)(16 * j) * 64);
                bl[2 * j][0] = r0; bl[2 * j][1] = r1;
                bl[2 * j + 1][0] = r2; bl[2 * j + 1][1] = r3;
            }
            #pragma unroll
            for (int i = 0; i < 4; i++)
                #pragma unroll
                for (int t = 0; t < 4; t++) {
                    mma_bf16(acc[i][t], ah[i], bh[t]);
                    mma_bf16(acc[i][t], al[i], bh[t]);
                    mma_bf16(acc[i][t], ah[i], bl[t]);
                }
        }
        __syncthreads();             // stage consumed by all warps
        if (kc + 2 < KC) load_stage(kc & 1);
        CP_COMMIT();
        if (kc + 1 < KC) { CP_WAIT1(); __syncthreads(); }
    }

    const int gr = lane >> 2, gc = (lane & 3) * 2;
    if (mode == 0) {
        #pragma unroll
        for (int i = 0; i < 4; i++) {
            const int row0 = m0 + wm + i * 16 + gr;
            #pragma unroll
            for (int t = 0; t < 4; t++) {
                const int col = n0 + wn + t * 8 + gc;
                if (col < N) {
                    *(float2*)(C + (size_t)row0 * ldc + col) =
                        make_float2(acc[i][t][0], acc[i][t][1]);
                    *(float2*)(C + (size_t)(row0 + 8) * ldc + col) =
                        make_float2(acc[i][t][2], acc[i][t][3]);
                }
            }
        }
    } else {
        #pragma unroll
        for (int i = 0; i < 4; i++) {
            const int row0 = m0 + wm + i * 16 + gr;
            #pragma unroll
            for (int t = 0; t < 4; t++) {
                const int col = n0 + wn + t * 8 + gc;
                const int d = col % DQK;
                #pragma unroll
                for (int rr = 0; rr < 2; rr++) {
                    const int row = row0 + rr * 8;
                    float v0 = acc[i][t][rr * 2 + 0];
                    float v1 = acc[i][t][rr * 2 + 1];
                    if (d >= DN) {
                        const int fi = (d - DN) >> 1;
                        const float f = (float)(row & (S_ - 1)) * g_freq[fi];
                        float sn, cs;
                        sincosf(f, &sn, &cs);
                        const float e = v0, o = v1;
                        v0 = e * cs - o * sn;
                        v1 = e * sn + o * cs;
                    }
                    __nv_bfloat162 hi, lo;
                    hl_split2(v0, v1, hi, lo);
                    *(__nv_bfloat162*)(Chi + (size_t)row * ldc + col) = hi;
                    *(__nv_bfloat162*)(Clo + (size_t)row * ldc + col) = lo;
                }
            }
        }
    }
}

// ---------------------------------------------------------------------------
// freq init / RoPE(K)
// ---------------------------------------------------------------------------
__global__ void freq_init_kernel()
{
    if (threadIdx.x < 32)
        g_freq[threadIdx.x] = (float)pow(10000.0, -(double)threadIdx.x / 32.0);
}

__global__ void rope_k_kernel(float* __restrict__ kv)
{
    const int idx = blockIdx.x * blockDim.x + threadIdx.x;
    const int i   = idx & 31;
    const int row = idx >> 5;
    const int s   = row & (S_ - 1);
    float* p = kv + (size_t)row * (KVL + DR) + KVL + 2 * i;
    const float f = (float)s * g_freq[i];
    float sn, c;
    sincosf(f, &sn, &c);
    const float e = p[0], o = p[1];
    p[0] = e * c - o * sn;
    p[1] = e * sn + o * c;
}

// ---------------------------------------------------------------------------
// Flash prep: K assembly + V transpose (hi/lo)
// ---------------------------------------------------------------------------
__global__ void convk_kernel(const float* __restrict__ kvx, const float* __restrict__ kv,
                             __nv_bfloat16* __restrict__ kh, __nv_bfloat16* __restrict__ kl)
{
    const int idx = blockIdx.x * blockDim.x + threadIdx.x;
    if (idx >= BS * NH_ * 48) return;
    const int dg  = idx % 48;
    const int h   = (idx / 48) & (NH_ - 1);
    const int row = idx / (48 * NH_);
    float4 v;
    if (dg < 32) v = *(const float4*)(kvx + (size_t)row * (NH_ * 256) + h * 256 + dg * 4);
    else         v = *(const float4*)(kv + (size_t)row * (KVL + DR) + KVL + (dg - 32) * 4);
    __nv_bfloat162 hiA, loA, hiB, loB;
    hl_split2(v.x, v.y, hiA, loA);
    hl_split2(v.z, v.w, hiB, loB);
    const size_t o = ((size_t)row * NH_ + h) * 192 + dg * 4;
    *(__nv_bfloat162*)(kh + o + 0) = hiA;
    *(__nv_bfloat162*)(kh + o + 2) = hiB;
    *(__nv_bfloat162*)(kl + o + 0) = loA;
    *(__nv_bfloat162*)(kl + o + 2) = loB;
}

__global__ void convvt_kernel(const float* __restrict__ kvx,
                              __nv_bfloat16* __restrict__ vth, __nv_bfloat16* __restrict__ vtl)
{
    __shared__ float tile[32][33];
    const int bh = blockIdx.z;
    const int b = bh >> 4, h = bh & 15;
    const int s0 = blockIdx.x * 32, dv0 = blockIdx.y * 32;
    const int tx = threadIdx.x, ty = threadIdx.y;
    #pragma unroll
    for (int j = 0; j < 4; j++) {
        const int s = s0 + ty + 8 * j;
        tile[ty + 8 * j][tx] =
            kvx[(size_t)(b * S_ + s) * (NH_ * 256) + h * 256 + DN + dv0 + tx];
    }
    __syncthreads();
    #pragma unroll
    for (int j = 0; j < 4; j++) {
        const int dv = dv0 + ty + 8 * j;
        const float v = tile[tx][ty + 8 * j];
        const __nv_bfloat16 hi = __float2bfloat16(v);
        const __nv_bfloat16 lo = __float2bfloat16(v - __bfloat162float(hi));
        const size_t o = ((size_t)bh * DV + dv) * S_ + s0 + tx;
        vth[o] = hi; vtl[o] = lo;
    }
}

// ---------------------------------------------------------------------------
// Flash attention on HMMA (R11: fused-fragment QK) — unchanged
// ---------------------------------------------------------------------------
__global__ __launch_bounds__(256, 1)
void flash_mma_kernel(const __nv_bfloat16* __restrict__ qh, const __nv_bfloat16* __restrict__ ql,
                      const __nv_bfloat16* __restrict__ kh, const __nv_bfloat16* __restrict__ kl,
                      const __nv_bfloat16* __restrict__ vth, const __nv_bfloat16* __restrict__ vtl,
                      __nv_bfloat16* __restrict__ ohi, __nv_bfloat16* __restrict__ olo)
{
    extern __shared__ __align__(128) char sm[];
    const uint32_t sb = smem_u32(sm);
    const int tid = threadIdx.x, warp = tid >> 5, lane = tid & 31;
    const int h = blockIdx.y, b = blockIdx.z;
    const int q0 = blockIdx.x * 128;
    const int wr = warp * 16;

    auto load_k = [&](int kt) {
        for (int u = tid; u < 64 * 24; u += 256) {
            const int r = u / 24, c = u % 24;
            const size_t off = ((size_t)(b * S_ + kt + r) * NH_ + h) * 192 + c * 8;
            cp_async16(sb + SM_KH + r * 400 + c * 16, kh + off);
            cp_async16(sb + SM_KL + r * 400 + c * 16, kl + off);
        }
    };
    auto load_v = [&](int kt) {
        for (int u = tid; u < 128 * 8; u += 256) {
            const int dv = u / 8, ck = u % 8;
            const size_t off = ((size_t)(b * NH_ + h) * DV + dv) * S_ + kt + ck * 8;
            cp_async16(sb + SM_VH + dv * 144 + ck * 16, vth + off);
            cp_async16(sb + SM_VL + dv * 144 + ck * 16, vtl + off);
        }
    };

    for (int u = tid; u < 128 * 24; u += 256) {
        const int r = u / 24, c = u % 24;
        const size_t off = ((size_t)(b * S_ + q0 + r) * NH_ + h) * 192 + c * 8;
        cp_async16(sb + SM_QH + r * 400 + c * 16, qh + off);
        cp_async16(sb + SM_QL + r * 400 + c * 16, ql + off);
    }
    load_k(0);
    CP_COMMIT();
    load_v(0);
    CP_COMMIT();

    float oacc[16][4];
    #pragma unroll
    for (int i = 0; i < 16; i++)
        #pragma unroll
        for (int j = 0; j < 4; j++) oacc[i][j] = 0.f;
    float m0 = -1e30f, m1 = -1e30f, l0 = 0.f, l1 = 0.f;

    const uint32_t aQoff = (uint32_t)(wr + (lane & 15)) * 400 + ((lane >> 4) << 4);
    const int rB8  = (lane & 7) + ((lane >> 4) << 3);
    const uint32_t bKoff = (uint32_t)rB8 * 400 + (((lane >> 3) & 1) << 4);
    const uint32_t bVoff = (uint32_t)rB8 * 144 + (((lane >> 3) & 1) << 4);

    for (int kt = 0; kt < S_; kt += 64) {
        const bool has_next = (kt + 64 < S_);
        CP_WAIT1();
        __syncthreads();

        float sacc[8][4];
        #pragma unroll
        for (int i = 0; i < 8; i++)
            #pragma unroll
            for (int j = 0; j < 4; j++) sacc[i][j] = 0.f;

        #pragma unroll
        for (int ks = 0; ks < 12; ks++) {
            uint32_t ah[4], al[4];
            ldsm_x4(ah[0], ah[1], ah[2], ah[3], sb + SM_QH + aQoff + ks * 32);
            ldsm_x4(al[0], al[1], al[2], al[3], sb + SM_QL + aQoff + ks * 32);
            #pragma unroll
            for (int g = 0; g < 4; g++) {
                uint32_t h0, h1, h2, h3, l0r, l1r, l2r, l3r;
                ldsm_x4(h0, h1, h2, h3,
                        sb + SM_KH + bKoff + (uint32_t)g * 16 * 400 + ks * 32);
                ldsm_x4(l0r, l1r, l2r, l3r,
                        sb + SM_KL + bKoff + (uint32_t)g * 16 * 400 + ks * 32);
                uint32_t bh0[2] = {h0, h1}, bh1[2] = {h2, h3};
                uint32_t bl0[2] = {l0r, l1r}, bl1[2] = {l2r, l3r};
                mma_bf16(sacc[2 * g],     ah, bh0);
                mma_bf16(sacc[2 * g + 1], ah, bh1);
                mma_bf16(sacc[2 * g],     al, bh0);
                mma_bf16(sacc[2 * g + 1], al, bh1);
                mma_bf16(sacc[2 * g],     ah, bl0);
                mma_bf16(sacc[2 * g + 1], ah, bl1);
            }
        }

        __syncthreads();
        if (has_next) load_k(kt + 64);
        CP_COMMIT();

        float mx0 = -1e30f, mx1 = -1e30f;
        #pragma unroll
        for (int nt = 0; nt < 8; nt++) {
            #pragma unroll
            for (int j = 0; j < 4; j++) sacc[nt][j] *= SCALE;
            mx0 = fmaxf(mx0, fmaxf(sacc[nt][0], sacc[nt][1]));
            mx1 = fmaxf(mx1, fmaxf(sacc[nt][2], sacc[nt][3]));
        }
        mx0 = fmaxf(mx0, __shfl_xor_sync(0xffffffffu, mx0, 1));
        mx0 = fmaxf(mx0, __shfl_xor_sync(0xffffffffu, mx0, 2));
        mx1 = fmaxf(mx1, __shfl_xor_sync(0xffffffffu, mx1, 1));
        mx1 = fmaxf(mx1, __shfl_xor_sync(0xffffffffu, mx1, 2));
        const float mn0 = fmaxf(m0, mx0), mn1 = fmaxf(m1, mx1);
        const float al0 = __expf(m0 - mn0), al1 = __expf(m1 - mn1);
        float rs0 = 0.f, rs1 = 0.f;
        #pragma unroll
        for (int nt = 0; nt < 8; nt++) {
            sacc[nt][0] = __expf(sacc[nt][0] - mn0);
            sacc[nt][1] = __expf(sacc[nt][1] - mn0);
            sacc[nt][2] = __expf(sacc[nt][2] - mn1);
            sacc[nt][3] = __expf(sacc[nt][3] - mn1);
            rs0 += sacc[nt][0] + sacc[nt][1];
            rs1 += sacc[nt][2] + sacc[nt][3];
        }
        rs0 += __shfl_xor_sync(0xffffffffu, rs0, 1);
        rs0 += __shfl_xor_sync(0xffffffffu, rs0, 2);
        rs1 += __shfl_xor_sync(0xffffffffu, rs1, 1);
        rs1 += __shfl_xor_sync(0xffffffffu, rs1, 2);
        l0 = l0 * al0 + rs0; m0 = mn0;
        l1 = l1 * al1 + rs1; m1 = mn1;
        #pragma unroll
        for (int nt = 0; nt < 16; nt++) {
            oacc[nt][0] *= al0; oacc[nt][1] *= al0;
            oacc[nt][2] *= al1; oacc[nt][3] *= al1;
        }

        if (has_next) { CP_WAIT1(); } else { CP_WAIT0(); }
        __syncthreads();

        #pragma unroll
        for (int kk = 0; kk < 4; kk++) {
            uint32_t ah[4], alr[4];
            {
                const float* p0 = sacc[2 * kk];
                const float* p1 = sacc[2 * kk + 1];
                float h00 = __bfloat162float(__float2bfloat16(p0[0]));
                float h01 = __bfloat162float(__float2bfloat16(p0[1]));
                float h02 = __bfloat162float(__float2bfloat16(p0[2]));
                float h03 = __bfloat162float(__float2bfloat16(p0[3]));
                float h10 = __bfloat162float(__float2bfloat16(p1[0]));
                float h11 = __bfloat162float(__float2bfloat16(p1[1]));
                float h12 = __bfloat162float(__float2bfloat16(p1[2]));
                float h13 = __bfloat162float(__float2bfloat16(p1[3]));
                ah[0] = pack_bf2(p0[0], p0[1]);
                ah[1] = pack_bf2(p0[2], p0[3]);
                ah[2] = pack_bf2(p1[0], p1[1]);
                ah[3] = pack_bf2(p1[2], p1[3]);
                alr[0] = pack_bf2(p0[0] - h00, p0[1] - h01);
                alr[1] = pack_bf2(p0[2] - h02, p0[3] - h03);
                alr[2] = pack_bf2(p1[0] - h10, p1[1] - h11);
                alr[3] = pack_bf2(p1[2] - h12, p1[3] - h13);
            }
            #pragma unroll
            for (int half = 0; half < 2; half++) {
                uint32_t bv[8][2];
                #pragma unroll
                for (int g = 0; g < 4; g++) {
                    uint32_t r0, r1, r2, r3;
                    ldsm_x4(r0, r1, r2, r3,
                            sb + SM_VH + bVoff + (uint32_t)(half * 64 + g * 16) * 144 + kk * 32);
                    bv[2 * g][0] = r0; bv[2 * g][1] = r1;
                    bv[2 * g + 1][0] = r2; bv[2 * g + 1][1] = r3;
                }
                #pragma unroll
                for (int t = 0; t < 8; t++) {
                    mma_bf16(oacc[half * 8 + t], ah, bv[t]);
                    mma_bf16(oacc[half * 8 + t], alr, bv[t]);
                }
                #pragma unroll
                for (int g = 0; g < 4; g++) {
                    uint32_t r0, r1, r2, r3;
                    ldsm_x4(r0, r1, r2, r3,
                            sb + SM_VL + bVoff + (uint32_t)(half * 64 + g * 16) * 144 + kk * 32);
                    bv[2 * g][0] = r0; bv[2 * g][1] = r1;
                    bv[2 * g + 1][0] = r2; bv[2 * g + 1][1] = r3;
                }
                #pragma unroll
                for (int t = 0; t < 8; t++)
                    mma_bf16(oacc[half * 8 + t], ah, bv[t]);
            }
        }

        __syncthreads();
        if (has_next) load_v(kt + 64);
        CP_COMMIT();
    }

    const float inv0 = 1.f / l0, inv1 = 1.f / l1;
    const int gr = lane >> 2, gc = (lane & 3) * 2;
    const int row0 = b * S_ + q0 + wr + gr;
    #pragma unroll
    for (int nt = 0; nt < 16; nt++) {
        const int col = h * DV + nt * 8 + gc;
        __nv_bfloat162 hi, lo;
        hl_split2(oacc[nt][0] * inv0, oacc[nt][1] * inv0, hi, lo);
        *(__nv_bfloat162*)(ohi + (size_t)row0 * (NH_ * DV) + col) = hi;
        *(__nv_bfloat162*)(olo + (size_t)row0 * (NH_ * DV) + col) = lo;
        hl_split2(oacc[nt][2] * inv1, oacc[nt][3] * inv1, hi, lo);
        *(__nv_bfloat162*)(ohi + (size_t)(row0 + 8) * (NH_ * DV) + col) = hi;
        *(__nv_bfloat162*)(olo + (size_t)(row0 + 8) * (NH_ * DV) + col) = lo;
    }
}

// ---------------------------------------------------------------------------
// Launcher
// ---------------------------------------------------------------------------
static inline void run_conv(const float* in, __nv_bfloat16* hi, __nv_bfloat16* lo,
                            int R, int Rpad, int Kin, int ldin)
{
    const int total = Rpad * (Kin / 4);
    conv_hl_kernel<<<(total + 255) / 256, 256>>>(in, hi, lo, R, Rpad, Kin, ldin);
}

extern "C" void kernel_launch(void* const* d_in, const int* in_sizes, int n_in,
                              void* d_out, int out_size)
{
    const float* hs    = (const float*)d_in[0];
    const float* wq_a  = (const float*)d_in[1];
    const float* qnw   = (const float*)d_in[2];
    const float* wq_b  = (const float*)d_in[3];
    const float* wkv_a = (const float*)d_in[4];
    const float* kvnw  = (const float*)d_in[5];
    const float* wkv_b = (const float*)d_in[6];
    const float* wo    = (const float*)d_in[7];
    float* out = (float*)d_out;

    void* p;
    cudaGetSymbolAddress(&p, g_qlora); float* qlora = (float*)p;
    cudaGetSymbolAddress(&p, g_kv);    float* kvbuf = (float*)p;
    cudaGetSymbolAddress(&p, g_kvx);   float* kvx   = (float*)p;
    cudaGetSymbolAddress(&p, g_a3);    __nv_bfloat16* a3 = (__nv_bfloat16*)p;
    cudaGetSymbolAddress(&p, g_b3);    __nv_bfloat16* b3 = (__nv_bfloat16*)p;
    cudaGetSymbolAddress(&p, g_qh);    __nv_bfloat16* qh = (__nv_bfloat16*)p;
    cudaGetSymbolAddress(&p, g_ql2);   __nv_bfloat16* ql = (__nv_bfloat16*)p;
    cudaGetSymbolAddress(&p, g_kh);    __nv_bfloat16* kh = (__nv_bfloat16*)p;
    cudaGetSymbolAddress(&p, g_kl);    __nv_bfloat16* kl = (__nv_bfloat16*)p;
    cudaGetSymbolAddress(&p, g_vth);   __nv_bfloat16* vth = (__nv_bfloat16*)p;
    cudaGetSymbolAddress(&p, g_vtl);   __nv_bfloat16* vtl = (__nv_bfloat16*)p;

    cudaFuncSetAttribute(flash_mma_kernel, cudaFuncAttributeMaxDynamicSharedMemorySize,
                         FLASH_SMEM);

    freq_init_kernel<<<1, 32>>>();

    // 1) q_lora = hs @ wq_a^T        [4096, 1536], K=2048
    run_conv(hs, a3, a3 + (size_t)BS * H_, BS, BS, H_, H_);
    run_conv(wq_a, b3, b3 + (size_t)QL * H_, QL, QL, H_, H_);
    gemm_bf16_kernel<<<dim3(QL / 64, BS / 128), 128>>>(
        a3, a3 + (size_t)BS * H_, b3, b3 + (size_t)QL * H_,
        qlora, nullptr, nullptr, QL, H_, QL, 0);

    // 2) kv = hs @ wkv_a^T           [4096, 576] (Npad 640), same A
    run_conv(wkv_a, b3, b3 + (size_t)640 * H_, KVL + DR, 640, H_, H_);
    gemm_bf16_kernel<<<dim3(640 / 64, BS / 128), 128>>>(
        a3, a3 + (size_t)BS * H_, b3, b3 + (size_t)640 * H_,
        kvbuf, nullptr, nullptr, KVL + DR, H_, KVL + DR, 0);

    // 3) k rope (in place, pe cols only)
    rope_k_kernel<<<(BS * 32) / 256, 256>>>(kvbuf);

    // 4) q = q_lora @ wq_b^T         [4096, 3072], K=1536; fused rope + hi/lo out
    rms_conv_hl_kernel<<<BS, 256>>>(qlora, qnw, a3, a3 + (size_t)BS * QL, QL, QL);
    run_conv(wq_b, b3, b3 + (size_t)3072 * QL, NH_ * DQK, NH_ * DQK, QL, QL);
    gemm_bf16_kernel<<<dim3((NH_ * DQK) / 64, BS / 128), 128>>>(
        a3, a3 + (size_t)BS * QL, b3, b3 + (size_t)3072 * QL,
        nullptr, qh, ql, NH_ * DQK, QL, NH_ * DQK, 1);

    // 5) kv_x = kv_c @ wkv_b^T       [4096, 4096], K=512
    rms_conv_hl_kernel<<<BS, 256>>>(kvbuf, kvnw, a3, a3 + (size_t)BS * KVL, KVL, KVL + DR);
    run_conv(wkv_b, b3, b3 + (size_t)4096 * KVL, NH_ * (DN + DV), NH_ * (DN + DV), KVL, KVL);
    gemm_bf16_kernel<<<dim3((NH_ * (DN + DV)) / 64, BS / 128), 128>>>(
        a3, a3 + (size_t)BS * KVL, b3, b3 + (size_t)4096 * KVL,
        kvx, nullptr, nullptr, NH_ * (DN + DV), KVL, NH_ * (DN + DV), 0);

    // 6) flash prep: K assembly + V transpose (hi/lo)
    convk_kernel<<<(BS * NH_ * 48 + 255) / 256, 256>>>(kvx, kvbuf, kh, kl);
    convvt_kernel<<<dim3(S_ / 32, DV / 32, B_ * NH_), dim3(32, 8)>>>(kvx, vth, vtl);

    // 7) flash attention -> a3 hi/lo directly (split-2 A for final GEMM)
    flash_mma_kernel<<<dim3(S_ / 128, NH_, B_), 256, FLASH_SMEM>>>(
        qh, ql, kh, kl, vth, vtl, a3, a3 + (size_t)BS * (NH_ * DV));

    // 8) out = attn @ wo^T           [4096, 2048], K=2048
    run_conv(wo, b3, b3 + (size_t)H_ * (NH_ * DV), H_, H_, NH_ * DV, NH_ * DV);
    gemm_bf16_kernel<<<dim3(H_ / 64, BS / 128), 128>>>(
        a3, a3 + (size_t)BS * (NH_ * DV), b3, b3 + (size_t)H_ * (NH_ * DV),
        out, nullptr, nullptr, H_, NH_ * DV, H_, 0);
}